// round 2
// baseline (speedup 1.0000x reference)
#include <cuda_runtime.h>
#include <cuda_bf16.h>

// ---------------------------------------------------------------------------
// GraphEncoder: 2-layer GCN + edge MLP + classifier.
// Inputs (metadata order): x[N,256] f32, edge_index[2,E] int32, W1[256,256],
// b1[256], W2[256,128], b2[128], Wp1[256,256], bp1[256], Wp2[256,128],
// bp2[128], Wc[128,40], bc[40].
// Output (f32, concatenated): f[N,128], edge_feats[E,128], logits[N,40],
// edge_index[2,E] (cast to float).
// ---------------------------------------------------------------------------

#define MAXN 100000
#define MAXE 800000

// Scratch (static device globals: allocation-free per harness rules)
__device__ float g_xw[(size_t)MAXN * 256];   // x @ W1
__device__ float g_h [(size_t)MAXN * 256];   // layer-1 accum / hidden
__device__ float g_hw[(size_t)MAXN * 128];   // h @ W2
__device__ float g_deg[MAXN];                // degree -> dinv

// ---------------------------------------------------------------------------
__global__ void k_init_deg(float* deg, int n) {
    int i = blockIdx.x * blockDim.x + threadIdx.x;
    if (i < n) deg[i] = 1.0f;   // self-loop
}

__global__ void k_count_deg(const int* __restrict__ ei, float* deg, int E) {
    int e = blockIdx.x * blockDim.x + threadIdx.x;
    if (e < E) atomicAdd(&deg[ei[E + e]], 1.0f);
}

__global__ void k_rsqrt(float* deg, int n) {
    int i = blockIdx.x * blockDim.x + threadIdx.x;
    if (i < n) deg[i] = rsqrtf(deg[i]);   // deg >= 1 always
}

// ---------------------------------------------------------------------------
// Generic tiled SGEMM: C[M,N] = A[M,K] @ B[K,N] (+bias) (optional relu)
// BM=BN=64, BK=16, 256 threads, 4x4 microtile.
__global__ __launch_bounds__(256)
void k_sgemm(int M, int N, int K,
             const float* __restrict__ A, const float* __restrict__ B,
             const float* __restrict__ bias, float* __restrict__ C, int relu)
{
    __shared__ float As[64 * 16];
    __shared__ float Bs[16 * 64];
    int t = threadIdx.x;
    int tx = t & 15, ty = t >> 4;
    int row0 = blockIdx.y * 64, col0 = blockIdx.x * 64;
    float acc[4][4] = {};

    for (int k0 = 0; k0 < K; k0 += 16) {
        for (int i = t; i < 64 * 16; i += 256) {
            int r = i >> 4, c = i & 15;
            int gr = row0 + r, gc = k0 + c;
            As[i] = (gr < M && gc < K) ? A[(long long)gr * K + gc] : 0.f;
        }
        for (int i = t; i < 16 * 64; i += 256) {
            int r = i >> 6, c = i & 63;
            int gr = k0 + r, gc = col0 + c;
            Bs[i] = (gr < K && gc < N) ? B[(long long)gr * N + gc] : 0.f;
        }
        __syncthreads();
        #pragma unroll
        for (int kk = 0; kk < 16; kk++) {
            float a[4], b[4];
            #pragma unroll
            for (int m = 0; m < 4; m++) a[m] = As[(ty * 4 + m) * 16 + kk];
            #pragma unroll
            for (int nn = 0; nn < 4; nn++) b[nn] = Bs[kk * 64 + tx * 4 + nn];
            #pragma unroll
            for (int m = 0; m < 4; m++)
                #pragma unroll
                for (int nn = 0; nn < 4; nn++)
                    acc[m][nn] += a[m] * b[nn];
        }
        __syncthreads();
    }
    #pragma unroll
    for (int m = 0; m < 4; m++) {
        int r = row0 + ty * 4 + m;
        if (r >= M) continue;
        #pragma unroll
        for (int nn = 0; nn < 4; nn++) {
            int c = col0 + tx * 4 + nn;
            if (c >= N) continue;
            float v = acc[m][nn] + (bias ? bias[c] : 0.f);
            if (relu) v = fmaxf(v, 0.f);
            C[(long long)r * N + c] = v;
        }
    }
}

// ---------------------------------------------------------------------------
// Edge scatter-aggregate: dst[c] += dinv[r]*dinv[c] * src[r]  (float4 chunks)
__global__ void k_agg(const int* __restrict__ ei,
                      const float* __restrict__ dinv,
                      const float* __restrict__ src,
                      float* __restrict__ dst, int E, int logF4)
{
    long long idx = (long long)blockIdx.x * blockDim.x + threadIdx.x;
    int F4 = 1 << logF4;
    if (idx >= ((long long)E << logF4)) return;
    int e = (int)(idx >> logF4);
    int j = (int)(idx & (F4 - 1));
    int r = ei[e];
    int c = ei[E + e];
    float w = dinv[r] * dinv[c];
    float4 v = ((const float4*)src)[(long long)r * F4 + j];
    float* d = dst + (((long long)c * F4 + j) << 2);
    atomicAdd(d + 0, w * v.x);
    atomicAdd(d + 1, w * v.y);
    atomicAdd(d + 2, w * v.z);
    atomicAdd(d + 3, w * v.w);
}

// Add self-loop term + bias, optional relu: acc += dinv^2 * self + bias
__global__ void k_finalize(float* __restrict__ acc,
                           const float* __restrict__ self,
                           const float* __restrict__ dinv,
                           const float* __restrict__ bias,
                           int n, int logF4, int relu)
{
    long long idx = (long long)blockIdx.x * blockDim.x + threadIdx.x;
    int F4 = 1 << logF4;
    if (idx >= ((long long)n << logF4)) return;
    int i = (int)(idx >> logF4);
    int j = (int)(idx & (F4 - 1));
    float di = dinv[i];
    float w = di * di;
    float4 s = ((const float4*)self)[idx];
    float4 a = ((float4*)acc)[idx];
    float4 b = ((const float4*)bias)[j];
    a.x += w * s.x + b.x;
    a.y += w * s.y + b.y;
    a.z += w * s.z + b.z;
    a.w += w * s.w + b.w;
    if (relu) {
        a.x = fmaxf(a.x, 0.f); a.y = fmaxf(a.y, 0.f);
        a.z = fmaxf(a.z, 0.f); a.w = fmaxf(a.w, 0.f);
    }
    ((float4*)acc)[idx] = a;
}

__global__ void k_copy_ei(const int* __restrict__ ei, float* __restrict__ out, int n2) {
    int i = blockIdx.x * blockDim.x + threadIdx.x;
    if (i < n2) out[i] = (float)ei[i];
}

// ---------------------------------------------------------------------------
// Fused edge MLP: for each edge (r,c):
//   ef = [f[r], f[c]] (256)  ->  hid = relu(ef @ Wp1 + bp1) (256)
//   out = hid @ Wp2 + bp2 (128)
// 16 edges per block, 256 threads. ef/hid tile 16KB, weight stream tile 32KB.
#define TE 16
__global__ __launch_bounds__(256)
void k_edge_mlp(const int* __restrict__ ei,
                const float* __restrict__ f,
                const float* __restrict__ Wp1, const float* __restrict__ bp1,
                const float* __restrict__ Wp2, const float* __restrict__ bp2,
                float* __restrict__ out, int E)
{
    __shared__ float s_ef[TE * 256];   // ef tile, reused as hidden
    __shared__ float s_b[32 * 256];    // streamed weight tile

    int t = threadIdx.x;
    long long e0 = (long long)blockIdx.x * TE;

    // Load ef tile (float4): row layout [f[r](128) | f[c](128)] -> 64 float4
    const float4* f4 = (const float4*)f;
    float4* ef4 = (float4*)s_ef;
    for (int i = t; i < TE * 64; i += 256) {
        int row = i >> 6;
        int c4 = i & 63;
        long long e = e0 + row;
        float4 v = make_float4(0.f, 0.f, 0.f, 0.f);
        if (e < E) {
            int node = (c4 < 32) ? ei[e] : ei[E + e];
            v = f4[(long long)node * 32 + (c4 & 31)];
        }
        ef4[i] = v;
    }
    __syncthreads();

    int row = t >> 4;
    int cb  = t & 15;

    // GEMM1: hid[16,256] = relu(ef @ Wp1 + bp1); thread -> (row, cols cb+16j)
    float acc[16];
    #pragma unroll
    for (int j = 0; j < 16; j++) acc[j] = 0.f;

    for (int k0 = 0; k0 < 256; k0 += 32) {
        const float4* w4 = (const float4*)(Wp1 + k0 * 256);
        float4* sb4 = (float4*)s_b;
        #pragma unroll
        for (int i = t; i < 32 * 64; i += 256) sb4[i] = w4[i];
        __syncthreads();
        #pragma unroll
        for (int kk = 0; kk < 32; kk++) {
            float a = s_ef[row * 256 + k0 + kk];
            #pragma unroll
            for (int j = 0; j < 16; j++)
                acc[j] += a * s_b[kk * 256 + cb + 16 * j];
        }
        __syncthreads();
    }
    // Write hidden (relu + bias) into s_ef (ef is dead)
    #pragma unroll
    for (int j = 0; j < 16; j++) {
        int col = cb + 16 * j;
        s_ef[row * 256 + col] = fmaxf(acc[j] + bp1[col], 0.f);
    }
    __syncthreads();

    // GEMM2: out[16,128] = hid @ Wp2 + bp2; thread -> (row, cols cb+16j), j<8
    float acc2[8];
    #pragma unroll
    for (int j = 0; j < 8; j++) acc2[j] = 0.f;

    for (int k0 = 0; k0 < 256; k0 += 32) {
        const float4* w4 = (const float4*)(Wp2 + k0 * 128);
        float4* sb4 = (float4*)s_b;
        #pragma unroll
        for (int i = t; i < 32 * 32; i += 256) sb4[i] = w4[i];
        __syncthreads();
        #pragma unroll
        for (int kk = 0; kk < 32; kk++) {
            float a = s_ef[row * 256 + k0 + kk];
            #pragma unroll
            for (int j = 0; j < 8; j++)
                acc2[j] += a * s_b[kk * 128 + cb + 16 * j];
        }
        __syncthreads();
    }

    long long e = e0 + row;
    if (e < E) {
        #pragma unroll
        for (int j = 0; j < 8; j++) {
            int col = cb + 16 * j;
            out[e * 128 + col] = acc2[j] + bp2[col];
        }
    }
}

// ---------------------------------------------------------------------------
extern "C" void kernel_launch(void* const* d_in, const int* in_sizes, int n_in,
                              void* d_out, int out_size)
{
    const float* x   = (const float*)d_in[0];
    const int*   ei  = (const int*)d_in[1];
    const float* W1  = (const float*)d_in[2];
    const float* b1  = (const float*)d_in[3];
    const float* W2  = (const float*)d_in[4];
    const float* b2  = (const float*)d_in[5];
    const float* Wp1 = (const float*)d_in[6];
    const float* bp1 = (const float*)d_in[7];
    const float* Wp2 = (const float*)d_in[8];
    const float* bp2 = (const float*)d_in[9];
    const float* Wc  = (const float*)d_in[10];
    const float* bc  = (const float*)d_in[11];

    int n = in_sizes[0] / 256;   // nodes
    int E = in_sizes[1] / 2;     // edges

    float* out    = (float*)d_out;
    float* f      = out;                                   // [n,128]
    float* ef_out = f + (long long)n * 128;                // [E,128]
    float* logits = ef_out + (long long)E * 128;           // [n,40]
    float* ei_out = logits + (long long)n * 40;            // [2E]

    float *xw, *h, *hw, *deg;
    cudaGetSymbolAddress((void**)&xw,  g_xw);
    cudaGetSymbolAddress((void**)&h,   g_h);
    cudaGetSymbolAddress((void**)&hw,  g_hw);
    cudaGetSymbolAddress((void**)&deg, g_deg);

    // --- degree normalization ---
    k_init_deg<<<(n + 255) / 256, 256>>>(deg, n);
    k_count_deg<<<(E + 255) / 256, 256>>>(ei, deg, E);
    k_rsqrt<<<(n + 255) / 256, 256>>>(deg, n);

    // --- layer 1: h = relu(aggregate(x @ W1) + b1) ---
    k_sgemm<<<dim3(4, (n + 63) / 64), 256>>>(n, 256, 256, x, W1, nullptr, xw, 0);
    cudaMemsetAsync(h, 0, (size_t)n * 256 * sizeof(float));
    {
        long long tot = (long long)E * 64;
        k_agg<<<(unsigned)((tot + 255) / 256), 256>>>(ei, deg, xw, h, E, 6);
    }
    {
        long long tot = (long long)n * 64;
        k_finalize<<<(unsigned)((tot + 255) / 256), 256>>>(h, xw, deg, b1, n, 6, 1);
    }

    // --- layer 2: f = aggregate(h @ W2) + b2 ---
    k_sgemm<<<dim3(2, (n + 63) / 64), 256>>>(n, 128, 256, h, W2, nullptr, hw, 0);
    cudaMemsetAsync(f, 0, (size_t)n * 128 * sizeof(float));
    {
        long long tot = (long long)E * 32;
        k_agg<<<(unsigned)((tot + 255) / 256), 256>>>(ei, deg, hw, f, E, 5);
    }
    {
        long long tot = (long long)n * 32;
        k_finalize<<<(unsigned)((tot + 255) / 256), 256>>>(f, hw, deg, b2, n, 5, 0);
    }

    // --- classifier logits = f @ Wc + bc ---
    k_sgemm<<<dim3(1, (n + 63) / 64), 256>>>(n, 40, 128, f, Wc, bc, logits, 0);

    // --- edge_index passthrough (as float) ---
    k_copy_ei<<<(2 * E + 255) / 256, 256>>>(ei, ei_out, 2 * E);

    // --- edge MLP ---
    k_edge_mlp<<<(E + TE - 1) / TE, 256>>>(ei, f, Wp1, bp1, Wp2, bp2, ef_out, E);
}

// round 3
// speedup vs baseline: 3.4172x; 3.4172x over previous
#include <cuda_runtime.h>
#include <cuda_bf16.h>

// ---------------------------------------------------------------------------
// GraphEncoder: 2-layer GCN + edge MLP + classifier.
// Inputs: x[N,256] f32, edge_index[2,E] int32, W1[256,256], b1[256],
// W2[256,128], b2[128], Wp1[256,256], bp1[256], Wp2[256,128], bp2[128],
// Wc[128,40], bc[40].
// Output (f32): f[N,128], edge_feats[E,128], logits[N,40], edge_index (float).
// ---------------------------------------------------------------------------

#define MAXN 100000
#define MAXE 800000

__device__ float g_xw[(size_t)MAXN * 256];
__device__ float g_h [(size_t)MAXN * 256];
__device__ float g_hw[(size_t)MAXN * 128];
__device__ float g_deg[MAXN];

// ---------------------------------------------------------------------------
__device__ __forceinline__ float to_tf32(float x) {
    float r;
    asm("cvt.rna.tf32.f32 %0, %1;" : "=f"(r) : "f"(x));
    return r;
}

__device__ __forceinline__ void mma_tf32(float c[4],
    unsigned a0, unsigned a1, unsigned a2, unsigned a3,
    unsigned b0, unsigned b1)
{
    asm volatile(
        "mma.sync.aligned.m16n8k8.row.col.f32.tf32.tf32.f32 "
        "{%0,%1,%2,%3}, {%4,%5,%6,%7}, {%8,%9}, {%0,%1,%2,%3};"
        : "+f"(c[0]), "+f"(c[1]), "+f"(c[2]), "+f"(c[3])
        : "r"(a0), "r"(a1), "r"(a2), "r"(a3), "r"(b0), "r"(b1));
}

// ---------------------------------------------------------------------------
__global__ void k_init_deg(float* deg, int n) {
    int i = blockIdx.x * blockDim.x + threadIdx.x;
    if (i < n) deg[i] = 1.0f;
}

__global__ void k_count_deg(const int* __restrict__ ei, float* deg, int E) {
    int e = blockIdx.x * blockDim.x + threadIdx.x;
    if (e < E) atomicAdd(&deg[ei[E + e]], 1.0f);
}

__global__ void k_rsqrt(float* deg, int n) {
    int i = blockIdx.x * blockDim.x + threadIdx.x;
    if (i < n) deg[i] = rsqrtf(deg[i]);
}

// ---------------------------------------------------------------------------
// Generic tiled SGEMM (known-good from R2)
__global__ __launch_bounds__(256)
void k_sgemm(int M, int N, int K,
             const float* __restrict__ A, const float* __restrict__ B,
             const float* __restrict__ bias, float* __restrict__ C, int relu)
{
    __shared__ float As[64 * 16];
    __shared__ float Bs[16 * 64];
    int t = threadIdx.x;
    int tx = t & 15, ty = t >> 4;
    int row0 = blockIdx.y * 64, col0 = blockIdx.x * 64;
    float acc[4][4] = {};

    for (int k0 = 0; k0 < K; k0 += 16) {
        for (int i = t; i < 64 * 16; i += 256) {
            int r = i >> 4, c = i & 15;
            int gr = row0 + r, gc = k0 + c;
            As[i] = (gr < M && gc < K) ? A[(long long)gr * K + gc] : 0.f;
        }
        for (int i = t; i < 16 * 64; i += 256) {
            int r = i >> 6, c = i & 63;
            int gr = k0 + r, gc = col0 + c;
            Bs[i] = (gr < K && gc < N) ? B[(long long)gr * N + gc] : 0.f;
        }
        __syncthreads();
        #pragma unroll
        for (int kk = 0; kk < 16; kk++) {
            float a[4], b[4];
            #pragma unroll
            for (int m = 0; m < 4; m++) a[m] = As[(ty * 4 + m) * 16 + kk];
            #pragma unroll
            for (int nn = 0; nn < 4; nn++) b[nn] = Bs[kk * 64 + tx * 4 + nn];
            #pragma unroll
            for (int m = 0; m < 4; m++)
                #pragma unroll
                for (int nn = 0; nn < 4; nn++)
                    acc[m][nn] += a[m] * b[nn];
        }
        __syncthreads();
    }
    #pragma unroll
    for (int m = 0; m < 4; m++) {
        int r = row0 + ty * 4 + m;
        if (r >= M) continue;
        #pragma unroll
        for (int nn = 0; nn < 4; nn++) {
            int c = col0 + tx * 4 + nn;
            if (c >= N) continue;
            float v = acc[m][nn] + (bias ? bias[c] : 0.f);
            if (relu) v = fmaxf(v, 0.f);
            C[(long long)r * N + c] = v;
        }
    }
}

// ---------------------------------------------------------------------------
// Edge scatter-aggregate with vector reduction (sm_90+ red.global.add.v4.f32)
__global__ void k_agg(const int* __restrict__ ei,
                      const float* __restrict__ dinv,
                      const float* __restrict__ src,
                      float* __restrict__ dst, int E, int logF4)
{
    long long idx = (long long)blockIdx.x * blockDim.x + threadIdx.x;
    int F4 = 1 << logF4;
    if (idx >= ((long long)E << logF4)) return;
    int e = (int)(idx >> logF4);
    int j = (int)(idx & (F4 - 1));
    int r = ei[e];
    int c = ei[E + e];
    float w = dinv[r] * dinv[c];
    float4 v = ((const float4*)src)[(long long)r * F4 + j];
    float* d = dst + (((long long)c * F4 + j) << 2);
    asm volatile("red.global.add.v4.f32 [%0], {%1,%2,%3,%4};"
                 :: "l"(d), "f"(w * v.x), "f"(w * v.y), "f"(w * v.z), "f"(w * v.w)
                 : "memory");
}

__global__ void k_finalize(float* __restrict__ acc,
                           const float* __restrict__ self,
                           const float* __restrict__ dinv,
                           const float* __restrict__ bias,
                           int n, int logF4, int relu)
{
    long long idx = (long long)blockIdx.x * blockDim.x + threadIdx.x;
    int F4 = 1 << logF4;
    if (idx >= ((long long)n << logF4)) return;
    int i = (int)(idx >> logF4);
    int j = (int)(idx & (F4 - 1));
    float di = dinv[i];
    float w = di * di;
    float4 s = ((const float4*)self)[idx];
    float4 a = ((float4*)acc)[idx];
    float4 b = ((const float4*)bias)[j];
    a.x += w * s.x + b.x;
    a.y += w * s.y + b.y;
    a.z += w * s.z + b.z;
    a.w += w * s.w + b.w;
    if (relu) {
        a.x = fmaxf(a.x, 0.f); a.y = fmaxf(a.y, 0.f);
        a.z = fmaxf(a.z, 0.f); a.w = fmaxf(a.w, 0.f);
    }
    ((float4*)acc)[idx] = a;
}

__global__ void k_copy_ei(const int* __restrict__ ei, float* __restrict__ out, int n2) {
    int i = blockIdx.x * blockDim.x + threadIdx.x;
    if (i < n2) out[i] = (float)ei[i];
}

// ---------------------------------------------------------------------------
// Tensor-core edge MLP (tf32 mma.sync.m16n8k8).
// Block: 32 edges, 256 threads = 8 warps.
// GEMM1: [32,256] = ef[32,256] @ Wp1[256,256]; warp tile 16x64 (8 subtiles).
// GEMM2: [32,128] = hid[32,256] @ Wp2[256,128]; warp tile 16x32 (4 subtiles).
// smem pitch 264 (pitch%32==8 -> conflict-free fragment loads).
#define TE 32
#define PITCH1 264
#define PITCH2 136
__global__ __launch_bounds__(256)
void k_edge_mlp_tc(const int* __restrict__ ei,
                   const float* __restrict__ f,
                   const float* __restrict__ Wp1, const float* __restrict__ bp1,
                   const float* __restrict__ Wp2, const float* __restrict__ bp2,
                   float* __restrict__ out, int E)
{
    __shared__ float s_ef[TE * PITCH1];   // ef (tf32), later hidden (tf32)
    __shared__ float s_b [TE * PITCH1];   // streamed weight chunk (tf32)

    int t = threadIdx.x;
    int lane = t & 31, w = t >> 5;
    int g = lane >> 2, q = lane & 3;       // mma fragment coords
    int wr = w >> 2, wc = w & 3;           // warp grid 2x4
    int e0 = blockIdx.x * TE;

    // --- gather ef tile: row = edge, cols [f[src](128) | f[dst](128)] ---
    const float4* f4 = (const float4*)f;
    for (int i = t; i < TE * 64; i += 256) {
        int row = i >> 6, c4 = i & 63;
        int e = e0 + row;
        float4 v = make_float4(0.f, 0.f, 0.f, 0.f);
        if (e < E) {
            int node = (c4 < 32) ? ei[e] : ei[E + e];
            v = f4[(size_t)node * 32 + (c4 & 31)];
        }
        v.x = to_tf32(v.x); v.y = to_tf32(v.y);
        v.z = to_tf32(v.z); v.w = to_tf32(v.w);
        *(float4*)&s_ef[row * PITCH1 + c4 * 4] = v;
    }

    // --- GEMM1 ---
    float acc[8][4];
    #pragma unroll
    for (int s = 0; s < 8; s++)
        #pragma unroll
        for (int i = 0; i < 4; i++) acc[s][i] = 0.f;

    for (int k0 = 0; k0 < 256; k0 += 32) {
        __syncthreads();
        const float4* w4 = (const float4*)(Wp1 + k0 * 256);
        for (int i = t; i < 32 * 64; i += 256) {
            int row = i >> 6, c4 = i & 63;
            float4 v = w4[row * 64 + c4];
            v.x = to_tf32(v.x); v.y = to_tf32(v.y);
            v.z = to_tf32(v.z); v.w = to_tf32(v.w);
            *(float4*)&s_b[row * PITCH1 + c4 * 4] = v;
        }
        __syncthreads();
        #pragma unroll
        for (int ks = 0; ks < 32; ks += 8) {
            int arow = (wr * 16 + g) * PITCH1 + k0 + ks + q;
            unsigned a0 = __float_as_uint(s_ef[arow]);
            unsigned a1 = __float_as_uint(s_ef[arow + 8 * PITCH1]);
            unsigned a2 = __float_as_uint(s_ef[arow + 4]);
            unsigned a3 = __float_as_uint(s_ef[arow + 8 * PITCH1 + 4]);
            #pragma unroll
            for (int sub = 0; sub < 8; sub++) {
                int n0 = wc * 64 + sub * 8;
                unsigned b0 = __float_as_uint(s_b[(ks + q) * PITCH1 + n0 + g]);
                unsigned b1 = __float_as_uint(s_b[(ks + q + 4) * PITCH1 + n0 + g]);
                mma_tf32(acc[sub], a0, a1, a2, a3, b0, b1);
            }
        }
    }
    __syncthreads();

    // --- hidden = relu(acc + bp1), stored tf32 into s_ef ---
    {
        int r0 = wr * 16 + g;
        #pragma unroll
        for (int sub = 0; sub < 8; sub++) {
            int n0 = wc * 64 + sub * 8 + 2 * q;
            float bx = bp1[n0], by = bp1[n0 + 1];
            s_ef[r0 * PITCH1 + n0]           = to_tf32(fmaxf(acc[sub][0] + bx, 0.f));
            s_ef[r0 * PITCH1 + n0 + 1]       = to_tf32(fmaxf(acc[sub][1] + by, 0.f));
            s_ef[(r0 + 8) * PITCH1 + n0]     = to_tf32(fmaxf(acc[sub][2] + bx, 0.f));
            s_ef[(r0 + 8) * PITCH1 + n0 + 1] = to_tf32(fmaxf(acc[sub][3] + by, 0.f));
        }
    }

    // --- GEMM2 ---
    float acc2[4][4];
    #pragma unroll
    for (int s = 0; s < 4; s++)
        #pragma unroll
        for (int i = 0; i < 4; i++) acc2[s][i] = 0.f;

    for (int k0 = 0; k0 < 256; k0 += 32) {
        __syncthreads();
        const float4* w4 = (const float4*)(Wp2 + k0 * 128);
        for (int i = t; i < 32 * 32; i += 256) {
            int row = i >> 5, c4 = i & 31;
            float4 v = w4[row * 32 + c4];
            v.x = to_tf32(v.x); v.y = to_tf32(v.y);
            v.z = to_tf32(v.z); v.w = to_tf32(v.w);
            *(float4*)&s_b[row * PITCH2 + c4 * 4] = v;
        }
        __syncthreads();
        #pragma unroll
        for (int ks = 0; ks < 32; ks += 8) {
            int arow = (wr * 16 + g) * PITCH1 + k0 + ks + q;
            unsigned a0 = __float_as_uint(s_ef[arow]);
            unsigned a1 = __float_as_uint(s_ef[arow + 8 * PITCH1]);
            unsigned a2 = __float_as_uint(s_ef[arow + 4]);
            unsigned a3 = __float_as_uint(s_ef[arow + 8 * PITCH1 + 4]);
            #pragma unroll
            for (int sub = 0; sub < 4; sub++) {
                int n0 = wc * 32 + sub * 8;
                unsigned b0 = __float_as_uint(s_b[(ks + q) * PITCH2 + n0 + g]);
                unsigned b1 = __float_as_uint(s_b[(ks + q + 4) * PITCH2 + n0 + g]);
                mma_tf32(acc2[sub], a0, a1, a2, a3, b0, b1);
            }
        }
    }

    // --- output ---
    {
        int er0 = e0 + wr * 16 + g;
        #pragma unroll
        for (int sub = 0; sub < 4; sub++) {
            int n0 = wc * 32 + sub * 8 + 2 * q;
            float bx = bp2[n0], by = bp2[n0 + 1];
            if (er0 < E) {
                float2 v = make_float2(acc2[sub][0] + bx, acc2[sub][1] + by);
                *(float2*)&out[(size_t)er0 * 128 + n0] = v;
            }
            if (er0 + 8 < E) {
                float2 v = make_float2(acc2[sub][2] + bx, acc2[sub][3] + by);
                *(float2*)&out[(size_t)(er0 + 8) * 128 + n0] = v;
            }
        }
    }
}

// ---------------------------------------------------------------------------
extern "C" void kernel_launch(void* const* d_in, const int* in_sizes, int n_in,
                              void* d_out, int out_size)
{
    const float* x   = (const float*)d_in[0];
    const int*   ei  = (const int*)d_in[1];
    const float* W1  = (const float*)d_in[2];
    const float* b1  = (const float*)d_in[3];
    const float* W2  = (const float*)d_in[4];
    const float* b2  = (const float*)d_in[5];
    const float* Wp1 = (const float*)d_in[6];
    const float* bp1 = (const float*)d_in[7];
    const float* Wp2 = (const float*)d_in[8];
    const float* bp2 = (const float*)d_in[9];
    const float* Wc  = (const float*)d_in[10];
    const float* bc  = (const float*)d_in[11];

    int n = in_sizes[0] / 256;
    int E = in_sizes[1] / 2;

    float* out    = (float*)d_out;
    float* f      = out;
    float* ef_out = f + (long long)n * 128;
    float* logits = ef_out + (long long)E * 128;
    float* ei_out = logits + (long long)n * 40;

    float *xw, *h, *hw, *deg;
    cudaGetSymbolAddress((void**)&xw,  g_xw);
    cudaGetSymbolAddress((void**)&h,   g_h);
    cudaGetSymbolAddress((void**)&hw,  g_hw);
    cudaGetSymbolAddress((void**)&deg, g_deg);

    // degree normalization
    k_init_deg<<<(n + 255) / 256, 256>>>(deg, n);
    k_count_deg<<<(E + 255) / 256, 256>>>(ei, deg, E);
    k_rsqrt<<<(n + 255) / 256, 256>>>(deg, n);

    // layer 1
    k_sgemm<<<dim3(4, (n + 63) / 64), 256>>>(n, 256, 256, x, W1, nullptr, xw, 0);
    cudaMemsetAsync(h, 0, (size_t)n * 256 * sizeof(float));
    {
        long long tot = (long long)E * 64;
        k_agg<<<(unsigned)((tot + 255) / 256), 256>>>(ei, deg, xw, h, E, 6);
    }
    {
        long long tot = (long long)n * 64;
        k_finalize<<<(unsigned)((tot + 255) / 256), 256>>>(h, xw, deg, b1, n, 6, 1);
    }

    // layer 2
    k_sgemm<<<dim3(2, (n + 63) / 64), 256>>>(n, 128, 256, h, W2, nullptr, hw, 0);
    cudaMemsetAsync(f, 0, (size_t)n * 128 * sizeof(float));
    {
        long long tot = (long long)E * 32;
        k_agg<<<(unsigned)((tot + 255) / 256), 256>>>(ei, deg, hw, f, E, 5);
    }
    {
        long long tot = (long long)n * 32;
        k_finalize<<<(unsigned)((tot + 255) / 256), 256>>>(f, hw, deg, b2, n, 5, 0);
    }

    // classifier
    k_sgemm<<<dim3(1, (n + 63) / 64), 256>>>(n, 40, 128, f, Wc, bc, logits, 0);

    // edge_index passthrough
    k_copy_ei<<<(2 * E + 255) / 256, 256>>>(ei, ei_out, 2 * E);

    // edge MLP (tensor cores)
    k_edge_mlp_tc<<<(E + TE - 1) / TE, 256>>>(ei, f, Wp1, bp1, Wp2, bp2, ef_out, E);
}

// round 4
// speedup vs baseline: 5.3085x; 1.5535x over previous
#include <cuda_runtime.h>
#include <cuda_bf16.h>

// ---------------------------------------------------------------------------
// GraphEncoder: 2-layer GCN + edge MLP + classifier.
// Output (f32): f[N,128], edge_feats[E,128], logits[N,40], edge_index (float).
// ---------------------------------------------------------------------------

#define MAXN 100000
#define MAXE 800000

__device__ float g_xw[(size_t)MAXN * 256];   // scaled: dinv[r] * (x@W1)[r]
__device__ float g_h [(size_t)MAXN * 256];   // layer-1 accumulator
__device__ float g_hw[(size_t)MAXN * 128];   // scaled: dinv[r] * (relu(h)@W2)[r]
__device__ float g_deg[MAXN];
__device__ float g_W1c [256 * 256];          // tf32 pre-converted weights
__device__ float g_W2c [256 * 128];
__device__ float g_Wp1c[256 * 256];
__device__ float g_Wp2c[256 * 128];

// ---------------------------------------------------------------------------
__device__ __forceinline__ float to_tf32(float x) {
    float r;
    asm("cvt.rna.tf32.f32 %0, %1;" : "=f"(r) : "f"(x));
    return r;
}

__device__ __forceinline__ void mma_tf32(float c[4],
    unsigned a0, unsigned a1, unsigned a2, unsigned a3,
    unsigned b0, unsigned b1)
{
    asm volatile(
        "mma.sync.aligned.m16n8k8.row.col.f32.tf32.tf32.f32 "
        "{%0,%1,%2,%3}, {%4,%5,%6,%7}, {%8,%9}, {%0,%1,%2,%3};"
        : "+f"(c[0]), "+f"(c[1]), "+f"(c[2]), "+f"(c[3])
        : "r"(a0), "r"(a1), "r"(a2), "r"(a3), "r"(b0), "r"(b1));
}

// ---------------------------------------------------------------------------
__global__ void k_cvt(const float* __restrict__ src, float* __restrict__ dst, int n) {
    int i = blockIdx.x * blockDim.x + threadIdx.x;
    if (i < n) dst[i] = to_tf32(src[i]);
}

__global__ void k_init_deg(float* deg, int n) {
    int i = blockIdx.x * blockDim.x + threadIdx.x;
    if (i < n) deg[i] = 1.0f;
}

__global__ void k_count_deg(const int* __restrict__ ei, float* deg, int E) {
    int e = blockIdx.x * blockDim.x + threadIdx.x;
    if (e < E) atomicAdd(&deg[ei[E + e]], 1.0f);
}

__global__ void k_rsqrt(float* deg, int n) {
    int i = blockIdx.x * blockDim.x + threadIdx.x;
    if (i < n) deg[i] = rsqrtf(deg[i]);
}

// ---------------------------------------------------------------------------
// tf32 tensor-core node GEMM. BM=64, BN=128, BK=32; 8 warps (2x4), warp tile
// 32x32. A fp32 (optional relu on load), B pre-converted tf32 [K,N].
// Epilogue: Cs[r] = dinv[r]*v  (scaled scratch for aggregation)
//           Ci[r] = dinv[r]*Cs[r] + bias[c]  (self-loop init of accumulator)
#define GP_A 36     // pitch % 32 == 4 -> conflict-free A-frag loads
#define GP_B 136    // pitch % 32 == 8 -> conflict-free B-frag loads
__global__ __launch_bounds__(256)
void k_gemm_tc(int M, int K, int N,
               const float* __restrict__ A, int reluA,
               const float* __restrict__ Bc,
               const float* __restrict__ dinv,
               const float* __restrict__ bias,
               float* __restrict__ Cs, float* __restrict__ Ci)
{
    __shared__ float s_a[64 * GP_A];
    __shared__ float s_b[32 * GP_B];
    int t = threadIdx.x;
    int lane = t & 31, w = t >> 5;
    int g = lane >> 2, q = lane & 3;
    int wr = w >> 2, wc = w & 3;         // 2 x 4 warp grid
    int row0 = blockIdx.y * 64;
    int col0 = blockIdx.x * 128;

    float acc[2][4][4] = {};

    for (int k0 = 0; k0 < K; k0 += 32) {
        __syncthreads();
        // A tile 64x32
        for (int i = t; i < 512; i += 256) {
            int r = i >> 3, c4 = i & 7;
            int gr = row0 + r;
            float4 v = make_float4(0.f, 0.f, 0.f, 0.f);
            if (gr < M) v = *(const float4*)&A[(size_t)gr * K + k0 + c4 * 4];
            if (reluA) {
                v.x = fmaxf(v.x, 0.f); v.y = fmaxf(v.y, 0.f);
                v.z = fmaxf(v.z, 0.f); v.w = fmaxf(v.w, 0.f);
            }
            v.x = to_tf32(v.x); v.y = to_tf32(v.y);
            v.z = to_tf32(v.z); v.w = to_tf32(v.w);
            *(float4*)&s_a[r * GP_A + c4 * 4] = v;
        }
        // B tile 32x128 (already tf32)
        for (int i = t; i < 1024; i += 256) {
            int r = i >> 5, c4 = i & 31;
            float4 v = *(const float4*)&Bc[(size_t)(k0 + r) * N + col0 + c4 * 4];
            *(float4*)&s_b[r * GP_B + c4 * 4] = v;
        }
        __syncthreads();
        #pragma unroll
        for (int ks = 0; ks < 32; ks += 8) {
            unsigned af[2][4];
            #pragma unroll
            for (int ms = 0; ms < 2; ms++) {
                int ar = (wr * 32 + ms * 16 + g) * GP_A + ks + q;
                af[ms][0] = __float_as_uint(s_a[ar]);
                af[ms][1] = __float_as_uint(s_a[ar + 8 * GP_A]);
                af[ms][2] = __float_as_uint(s_a[ar + 4]);
                af[ms][3] = __float_as_uint(s_a[ar + 8 * GP_A + 4]);
            }
            #pragma unroll
            for (int ns = 0; ns < 4; ns++) {
                int n0 = wc * 32 + ns * 8;
                unsigned b0 = __float_as_uint(s_b[(ks + q) * GP_B + n0 + g]);
                unsigned b1 = __float_as_uint(s_b[(ks + q + 4) * GP_B + n0 + g]);
                mma_tf32(acc[0][ns], af[0][0], af[0][1], af[0][2], af[0][3], b0, b1);
                mma_tf32(acc[1][ns], af[1][0], af[1][1], af[1][2], af[1][3], b0, b1);
            }
        }
    }
    // epilogue
    #pragma unroll
    for (int ms = 0; ms < 2; ms++) {
        #pragma unroll
        for (int ns = 0; ns < 4; ns++) {
            int c = col0 + wc * 32 + ns * 8 + 2 * q;
            float2 bb = *(const float2*)&bias[c];
            int r1 = row0 + wr * 32 + ms * 16 + g;
            if (r1 < M) {
                float d = dinv[r1];
                float s0 = d * acc[ms][ns][0], s1 = d * acc[ms][ns][1];
                *(float2*)&Cs[(size_t)r1 * N + c] = make_float2(s0, s1);
                *(float2*)&Ci[(size_t)r1 * N + c] =
                    make_float2(fmaf(d, s0, bb.x), fmaf(d, s1, bb.y));
            }
            int r2 = r1 + 8;
            if (r2 < M) {
                float d = dinv[r2];
                float s0 = d * acc[ms][ns][2], s1 = d * acc[ms][ns][3];
                *(float2*)&Cs[(size_t)r2 * N + c] = make_float2(s0, s1);
                *(float2*)&Ci[(size_t)r2 * N + c] =
                    make_float2(fmaf(d, s0, bb.x), fmaf(d, s1, bb.y));
            }
        }
    }
}

// ---------------------------------------------------------------------------
// fp32 SGEMM (classifier only: N=40)
__global__ __launch_bounds__(256)
void k_sgemm(int M, int N, int K,
             const float* __restrict__ A, const float* __restrict__ B,
             const float* __restrict__ bias, float* __restrict__ C, int relu)
{
    __shared__ float As[64 * 16];
    __shared__ float Bs[16 * 64];
    int t = threadIdx.x;
    int tx = t & 15, ty = t >> 4;
    int row0 = blockIdx.y * 64, col0 = blockIdx.x * 64;
    float acc[4][4] = {};

    for (int k0 = 0; k0 < K; k0 += 16) {
        for (int i = t; i < 64 * 16; i += 256) {
            int r = i >> 4, c = i & 15;
            int gr = row0 + r, gc = k0 + c;
            As[i] = (gr < M && gc < K) ? A[(long long)gr * K + gc] : 0.f;
        }
        for (int i = t; i < 16 * 64; i += 256) {
            int r = i >> 6, c = i & 63;
            int gr = k0 + r, gc = col0 + c;
            Bs[i] = (gr < K && gc < N) ? B[(long long)gr * N + gc] : 0.f;
        }
        __syncthreads();
        #pragma unroll
        for (int kk = 0; kk < 16; kk++) {
            float a[4], b[4];
            #pragma unroll
            for (int m = 0; m < 4; m++) a[m] = As[(ty * 4 + m) * 16 + kk];
            #pragma unroll
            for (int nn = 0; nn < 4; nn++) b[nn] = Bs[kk * 64 + tx * 4 + nn];
            #pragma unroll
            for (int m = 0; m < 4; m++)
                #pragma unroll
                for (int nn = 0; nn < 4; nn++)
                    acc[m][nn] += a[m] * b[nn];
        }
        __syncthreads();
    }
    #pragma unroll
    for (int m = 0; m < 4; m++) {
        int r = row0 + ty * 4 + m;
        if (r >= M) continue;
        #pragma unroll
        for (int nn = 0; nn < 4; nn++) {
            int c = col0 + tx * 4 + nn;
            if (c >= N) continue;
            float v = acc[m][nn] + (bias ? bias[c] : 0.f);
            if (relu) v = fmaxf(v, 0.f);
            C[(long long)r * N + c] = v;
        }
    }
}

// ---------------------------------------------------------------------------
// Edge scatter: dst[c] += dinv[c] * src_scaled[r]   (src pre-scaled by dinv[r])
__global__ void k_agg(const int* __restrict__ ei,
                      const float* __restrict__ dinv,
                      const float* __restrict__ src,
                      float* __restrict__ dst, int E, int logF4)
{
    long long idx = (long long)blockIdx.x * blockDim.x + threadIdx.x;
    int F4 = 1 << logF4;
    if (idx >= ((long long)E << logF4)) return;
    int e = (int)(idx >> logF4);
    int j = (int)(idx & (F4 - 1));
    int r = ei[e];
    int c = ei[E + e];
    float w = dinv[c];
    float4 v = ((const float4*)src)[(long long)r * F4 + j];
    float* d = dst + (((long long)c * F4 + j) << 2);
    asm volatile("red.global.add.v4.f32 [%0], {%1,%2,%3,%4};"
                 :: "l"(d), "f"(w * v.x), "f"(w * v.y), "f"(w * v.z), "f"(w * v.w)
                 : "memory");
}

__global__ void k_copy_ei(const int* __restrict__ ei, float* __restrict__ out, int n2) {
    int i = blockIdx.x * blockDim.x + threadIdx.x;
    if (i < n2) out[i] = (float)ei[i];
}

// ---------------------------------------------------------------------------
// Tensor-core edge MLP, 64 edges/block, 256 threads (8 warps, 2x4 grid).
// GEMM1: [64,256] = ef @ Wp1 ; warp tile 32x64 (2 m-sub x 8 n-sub)
// GEMM2: [64,128] = hid @ Wp2 ; warp tile 32x32 (2 m-sub x 4 n-sub)
#define TE 64
#define PITCH1 260   // % 32 == 4 -> conflict-free A-frag loads
#define PITCHB 264   // % 32 == 8 -> conflict-free B-frag loads (GEMM1)
#define PITCH2 136   // % 32 == 8 (GEMM2)
#define EMLP_SMEM ((TE * PITCH1 + 32 * PITCHB) * 4)
__global__ __launch_bounds__(256)
void k_edge_mlp_tc(const int* __restrict__ ei,
                   const float* __restrict__ f,
                   const float* __restrict__ Wp1c, const float* __restrict__ bp1,
                   const float* __restrict__ Wp2c, const float* __restrict__ bp2,
                   float* __restrict__ out, int E)
{
    extern __shared__ float smem[];
    float* s_ef = smem;                 // 64 x PITCH1
    float* s_b  = smem + TE * PITCH1;   // 32 x PITCHB

    int t = threadIdx.x;
    int lane = t & 31, w = t >> 5;
    int g = lane >> 2, q = lane & 3;
    int wr = w >> 2, wc = w & 3;        // 2 x 4
    int e0 = blockIdx.x * TE;

    // gather ef tile: row = edge, cols [f[src](128) | f[dst](128)]
    const float4* f4 = (const float4*)f;
    for (int i = t; i < TE * 64; i += 256) {
        int row = i >> 6, c4 = i & 63;
        int e = e0 + row;
        float4 v = make_float4(0.f, 0.f, 0.f, 0.f);
        if (e < E) {
            int node = (c4 < 32) ? ei[e] : ei[E + e];
            v = f4[(size_t)node * 32 + (c4 & 31)];
        }
        v.x = to_tf32(v.x); v.y = to_tf32(v.y);
        v.z = to_tf32(v.z); v.w = to_tf32(v.w);
        *(float4*)&s_ef[row * PITCH1 + c4 * 4] = v;
    }

    // ---- GEMM1 ----
    float acc[2][8][4];
    #pragma unroll
    for (int ms = 0; ms < 2; ms++)
        #pragma unroll
        for (int s = 0; s < 8; s++)
            #pragma unroll
            for (int i = 0; i < 4; i++) acc[ms][s][i] = 0.f;

    for (int k0 = 0; k0 < 256; k0 += 32) {
        __syncthreads();
        for (int i = t; i < 32 * 64; i += 256) {
            int row = i >> 6, c4 = i & 63;
            *(float4*)&s_b[row * PITCHB + c4 * 4] =
                *(const float4*)&Wp1c[(size_t)(k0 + row) * 256 + c4 * 4];
        }
        __syncthreads();
        #pragma unroll
        for (int ks = 0; ks < 32; ks += 8) {
            unsigned af[2][4];
            #pragma unroll
            for (int ms = 0; ms < 2; ms++) {
                int ar = (wr * 32 + ms * 16 + g) * PITCH1 + k0 + ks + q;
                af[ms][0] = __float_as_uint(s_ef[ar]);
                af[ms][1] = __float_as_uint(s_ef[ar + 8 * PITCH1]);
                af[ms][2] = __float_as_uint(s_ef[ar + 4]);
                af[ms][3] = __float_as_uint(s_ef[ar + 8 * PITCH1 + 4]);
            }
            #pragma unroll
            for (int ns = 0; ns < 8; ns++) {
                int n0 = wc * 64 + ns * 8;
                unsigned b0 = __float_as_uint(s_b[(ks + q) * PITCHB + n0 + g]);
                unsigned b1 = __float_as_uint(s_b[(ks + q + 4) * PITCHB + n0 + g]);
                mma_tf32(acc[0][ns], af[0][0], af[0][1], af[0][2], af[0][3], b0, b1);
                mma_tf32(acc[1][ns], af[1][0], af[1][1], af[1][2], af[1][3], b0, b1);
            }
        }
    }
    __syncthreads();

    // hidden = relu(acc + bp1) -> s_ef (tf32)
    #pragma unroll
    for (int ms = 0; ms < 2; ms++) {
        int r0 = wr * 32 + ms * 16 + g;
        #pragma unroll
        for (int ns = 0; ns < 8; ns++) {
            int n0 = wc * 64 + ns * 8 + 2 * q;
            float bx = bp1[n0], by = bp1[n0 + 1];
            s_ef[r0 * PITCH1 + n0]           = to_tf32(fmaxf(acc[ms][ns][0] + bx, 0.f));
            s_ef[r0 * PITCH1 + n0 + 1]       = to_tf32(fmaxf(acc[ms][ns][1] + by, 0.f));
            s_ef[(r0 + 8) * PITCH1 + n0]     = to_tf32(fmaxf(acc[ms][ns][2] + bx, 0.f));
            s_ef[(r0 + 8) * PITCH1 + n0 + 1] = to_tf32(fmaxf(acc[ms][ns][3] + by, 0.f));
        }
    }

    // ---- GEMM2 ----
    float acc2[2][4][4];
    #pragma unroll
    for (int ms = 0; ms < 2; ms++)
        #pragma unroll
        for (int s = 0; s < 4; s++)
            #pragma unroll
            for (int i = 0; i < 4; i++) acc2[ms][s][i] = 0.f;

    for (int k0 = 0; k0 < 256; k0 += 32) {
        __syncthreads();
        for (int i = t; i < 32 * 32; i += 256) {
            int row = i >> 5, c4 = i & 31;
            *(float4*)&s_b[row * PITCH2 + c4 * 4] =
                *(const float4*)&Wp2c[(size_t)(k0 + row) * 128 + c4 * 4];
        }
        __syncthreads();
        #pragma unroll
        for (int ks = 0; ks < 32; ks += 8) {
            unsigned af[2][4];
            #pragma unroll
            for (int ms = 0; ms < 2; ms++) {
                int ar = (wr * 32 + ms * 16 + g) * PITCH1 + k0 + ks + q;
                af[ms][0] = __float_as_uint(s_ef[ar]);
                af[ms][1] = __float_as_uint(s_ef[ar + 8 * PITCH1]);
                af[ms][2] = __float_as_uint(s_ef[ar + 4]);
                af[ms][3] = __float_as_uint(s_ef[ar + 8 * PITCH1 + 4]);
            }
            #pragma unroll
            for (int ns = 0; ns < 4; ns++) {
                int n0 = wc * 32 + ns * 8;
                unsigned b0 = __float_as_uint(s_b[(ks + q) * PITCH2 + n0 + g]);
                unsigned b1 = __float_as_uint(s_b[(ks + q + 4) * PITCH2 + n0 + g]);
                mma_tf32(acc2[0][ns], af[0][0], af[0][1], af[0][2], af[0][3], b0, b1);
                mma_tf32(acc2[1][ns], af[1][0], af[1][1], af[1][2], af[1][3], b0, b1);
            }
        }
    }

    // output
    #pragma unroll
    for (int ms = 0; ms < 2; ms++) {
        int er0 = e0 + wr * 32 + ms * 16 + g;
        #pragma unroll
        for (int ns = 0; ns < 4; ns++) {
            int n0 = wc * 32 + ns * 8 + 2 * q;
            float bx = bp2[n0], by = bp2[n0 + 1];
            if (er0 < E)
                *(float2*)&out[(size_t)er0 * 128 + n0] =
                    make_float2(acc2[ms][ns][0] + bx, acc2[ms][ns][1] + by);
            if (er0 + 8 < E)
                *(float2*)&out[(size_t)(er0 + 8) * 128 + n0] =
                    make_float2(acc2[ms][ns][2] + bx, acc2[ms][ns][3] + by);
        }
    }
}

// ---------------------------------------------------------------------------
extern "C" void kernel_launch(void* const* d_in, const int* in_sizes, int n_in,
                              void* d_out, int out_size)
{
    const float* x   = (const float*)d_in[0];
    const int*   ei  = (const int*)d_in[1];
    const float* W1  = (const float*)d_in[2];
    const float* b1  = (const float*)d_in[3];
    const float* W2  = (const float*)d_in[4];
    const float* b2  = (const float*)d_in[5];
    const float* Wp1 = (const float*)d_in[6];
    const float* bp1 = (const float*)d_in[7];
    const float* Wp2 = (const float*)d_in[8];
    const float* bp2 = (const float*)d_in[9];
    const float* Wc  = (const float*)d_in[10];
    const float* bc  = (const float*)d_in[11];

    int n = in_sizes[0] / 256;
    int E = in_sizes[1] / 2;

    float* out    = (float*)d_out;
    float* f      = out;
    float* ef_out = f + (long long)n * 128;
    float* logits = ef_out + (long long)E * 128;
    float* ei_out = logits + (long long)n * 40;

    float *xw, *h, *hw, *deg, *W1c, *W2c, *Wp1c, *Wp2c;
    cudaGetSymbolAddress((void**)&xw,   g_xw);
    cudaGetSymbolAddress((void**)&h,    g_h);
    cudaGetSymbolAddress((void**)&hw,   g_hw);
    cudaGetSymbolAddress((void**)&deg,  g_deg);
    cudaGetSymbolAddress((void**)&W1c,  g_W1c);
    cudaGetSymbolAddress((void**)&W2c,  g_W2c);
    cudaGetSymbolAddress((void**)&Wp1c, g_Wp1c);
    cudaGetSymbolAddress((void**)&Wp2c, g_Wp2c);

    cudaFuncSetAttribute(k_edge_mlp_tc,
                         cudaFuncAttributeMaxDynamicSharedMemorySize, EMLP_SMEM);

    // weight pre-conversion to tf32
    k_cvt<<<(256 * 256 + 255) / 256, 256>>>(W1,  W1c,  256 * 256);
    k_cvt<<<(256 * 128 + 255) / 256, 256>>>(W2,  W2c,  256 * 128);
    k_cvt<<<(256 * 256 + 255) / 256, 256>>>(Wp1, Wp1c, 256 * 256);
    k_cvt<<<(256 * 128 + 255) / 256, 256>>>(Wp2, Wp2c, 256 * 128);

    // degree normalization
    k_init_deg<<<(n + 255) / 256, 256>>>(deg, n);
    k_count_deg<<<(E + 255) / 256, 256>>>(ei, deg, E);
    k_rsqrt<<<(n + 255) / 256, 256>>>(deg, n);

    // layer 1: GEMM (epilogue: xw=dinv*(x@W1), h=dinv*xw+b1) then aggregate
    k_gemm_tc<<<dim3(2, (n + 63) / 64), 256>>>(n, 256, 256, x, 0, W1c, deg, b1, xw, h);
    {
        long long tot = (long long)E * 64;
        k_agg<<<(unsigned)((tot + 255) / 256), 256>>>(ei, deg, xw, h, E, 6);
    }

    // layer 2: A = relu(h) on load; epilogue -> hw scaled, f init
    k_gemm_tc<<<dim3(1, (n + 63) / 64), 256>>>(n, 256, 128, h, 1, W2c, deg, b2, hw, f);
    {
        long long tot = (long long)E * 32;
        k_agg<<<(unsigned)((tot + 255) / 256), 256>>>(ei, deg, hw, f, E, 5);
    }

    // classifier (fp32)
    k_sgemm<<<dim3(1, (n + 63) / 64), 256>>>(n, 40, 128, f, Wc, bc, logits, 0);

    // edge_index passthrough
    k_copy_ei<<<(2 * E + 255) / 256, 256>>>(ei, ei_out, 2 * E);

    // edge MLP
    k_edge_mlp_tc<<<(E + TE - 1) / TE, 256, EMLP_SMEM>>>(ei, f, Wp1c, bp1, Wp2c, bp2, ef_out, E);
}

// round 5
// speedup vs baseline: 5.3743x; 1.0124x over previous
#include <cuda_runtime.h>
#include <cuda_bf16.h>

// ---------------------------------------------------------------------------
// GraphEncoder: 2-layer GCN + edge MLP + classifier.
// Output (f32): f[N,128], edge_feats[E,128], logits[N,40], edge_index (float).
// ---------------------------------------------------------------------------

#define MAXN 100000
#define MAXE 800000

__device__ float g_xw[(size_t)MAXN * 256];   // scaled: dinv[r] * (x@W1)[r]
__device__ float g_h [(size_t)MAXN * 256];   // hidden (post-relu)
__device__ float g_hw[(size_t)MAXN * 128];   // scaled: dinv[r] * (h@W2)[r]
__device__ float g_dinv[MAXN];
__device__ int   g_cnt[MAXN];                // in-degree (excl self)
__device__ int   g_start[MAXN];              // CSR row start
__device__ int   g_cursor[MAXN];             // scatter cursor
__device__ int   g_csr[MAXE];                // src node ids sorted by dst
__device__ int   g_bsum[128];                // scan block sums
__device__ float g_W1c [256 * 256];          // tf32 pre-converted weights
__device__ float g_W2c [256 * 128];
__device__ float g_Wp1c[256 * 256];
__device__ float g_Wp2c[256 * 128];

// ---------------------------------------------------------------------------
__device__ __forceinline__ float to_tf32(float x) {
    float r;
    asm("cvt.rna.tf32.f32 %0, %1;" : "=f"(r) : "f"(x));
    return r;
}

__device__ __forceinline__ void mma_tf32(float c[4],
    unsigned a0, unsigned a1, unsigned a2, unsigned a3,
    unsigned b0, unsigned b1)
{
    asm volatile(
        "mma.sync.aligned.m16n8k8.row.col.f32.tf32.tf32.f32 "
        "{%0,%1,%2,%3}, {%4,%5,%6,%7}, {%8,%9}, {%0,%1,%2,%3};"
        : "+f"(c[0]), "+f"(c[1]), "+f"(c[2]), "+f"(c[3])
        : "r"(a0), "r"(a1), "r"(a2), "r"(a3), "r"(b0), "r"(b1));
}

// ---------------------------------------------------------------------------
__global__ void k_cvt(const float* __restrict__ src, float* __restrict__ dst, int n) {
    int i = blockIdx.x * blockDim.x + threadIdx.x;
    if (i < n) dst[i] = to_tf32(src[i]);
}

__global__ void k_hist(const int* __restrict__ ei, int* __restrict__ cnt, int E) {
    int e = blockIdx.x * blockDim.x + threadIdx.x;
    if (e < E) atomicAdd(&cnt[ei[E + e]], 1);
}

__global__ void k_dinv(const int* __restrict__ cnt, float* __restrict__ dinv, int n) {
    int i = blockIdx.x * blockDim.x + threadIdx.x;
    if (i < n) dinv[i] = rsqrtf((float)(cnt[i] + 1));   // +1 self-loop
}

// ---- exclusive scan (2-level), 1024 elems/block ----
__global__ void k_scan1(const int* __restrict__ in, int* __restrict__ out,
                        int* __restrict__ bsum, int n)
{
    __shared__ int wsum[8];
    int t = threadIdx.x;
    int base = blockIdx.x * 1024 + t * 4;
    int v0 = base + 0 < n ? in[base + 0] : 0;
    int v1 = base + 1 < n ? in[base + 1] : 0;
    int v2 = base + 2 < n ? in[base + 2] : 0;
    int v3 = base + 3 < n ? in[base + 3] : 0;
    int ts = v0 + v1 + v2 + v3;
    int lane = t & 31, w = t >> 5;
    int x = ts;
    #pragma unroll
    for (int o = 1; o < 32; o <<= 1) {
        int y = __shfl_up_sync(0xffffffffu, x, o);
        if (lane >= o) x += y;
    }
    if (lane == 31) wsum[w] = x;
    __syncthreads();
    if (t == 0) {
        int run = 0;
        #pragma unroll
        for (int i = 0; i < 8; i++) { int tmp = wsum[i]; wsum[i] = run; run += tmp; }
        bsum[blockIdx.x] = run;
    }
    __syncthreads();
    int excl = x - ts + wsum[w];
    if (base + 0 < n) out[base + 0] = excl;
    if (base + 1 < n) out[base + 1] = excl + v0;
    if (base + 2 < n) out[base + 2] = excl + v0 + v1;
    if (base + 3 < n) out[base + 3] = excl + v0 + v1 + v2;
}

__global__ void k_scan2(int* bsum, int nb) {
    if (threadIdx.x == 0) {
        int run = 0;
        for (int i = 0; i < nb; i++) { int t = bsum[i]; bsum[i] = run; run += t; }
    }
}

__global__ void k_scan3(int* __restrict__ out, int* __restrict__ cursor,
                        const int* __restrict__ bsum, int n)
{
    int i = blockIdx.x * blockDim.x + threadIdx.x;
    if (i < n) {
        int v = out[i] + bsum[i >> 10];
        out[i] = v;
        cursor[i] = v;
    }
}

__global__ void k_scatter(const int* __restrict__ ei, int* __restrict__ cursor,
                          int* __restrict__ csr, int E)
{
    int e = blockIdx.x * blockDim.x + threadIdx.x;
    if (e < E) {
        int c = ei[E + e];
        int pos = atomicAdd(&cursor[c], 1);
        csr[pos] = ei[e];
    }
}

// ---------------------------------------------------------------------------
// CSR gather-aggregate. WPN warps per node (feature width = WPN*128 floats).
// out[v] = maybe_relu( dinv[v]*(sum_{r in N(v)} srcS[r] + srcS[v]) + bias )
__global__ __launch_bounds__(256)
void k_agg_csr(const int* __restrict__ csr,
               const int* __restrict__ start, const int* __restrict__ cnt,
               const float* __restrict__ dinv,
               const float* __restrict__ srcS,
               const float* __restrict__ bias,
               float* __restrict__ out, int n, int WPN, int relu)
{
    int w = threadIdx.x >> 5, lane = threadIdx.x & 31;
    int npb = 8 / WPN;
    int node = blockIdx.x * npb + w / WPN;
    if (node >= n) return;
    int half = w % WPN;
    int F4 = WPN * 32;
    int col4 = half * 32 + lane;
    const float4* s4 = (const float4*)srcS;
    int s0 = start[node];
    int c0 = cnt[node];
    float ax = 0.f, ay = 0.f, az = 0.f, aw = 0.f;
    for (int b = 0; b < c0; b += 32) {
        int m = min(32, c0 - b);
        int idx = (b + lane < c0) ? csr[s0 + b + lane] : 0;
        for (int j = 0; j < m; j++) {
            int srcn = __shfl_sync(0xffffffffu, idx, j);
            float4 v = s4[(size_t)srcn * F4 + col4];
            ax += v.x; ay += v.y; az += v.z; aw += v.w;
        }
    }
    float4 self = s4[(size_t)node * F4 + col4];
    float d = dinv[node];
    float4 b4 = ((const float4*)bias)[col4];
    float rx = fmaf(d, ax + self.x, b4.x);
    float ry = fmaf(d, ay + self.y, b4.y);
    float rz = fmaf(d, az + self.z, b4.z);
    float rw = fmaf(d, aw + self.w, b4.w);
    if (relu) {
        rx = fmaxf(rx, 0.f); ry = fmaxf(ry, 0.f);
        rz = fmaxf(rz, 0.f); rw = fmaxf(rw, 0.f);
    }
    ((float4*)out)[(size_t)node * F4 + col4] = make_float4(rx, ry, rz, rw);
}

// ---------------------------------------------------------------------------
// tf32 tensor-core node GEMM. BM=64, BN=128, BK=32; 8 warps (2x4).
// Epilogue: Cs[r] = dinv[r] * acc  (pre-scaled scratch for aggregation)
#define GP_A 36
#define GP_B 136
__global__ __launch_bounds__(256)
void k_gemm_tc(int M, int K, int N,
               const float* __restrict__ A, int reluA,
               const float* __restrict__ Bc,
               const float* __restrict__ dinv,
               float* __restrict__ Cs)
{
    __shared__ float s_a[64 * GP_A];
    __shared__ float s_b[32 * GP_B];
    int t = threadIdx.x;
    int lane = t & 31, w = t >> 5;
    int g = lane >> 2, q = lane & 3;
    int wr = w >> 2, wc = w & 3;
    int row0 = blockIdx.y * 64;
    int col0 = blockIdx.x * 128;

    float acc[2][4][4] = {};

    for (int k0 = 0; k0 < K; k0 += 32) {
        __syncthreads();
        for (int i = t; i < 512; i += 256) {
            int r = i >> 3, c4 = i & 7;
            int gr = row0 + r;
            float4 v = make_float4(0.f, 0.f, 0.f, 0.f);
            if (gr < M) v = *(const float4*)&A[(size_t)gr * K + k0 + c4 * 4];
            if (reluA) {
                v.x = fmaxf(v.x, 0.f); v.y = fmaxf(v.y, 0.f);
                v.z = fmaxf(v.z, 0.f); v.w = fmaxf(v.w, 0.f);
            }
            v.x = to_tf32(v.x); v.y = to_tf32(v.y);
            v.z = to_tf32(v.z); v.w = to_tf32(v.w);
            *(float4*)&s_a[r * GP_A + c4 * 4] = v;
        }
        for (int i = t; i < 1024; i += 256) {
            int r = i >> 5, c4 = i & 31;
            float4 v = *(const float4*)&Bc[(size_t)(k0 + r) * N + col0 + c4 * 4];
            *(float4*)&s_b[r * GP_B + c4 * 4] = v;
        }
        __syncthreads();
        #pragma unroll
        for (int ks = 0; ks < 32; ks += 8) {
            unsigned af[2][4];
            #pragma unroll
            for (int ms = 0; ms < 2; ms++) {
                int ar = (wr * 32 + ms * 16 + g) * GP_A + ks + q;
                af[ms][0] = __float_as_uint(s_a[ar]);
                af[ms][1] = __float_as_uint(s_a[ar + 8 * GP_A]);
                af[ms][2] = __float_as_uint(s_a[ar + 4]);
                af[ms][3] = __float_as_uint(s_a[ar + 8 * GP_A + 4]);
            }
            #pragma unroll
            for (int ns = 0; ns < 4; ns++) {
                int n0 = wc * 32 + ns * 8;
                unsigned b0 = __float_as_uint(s_b[(ks + q) * GP_B + n0 + g]);
                unsigned b1 = __float_as_uint(s_b[(ks + q + 4) * GP_B + n0 + g]);
                mma_tf32(acc[0][ns], af[0][0], af[0][1], af[0][2], af[0][3], b0, b1);
                mma_tf32(acc[1][ns], af[1][0], af[1][1], af[1][2], af[1][3], b0, b1);
            }
        }
    }
    #pragma unroll
    for (int ms = 0; ms < 2; ms++) {
        #pragma unroll
        for (int ns = 0; ns < 4; ns++) {
            int c = col0 + wc * 32 + ns * 8 + 2 * q;
            int r1 = row0 + wr * 32 + ms * 16 + g;
            if (r1 < M) {
                float d = dinv[r1];
                *(float2*)&Cs[(size_t)r1 * N + c] =
                    make_float2(d * acc[ms][ns][0], d * acc[ms][ns][1]);
            }
            int r2 = r1 + 8;
            if (r2 < M) {
                float d = dinv[r2];
                *(float2*)&Cs[(size_t)r2 * N + c] =
                    make_float2(d * acc[ms][ns][2], d * acc[ms][ns][3]);
            }
        }
    }
}

// ---------------------------------------------------------------------------
// fp32 SGEMM (classifier only: N=40)
__global__ __launch_bounds__(256)
void k_sgemm(int M, int N, int K,
             const float* __restrict__ A, const float* __restrict__ B,
             const float* __restrict__ bias, float* __restrict__ C, int relu)
{
    __shared__ float As[64 * 16];
    __shared__ float Bs[16 * 64];
    int t = threadIdx.x;
    int tx = t & 15, ty = t >> 4;
    int row0 = blockIdx.y * 64, col0 = blockIdx.x * 64;
    float acc[4][4] = {};

    for (int k0 = 0; k0 < K; k0 += 16) {
        for (int i = t; i < 64 * 16; i += 256) {
            int r = i >> 4, c = i & 15;
            int gr = row0 + r, gc = k0 + c;
            As[i] = (gr < M && gc < K) ? A[(long long)gr * K + gc] : 0.f;
        }
        for (int i = t; i < 16 * 64; i += 256) {
            int r = i >> 6, c = i & 63;
            int gr = k0 + r, gc = col0 + c;
            Bs[i] = (gr < K && gc < N) ? B[(long long)gr * N + gc] : 0.f;
        }
        __syncthreads();
        #pragma unroll
        for (int kk = 0; kk < 16; kk++) {
            float a[4], b[4];
            #pragma unroll
            for (int m = 0; m < 4; m++) a[m] = As[(ty * 4 + m) * 16 + kk];
            #pragma unroll
            for (int nn = 0; nn < 4; nn++) b[nn] = Bs[kk * 64 + tx * 4 + nn];
            #pragma unroll
            for (int m = 0; m < 4; m++)
                #pragma unroll
                for (int nn = 0; nn < 4; nn++)
                    acc[m][nn] += a[m] * b[nn];
        }
        __syncthreads();
    }
    #pragma unroll
    for (int m = 0; m < 4; m++) {
        int r = row0 + ty * 4 + m;
        if (r >= M) continue;
        #pragma unroll
        for (int nn = 0; nn < 4; nn++) {
            int c = col0 + tx * 4 + nn;
            if (c >= N) continue;
            float v = acc[m][nn] + (bias ? bias[c] : 0.f);
            if (relu) v = fmaxf(v, 0.f);
            C[(long long)r * N + c] = v;
        }
    }
}

__global__ void k_copy_ei(const int* __restrict__ ei, float* __restrict__ out, int n2) {
    int i = blockIdx.x * blockDim.x + threadIdx.x;
    if (i < n2) out[i] = (float)ei[i];
}

// ---------------------------------------------------------------------------
// Tensor-core edge MLP: 128 edges/block, 512 threads (16 warps, 4x4 grid).
// GEMM1: [128,256] = ef @ Wp1 ; warp tile 32x64
// GEMM2: [128,128] = hid @ Wp2 ; warp tile 32x32
#define TE 128
#define PITCH1 260   // % 32 == 4
#define PITCHB 264   // % 32 == 8
#define PITCH2 136   // % 32 == 8
#define EMLP_SMEM ((TE * PITCH1 + 32 * PITCHB) * 4)
__global__ __launch_bounds__(512, 1)
void k_edge_mlp_tc(const int* __restrict__ ei,
                   const float* __restrict__ f,
                   const float* __restrict__ Wp1c, const float* __restrict__ bp1,
                   const float* __restrict__ Wp2c, const float* __restrict__ bp2,
                   float* __restrict__ out, int E)
{
    extern __shared__ float smem[];
    float* s_ef = smem;                 // TE x PITCH1
    float* s_b  = smem + TE * PITCH1;   // 32 x PITCHB

    int t = threadIdx.x;
    int lane = t & 31, w = t >> 5;
    int g = lane >> 2, q = lane & 3;
    int wr = w >> 2, wc = w & 3;        // 4 x 4
    int e0 = blockIdx.x * TE;

    // gather ef tile
    const float4* f4 = (const float4*)f;
    for (int i = t; i < TE * 64; i += 512) {
        int row = i >> 6, c4 = i & 63;
        int e = e0 + row;
        float4 v = make_float4(0.f, 0.f, 0.f, 0.f);
        if (e < E) {
            int node = (c4 < 32) ? ei[e] : ei[E + e];
            v = f4[(size_t)node * 32 + (c4 & 31)];
        }
        v.x = to_tf32(v.x); v.y = to_tf32(v.y);
        v.z = to_tf32(v.z); v.w = to_tf32(v.w);
        *(float4*)&s_ef[row * PITCH1 + c4 * 4] = v;
    }

    // ---- GEMM1 ----
    float acc[2][8][4];
    #pragma unroll
    for (int ms = 0; ms < 2; ms++)
        #pragma unroll
        for (int s = 0; s < 8; s++)
            #pragma unroll
            for (int i = 0; i < 4; i++) acc[ms][s][i] = 0.f;

    for (int k0 = 0; k0 < 256; k0 += 32) {
        __syncthreads();
        for (int i = t; i < 32 * 64; i += 512) {
            int row = i >> 6, c4 = i & 63;
            *(float4*)&s_b[row * PITCHB + c4 * 4] =
                *(const float4*)&Wp1c[(size_t)(k0 + row) * 256 + c4 * 4];
        }
        __syncthreads();
        #pragma unroll
        for (int ks = 0; ks < 32; ks += 8) {
            unsigned af[2][4];
            #pragma unroll
            for (int ms = 0; ms < 2; ms++) {
                int ar = (wr * 32 + ms * 16 + g) * PITCH1 + k0 + ks + q;
                af[ms][0] = __float_as_uint(s_ef[ar]);
                af[ms][1] = __float_as_uint(s_ef[ar + 8 * PITCH1]);
                af[ms][2] = __float_as_uint(s_ef[ar + 4]);
                af[ms][3] = __float_as_uint(s_ef[ar + 8 * PITCH1 + 4]);
            }
            #pragma unroll
            for (int ns = 0; ns < 8; ns++) {
                int n0 = wc * 64 + ns * 8;
                unsigned b0 = __float_as_uint(s_b[(ks + q) * PITCHB + n0 + g]);
                unsigned b1 = __float_as_uint(s_b[(ks + q + 4) * PITCHB + n0 + g]);
                mma_tf32(acc[0][ns], af[0][0], af[0][1], af[0][2], af[0][3], b0, b1);
                mma_tf32(acc[1][ns], af[1][0], af[1][1], af[1][2], af[1][3], b0, b1);
            }
        }
    }
    __syncthreads();

    // hidden = relu(acc + bp1) -> s_ef (tf32)
    #pragma unroll
    for (int ms = 0; ms < 2; ms++) {
        int r0 = wr * 32 + ms * 16 + g;
        #pragma unroll
        for (int ns = 0; ns < 8; ns++) {
            int n0 = wc * 64 + ns * 8 + 2 * q;
            float bx = bp1[n0], by = bp1[n0 + 1];
            s_ef[r0 * PITCH1 + n0]           = to_tf32(fmaxf(acc[ms][ns][0] + bx, 0.f));
            s_ef[r0 * PITCH1 + n0 + 1]       = to_tf32(fmaxf(acc[ms][ns][1] + by, 0.f));
            s_ef[(r0 + 8) * PITCH1 + n0]     = to_tf32(fmaxf(acc[ms][ns][2] + bx, 0.f));
            s_ef[(r0 + 8) * PITCH1 + n0 + 1] = to_tf32(fmaxf(acc[ms][ns][3] + by, 0.f));
        }
    }

    // ---- GEMM2 ----
    float acc2[2][4][4];
    #pragma unroll
    for (int ms = 0; ms < 2; ms++)
        #pragma unroll
        for (int s = 0; s < 4; s++)
            #pragma unroll
            for (int i = 0; i < 4; i++) acc2[ms][s][i] = 0.f;

    for (int k0 = 0; k0 < 256; k0 += 32) {
        __syncthreads();
        for (int i = t; i < 32 * 32; i += 512) {
            int row = i >> 5, c4 = i & 31;
            *(float4*)&s_b[row * PITCH2 + c4 * 4] =
                *(const float4*)&Wp2c[(size_t)(k0 + row) * 128 + c4 * 4];
        }
        __syncthreads();
        #pragma unroll
        for (int ks = 0; ks < 32; ks += 8) {
            unsigned af[2][4];
            #pragma unroll
            for (int ms = 0; ms < 2; ms++) {
                int ar = (wr * 32 + ms * 16 + g) * PITCH1 + k0 + ks + q;
                af[ms][0] = __float_as_uint(s_ef[ar]);
                af[ms][1] = __float_as_uint(s_ef[ar + 8 * PITCH1]);
                af[ms][2] = __float_as_uint(s_ef[ar + 4]);
                af[ms][3] = __float_as_uint(s_ef[ar + 8 * PITCH1 + 4]);
            }
            #pragma unroll
            for (int ns = 0; ns < 4; ns++) {
                int n0 = wc * 32 + ns * 8;
                unsigned b0 = __float_as_uint(s_b[(ks + q) * PITCH2 + n0 + g]);
                unsigned b1 = __float_as_uint(s_b[(ks + q + 4) * PITCH2 + n0 + g]);
                mma_tf32(acc2[0][ns], af[0][0], af[0][1], af[0][2], af[0][3], b0, b1);
                mma_tf32(acc2[1][ns], af[1][0], af[1][1], af[1][2], af[1][3], b0, b1);
            }
        }
    }

    // output
    #pragma unroll
    for (int ms = 0; ms < 2; ms++) {
        int er0 = e0 + wr * 32 + ms * 16 + g;
        #pragma unroll
        for (int ns = 0; ns < 4; ns++) {
            int n0 = wc * 32 + ns * 8 + 2 * q;
            float bx = bp2[n0], by = bp2[n0 + 1];
            if (er0 < E)
                *(float2*)&out[(size_t)er0 * 128 + n0] =
                    make_float2(acc2[ms][ns][0] + bx, acc2[ms][ns][1] + by);
            if (er0 + 8 < E)
                *(float2*)&out[(size_t)(er0 + 8) * 128 + n0] =
                    make_float2(acc2[ms][ns][2] + bx, acc2[ms][ns][3] + by);
        }
    }
}

// ---------------------------------------------------------------------------
extern "C" void kernel_launch(void* const* d_in, const int* in_sizes, int n_in,
                              void* d_out, int out_size)
{
    const float* x   = (const float*)d_in[0];
    const int*   ei  = (const int*)d_in[1];
    const float* W1  = (const float*)d_in[2];
    const float* b1  = (const float*)d_in[3];
    const float* W2  = (const float*)d_in[4];
    const float* b2  = (const float*)d_in[5];
    const float* Wp1 = (const float*)d_in[6];
    const float* bp1 = (const float*)d_in[7];
    const float* Wp2 = (const float*)d_in[8];
    const float* bp2 = (const float*)d_in[9];
    const float* Wc  = (const float*)d_in[10];
    const float* bc  = (const float*)d_in[11];

    int n = in_sizes[0] / 256;
    int E = in_sizes[1] / 2;

    float* out    = (float*)d_out;
    float* f      = out;
    float* ef_out = f + (long long)n * 128;
    float* logits = ef_out + (long long)E * 128;
    float* ei_out = logits + (long long)n * 40;

    float *xw, *h, *hw, *dinv, *W1c, *W2c, *Wp1c, *Wp2c;
    int *cnt, *startp, *cursor, *csr, *bsum;
    cudaGetSymbolAddress((void**)&xw,     g_xw);
    cudaGetSymbolAddress((void**)&h,      g_h);
    cudaGetSymbolAddress((void**)&hw,     g_hw);
    cudaGetSymbolAddress((void**)&dinv,   g_dinv);
    cudaGetSymbolAddress((void**)&cnt,    g_cnt);
    cudaGetSymbolAddress((void**)&startp, g_start);
    cudaGetSymbolAddress((void**)&cursor, g_cursor);
    cudaGetSymbolAddress((void**)&csr,    g_csr);
    cudaGetSymbolAddress((void**)&bsum,   g_bsum);
    cudaGetSymbolAddress((void**)&W1c,    g_W1c);
    cudaGetSymbolAddress((void**)&W2c,    g_W2c);
    cudaGetSymbolAddress((void**)&Wp1c,   g_Wp1c);
    cudaGetSymbolAddress((void**)&Wp2c,   g_Wp2c);

    cudaFuncSetAttribute(k_edge_mlp_tc,
                         cudaFuncAttributeMaxDynamicSharedMemorySize, EMLP_SMEM);

    // weight pre-conversion to tf32
    k_cvt<<<(256 * 256 + 255) / 256, 256>>>(W1,  W1c,  256 * 256);
    k_cvt<<<(256 * 128 + 255) / 256, 256>>>(W2,  W2c,  256 * 128);
    k_cvt<<<(256 * 256 + 255) / 256, 256>>>(Wp1, Wp1c, 256 * 256);
    k_cvt<<<(256 * 128 + 255) / 256, 256>>>(Wp2, Wp2c, 256 * 128);

    // CSR build: histogram -> scan -> scatter; dinv from degree
    cudaMemsetAsync(cnt, 0, (size_t)n * sizeof(int));
    k_hist<<<(E + 255) / 256, 256>>>(ei, cnt, E);
    k_dinv<<<(n + 255) / 256, 256>>>(cnt, dinv, n);
    int nb = (n + 1023) / 1024;
    k_scan1<<<nb, 256>>>(cnt, startp, bsum, n);
    k_scan2<<<1, 32>>>(bsum, nb);
    k_scan3<<<(n + 255) / 256, 256>>>(startp, cursor, bsum, n);
    k_scatter<<<(E + 255) / 256, 256>>>(ei, cursor, csr, E);

    // layer 1: xw = dinv*(x@W1); h = relu(dinv*(sum+self) + b1)
    k_gemm_tc<<<dim3(2, (n + 63) / 64), 256>>>(n, 256, 256, x, 0, W1c, dinv, xw);
    k_agg_csr<<<(n + 3) / 4, 256>>>(csr, startp, cnt, dinv, xw, b1, h, n, 2, 1);

    // layer 2: hw = dinv*(h@W2); f = dinv*(sum+self) + b2
    k_gemm_tc<<<dim3(1, (n + 63) / 64), 256>>>(n, 256, 128, h, 0, W2c, dinv, hw);
    k_agg_csr<<<(n + 7) / 8, 256>>>(csr, startp, cnt, dinv, hw, b2, f, n, 1, 0);

    // classifier (fp32)
    k_sgemm<<<dim3(1, (n + 63) / 64), 256>>>(n, 40, 128, f, Wc, bc, logits, 0);

    // edge_index passthrough
    k_copy_ei<<<(2 * E + 255) / 256, 256>>>(ei, ei_out, 2 * E);

    // edge MLP
    k_edge_mlp_tc<<<(E + TE - 1) / TE, 512, EMLP_SMEM>>>(ei, f, Wp1c, bp1, Wp2c, bp2, ef_out, E);
}

// round 6
// speedup vs baseline: 5.5083x; 1.0249x over previous
#include <cuda_runtime.h>
#include <cuda_bf16.h>

// ---------------------------------------------------------------------------
// GraphEncoder: 2-layer GCN + edge MLP + classifier.
// Output (f32): f[N,128], edge_feats[E,128], logits[N,40], edge_index (float).
// ---------------------------------------------------------------------------

#define MAXN 100000
#define MAXE 800000

__device__ float g_xw[(size_t)MAXN * 256];   // scaled: dinv[r] * (x@W1)[r]
__device__ float g_h [(size_t)MAXN * 256];   // hidden (post-relu)
__device__ float g_hw[(size_t)MAXN * 128];   // scaled: dinv[r] * (h@W2)[r]
__device__ float g_dinv[MAXN];
__device__ int   g_cnt[MAXN];
__device__ int   g_start[MAXN];
__device__ int   g_cursor[MAXN];
__device__ int   g_csr[MAXE];
__device__ int   g_bsum[128];
__device__ float g_W1c [256 * 256];
__device__ float g_W2c [256 * 128];
__device__ float g_Wp1c[256 * 256];
__device__ float g_Wp2c[256 * 128];

// ---------------------------------------------------------------------------
__device__ __forceinline__ float to_tf32(float x) {
    float r;
    asm("cvt.rna.tf32.f32 %0, %1;" : "=f"(r) : "f"(x));
    return r;
}

__device__ __forceinline__ void mma_tf32(float c[4],
    unsigned a0, unsigned a1, unsigned a2, unsigned a3,
    unsigned b0, unsigned b1)
{
    asm volatile(
        "mma.sync.aligned.m16n8k8.row.col.f32.tf32.tf32.f32 "
        "{%0,%1,%2,%3}, {%4,%5,%6,%7}, {%8,%9}, {%0,%1,%2,%3};"
        : "+f"(c[0]), "+f"(c[1]), "+f"(c[2]), "+f"(c[3])
        : "r"(a0), "r"(a1), "r"(a2), "r"(a3), "r"(b0), "r"(b1));
}

// ---------------------------------------------------------------------------
__global__ void k_cvt(const float* __restrict__ src, float* __restrict__ dst, int n) {
    int i = blockIdx.x * blockDim.x + threadIdx.x;
    if (i < n) dst[i] = to_tf32(src[i]);
}

__global__ void k_hist(const int* __restrict__ ei, int* __restrict__ cnt, int E) {
    int e = blockIdx.x * blockDim.x + threadIdx.x;
    if (e < E) atomicAdd(&cnt[ei[E + e]], 1);
}

__global__ void k_dinv(const int* __restrict__ cnt, float* __restrict__ dinv, int n) {
    int i = blockIdx.x * blockDim.x + threadIdx.x;
    if (i < n) dinv[i] = rsqrtf((float)(cnt[i] + 1));
}

// ---- exclusive scan (2-level) ----
__global__ void k_scan1(const int* __restrict__ in, int* __restrict__ out,
                        int* __restrict__ bsum, int n)
{
    __shared__ int wsum[8];
    int t = threadIdx.x;
    int base = blockIdx.x * 1024 + t * 4;
    int v0 = base + 0 < n ? in[base + 0] : 0;
    int v1 = base + 1 < n ? in[base + 1] : 0;
    int v2 = base + 2 < n ? in[base + 2] : 0;
    int v3 = base + 3 < n ? in[base + 3] : 0;
    int ts = v0 + v1 + v2 + v3;
    int lane = t & 31, w = t >> 5;
    int x = ts;
    #pragma unroll
    for (int o = 1; o < 32; o <<= 1) {
        int y = __shfl_up_sync(0xffffffffu, x, o);
        if (lane >= o) x += y;
    }
    if (lane == 31) wsum[w] = x;
    __syncthreads();
    if (t == 0) {
        int run = 0;
        #pragma unroll
        for (int i = 0; i < 8; i++) { int tmp = wsum[i]; wsum[i] = run; run += tmp; }
        bsum[blockIdx.x] = run;
    }
    __syncthreads();
    int excl = x - ts + wsum[w];
    if (base + 0 < n) out[base + 0] = excl;
    if (base + 1 < n) out[base + 1] = excl + v0;
    if (base + 2 < n) out[base + 2] = excl + v0 + v1;
    if (base + 3 < n) out[base + 3] = excl + v0 + v1 + v2;
}

__global__ void k_scan2(int* bsum, int nb) {
    if (threadIdx.x == 0) {
        int run = 0;
        for (int i = 0; i < nb; i++) { int t = bsum[i]; bsum[i] = run; run += t; }
    }
}

__global__ void k_scan3(int* __restrict__ out, int* __restrict__ cursor,
                        const int* __restrict__ bsum, int n)
{
    int i = blockIdx.x * blockDim.x + threadIdx.x;
    if (i < n) {
        int v = out[i] + bsum[i >> 10];
        out[i] = v;
        cursor[i] = v;
    }
}

__global__ void k_scatter(const int* __restrict__ ei, int* __restrict__ cursor,
                          int* __restrict__ csr, int E)
{
    int e = blockIdx.x * blockDim.x + threadIdx.x;
    if (e < E) {
        int c = ei[E + e];
        int pos = atomicAdd(&cursor[c], 1);
        csr[pos] = ei[e];
    }
}

// ---------------------------------------------------------------------------
// CSR gather-aggregate with 4-way unrolled neighbor loop (MLP=4).
__global__ __launch_bounds__(256)
void k_agg_csr(const int* __restrict__ csr,
               const int* __restrict__ start, const int* __restrict__ cnt,
               const float* __restrict__ dinv,
               const float* __restrict__ srcS,
               const float* __restrict__ bias,
               float* __restrict__ out, int n, int WPN, int relu)
{
    int w = threadIdx.x >> 5, lane = threadIdx.x & 31;
    int npb = 8 / WPN;
    int node = blockIdx.x * npb + w / WPN;
    if (node >= n) return;
    int half = w % WPN;
    int F4 = WPN * 32;
    int col4 = half * 32 + lane;
    const float4* s4 = (const float4*)srcS;
    int s0 = start[node];
    int c0 = cnt[node];
    float ax = 0.f, ay = 0.f, az = 0.f, aw = 0.f;
    for (int b = 0; b < c0; b += 32) {
        int m = min(32, c0 - b);
        int idx = (b + lane < c0) ? csr[s0 + b + lane] : 0;
        int j = 0;
        for (; j + 4 <= m; j += 4) {
            int n0 = __shfl_sync(0xffffffffu, idx, j);
            int n1 = __shfl_sync(0xffffffffu, idx, j + 1);
            int n2 = __shfl_sync(0xffffffffu, idx, j + 2);
            int n3 = __shfl_sync(0xffffffffu, idx, j + 3);
            float4 v0 = s4[(size_t)n0 * F4 + col4];
            float4 v1 = s4[(size_t)n1 * F4 + col4];
            float4 v2 = s4[(size_t)n2 * F4 + col4];
            float4 v3 = s4[(size_t)n3 * F4 + col4];
            ax += (v0.x + v1.x) + (v2.x + v3.x);
            ay += (v0.y + v1.y) + (v2.y + v3.y);
            az += (v0.z + v1.z) + (v2.z + v3.z);
            aw += (v0.w + v1.w) + (v2.w + v3.w);
        }
        for (; j < m; j++) {
            int srcn = __shfl_sync(0xffffffffu, idx, j);
            float4 v = s4[(size_t)srcn * F4 + col4];
            ax += v.x; ay += v.y; az += v.z; aw += v.w;
        }
    }
    float4 self = s4[(size_t)node * F4 + col4];
    float d = dinv[node];
    float4 b4 = ((const float4*)bias)[col4];
    float rx = fmaf(d, ax + self.x, b4.x);
    float ry = fmaf(d, ay + self.y, b4.y);
    float rz = fmaf(d, az + self.z, b4.z);
    float rw = fmaf(d, aw + self.w, b4.w);
    if (relu) {
        rx = fmaxf(rx, 0.f); ry = fmaxf(ry, 0.f);
        rz = fmaxf(rz, 0.f); rw = fmaxf(rw, 0.f);
    }
    ((float4*)out)[(size_t)node * F4 + col4] = make_float4(rx, ry, rz, rw);
}

// ---------------------------------------------------------------------------
// tf32 tensor-core node GEMM. BM=64, BN=128, BK=32; 8 warps (2x4).
#define GP_A 36
#define GP_B 136
__global__ __launch_bounds__(256)
void k_gemm_tc(int M, int K, int N,
               const float* __restrict__ A, int reluA,
               const float* __restrict__ Bc,
               const float* __restrict__ dinv,
               float* __restrict__ Cs)
{
    __shared__ float s_a[64 * GP_A];
    __shared__ float s_b[32 * GP_B];
    int t = threadIdx.x;
    int lane = t & 31, w = t >> 5;
    int g = lane >> 2, q = lane & 3;
    int wr = w >> 2, wc = w & 3;
    int row0 = blockIdx.y * 64;
    int col0 = blockIdx.x * 128;

    float acc[2][4][4] = {};

    for (int k0 = 0; k0 < K; k0 += 32) {
        __syncthreads();
        for (int i = t; i < 512; i += 256) {
            int r = i >> 3, c4 = i & 7;
            int gr = row0 + r;
            float4 v = make_float4(0.f, 0.f, 0.f, 0.f);
            if (gr < M) v = *(const float4*)&A[(size_t)gr * K + k0 + c4 * 4];
            if (reluA) {
                v.x = fmaxf(v.x, 0.f); v.y = fmaxf(v.y, 0.f);
                v.z = fmaxf(v.z, 0.f); v.w = fmaxf(v.w, 0.f);
            }
            v.x = to_tf32(v.x); v.y = to_tf32(v.y);
            v.z = to_tf32(v.z); v.w = to_tf32(v.w);
            *(float4*)&s_a[r * GP_A + c4 * 4] = v;
        }
        for (int i = t; i < 1024; i += 256) {
            int r = i >> 5, c4 = i & 31;
            float4 v = *(const float4*)&Bc[(size_t)(k0 + r) * N + col0 + c4 * 4];
            *(float4*)&s_b[r * GP_B + c4 * 4] = v;
        }
        __syncthreads();
        #pragma unroll
        for (int ks = 0; ks < 32; ks += 8) {
            unsigned af[2][4];
            #pragma unroll
            for (int ms = 0; ms < 2; ms++) {
                int ar = (wr * 32 + ms * 16 + g) * GP_A + ks + q;
                af[ms][0] = __float_as_uint(s_a[ar]);
                af[ms][1] = __float_as_uint(s_a[ar + 8 * GP_A]);
                af[ms][2] = __float_as_uint(s_a[ar + 4]);
                af[ms][3] = __float_as_uint(s_a[ar + 8 * GP_A + 4]);
            }
            #pragma unroll
            for (int ns = 0; ns < 4; ns++) {
                int n0 = wc * 32 + ns * 8;
                unsigned b0 = __float_as_uint(s_b[(ks + q) * GP_B + n0 + g]);
                unsigned b1 = __float_as_uint(s_b[(ks + q + 4) * GP_B + n0 + g]);
                mma_tf32(acc[0][ns], af[0][0], af[0][1], af[0][2], af[0][3], b0, b1);
                mma_tf32(acc[1][ns], af[1][0], af[1][1], af[1][2], af[1][3], b0, b1);
            }
        }
    }
    #pragma unroll
    for (int ms = 0; ms < 2; ms++) {
        #pragma unroll
        for (int ns = 0; ns < 4; ns++) {
            int c = col0 + wc * 32 + ns * 8 + 2 * q;
            int r1 = row0 + wr * 32 + ms * 16 + g;
            if (r1 < M) {
                float d = dinv[r1];
                *(float2*)&Cs[(size_t)r1 * N + c] =
                    make_float2(d * acc[ms][ns][0], d * acc[ms][ns][1]);
            }
            int r2 = r1 + 8;
            if (r2 < M) {
                float d = dinv[r2];
                *(float2*)&Cs[(size_t)r2 * N + c] =
                    make_float2(d * acc[ms][ns][2], d * acc[ms][ns][3]);
            }
        }
    }
}

// ---------------------------------------------------------------------------
// fp32 SGEMM (classifier only: N=40)
__global__ __launch_bounds__(256)
void k_sgemm(int M, int N, int K,
             const float* __restrict__ A, const float* __restrict__ B,
             const float* __restrict__ bias, float* __restrict__ C, int relu)
{
    __shared__ float As[64 * 16];
    __shared__ float Bs[16 * 64];
    int t = threadIdx.x;
    int tx = t & 15, ty = t >> 4;
    int row0 = blockIdx.y * 64, col0 = blockIdx.x * 64;
    float acc[4][4] = {};

    for (int k0 = 0; k0 < K; k0 += 16) {
        for (int i = t; i < 64 * 16; i += 256) {
            int r = i >> 4, c = i & 15;
            int gr = row0 + r, gc = k0 + c;
            As[i] = (gr < M && gc < K) ? A[(long long)gr * K + gc] : 0.f;
        }
        for (int i = t; i < 16 * 64; i += 256) {
            int r = i >> 6, c = i & 63;
            int gr = k0 + r, gc = col0 + c;
            Bs[i] = (gr < K && gc < N) ? B[(long long)gr * N + gc] : 0.f;
        }
        __syncthreads();
        #pragma unroll
        for (int kk = 0; kk < 16; kk++) {
            float a[4], b[4];
            #pragma unroll
            for (int m = 0; m < 4; m++) a[m] = As[(ty * 4 + m) * 16 + kk];
            #pragma unroll
            for (int nn = 0; nn < 4; nn++) b[nn] = Bs[kk * 64 + tx * 4 + nn];
            #pragma unroll
            for (int m = 0; m < 4; m++)
                #pragma unroll
                for (int nn = 0; nn < 4; nn++)
                    acc[m][nn] += a[m] * b[nn];
        }
        __syncthreads();
    }
    #pragma unroll
    for (int m = 0; m < 4; m++) {
        int r = row0 + ty * 4 + m;
        if (r >= M) continue;
        #pragma unroll
        for (int nn = 0; nn < 4; nn++) {
            int c = col0 + tx * 4 + nn;
            if (c >= N) continue;
            float v = acc[m][nn] + (bias ? bias[c] : 0.f);
            if (relu) v = fmaxf(v, 0.f);
            C[(long long)r * N + c] = v;
        }
    }
}

__global__ void k_copy_ei(const int* __restrict__ ei, float* __restrict__ out, int n2) {
    int i = blockIdx.x * blockDim.x + threadIdx.x;
    if (i < n2) out[i] = (float)ei[i];
}

// ---------------------------------------------------------------------------
// Tensor-core edge MLP: 128 edges/block, 512 threads (16 warps, 4x4 grid),
// double-buffered weight tiles.
#define TE 128
#define PITCH1 260   // % 32 == 4
#define PITCHB 264   // % 32 == 8
#define PITCH2 136   // % 32 == 8
#define BUFSZ (32 * PITCHB)
#define EMLP_SMEM ((TE * PITCH1 + 2 * BUFSZ) * 4)
__global__ __launch_bounds__(512, 1)
void k_edge_mlp_tc(const int* __restrict__ ei,
                   const float* __restrict__ f,
                   const float* __restrict__ Wp1c, const float* __restrict__ bp1,
                   const float* __restrict__ Wp2c, const float* __restrict__ bp2,
                   float* __restrict__ out, int E)
{
    extern __shared__ float smem[];
    float* s_ef = smem;                  // TE x PITCH1
    float* s_b  = smem + TE * PITCH1;    // 2 x (32 x PITCHB)

    int t = threadIdx.x;
    int lane = t & 31, w = t >> 5;
    int g = lane >> 2, q = lane & 3;
    int wr = w >> 2, wc = w & 3;         // 4 x 4
    int e0 = blockIdx.x * TE;

    // gather ef tile
    const float4* f4 = (const float4*)f;
    for (int i = t; i < TE * 64; i += 512) {
        int row = i >> 6, c4 = i & 63;
        int e = e0 + row;
        float4 v = make_float4(0.f, 0.f, 0.f, 0.f);
        if (e < E) {
            int node = (c4 < 32) ? ei[e] : ei[E + e];
            v = f4[(size_t)node * 32 + (c4 & 31)];
        }
        v.x = to_tf32(v.x); v.y = to_tf32(v.y);
        v.z = to_tf32(v.z); v.w = to_tf32(v.w);
        *(float4*)&s_ef[row * PITCH1 + c4 * 4] = v;
    }

    // preload GEMM1 weight chunk 0 into buffer 0
    for (int i = t; i < 32 * 64; i += 512) {
        int row = i >> 6, c4 = i & 63;
        *(float4*)&s_b[row * PITCHB + c4 * 4] =
            *(const float4*)&Wp1c[(size_t)row * 256 + c4 * 4];
    }
    __syncthreads();

    // ---- GEMM1 (double-buffered) ----
    float acc[2][8][4];
    #pragma unroll
    for (int ms = 0; ms < 2; ms++)
        #pragma unroll
        for (int s = 0; s < 8; s++)
            #pragma unroll
            for (int i = 0; i < 4; i++) acc[ms][s][i] = 0.f;

    #pragma unroll
    for (int c = 0; c < 8; c++) {
        const float* cur = s_b + (c & 1) * BUFSZ;
        if (c + 1 < 8) {
            float* nxt = s_b + ((c + 1) & 1) * BUFSZ;
            const float* wsrc = Wp1c + (size_t)(c + 1) * 32 * 256;
            for (int i = t; i < 32 * 64; i += 512) {
                int row = i >> 6, c4 = i & 63;
                *(float4*)&nxt[row * PITCHB + c4 * 4] =
                    *(const float4*)&wsrc[(size_t)row * 256 + c4 * 4];
            }
        }
        int k0 = c * 32;
        #pragma unroll
        for (int ks = 0; ks < 32; ks += 8) {
            unsigned af[2][4];
            #pragma unroll
            for (int ms = 0; ms < 2; ms++) {
                int ar = (wr * 32 + ms * 16 + g) * PITCH1 + k0 + ks + q;
                af[ms][0] = __float_as_uint(s_ef[ar]);
                af[ms][1] = __float_as_uint(s_ef[ar + 8 * PITCH1]);
                af[ms][2] = __float_as_uint(s_ef[ar + 4]);
                af[ms][3] = __float_as_uint(s_ef[ar + 8 * PITCH1 + 4]);
            }
            #pragma unroll
            for (int ns = 0; ns < 8; ns++) {
                int n0 = wc * 64 + ns * 8;
                unsigned b0 = __float_as_uint(cur[(ks + q) * PITCHB + n0 + g]);
                unsigned b1 = __float_as_uint(cur[(ks + q + 4) * PITCHB + n0 + g]);
                mma_tf32(acc[0][ns], af[0][0], af[0][1], af[0][2], af[0][3], b0, b1);
                mma_tf32(acc[1][ns], af[1][0], af[1][1], af[1][2], af[1][3], b0, b1);
            }
        }
        __syncthreads();
    }

    // hidden = relu(acc + bp1) -> s_ef (tf32)
    #pragma unroll
    for (int ms = 0; ms < 2; ms++) {
        int r0 = wr * 32 + ms * 16 + g;
        #pragma unroll
        for (int ns = 0; ns < 8; ns++) {
            int n0 = wc * 64 + ns * 8 + 2 * q;
            float bx = bp1[n0], by = bp1[n0 + 1];
            s_ef[r0 * PITCH1 + n0]           = to_tf32(fmaxf(acc[ms][ns][0] + bx, 0.f));
            s_ef[r0 * PITCH1 + n0 + 1]       = to_tf32(fmaxf(acc[ms][ns][1] + by, 0.f));
            s_ef[(r0 + 8) * PITCH1 + n0]     = to_tf32(fmaxf(acc[ms][ns][2] + bx, 0.f));
            s_ef[(r0 + 8) * PITCH1 + n0 + 1] = to_tf32(fmaxf(acc[ms][ns][3] + by, 0.f));
        }
    }

    // preload GEMM2 weight chunk 0 into buffer 0
    for (int i = t; i < 32 * 32; i += 512) {
        int row = i >> 5, c4 = i & 31;
        *(float4*)&s_b[row * PITCH2 + c4 * 4] =
            *(const float4*)&Wp2c[(size_t)row * 128 + c4 * 4];
    }
    __syncthreads();

    // ---- GEMM2 (double-buffered) ----
    float acc2[2][4][4];
    #pragma unroll
    for (int ms = 0; ms < 2; ms++)
        #pragma unroll
        for (int s = 0; s < 4; s++)
            #pragma unroll
            for (int i = 0; i < 4; i++) acc2[ms][s][i] = 0.f;

    #pragma unroll
    for (int c = 0; c < 8; c++) {
        const float* cur = s_b + (c & 1) * BUFSZ;
        if (c + 1 < 8) {
            float* nxt = s_b + ((c + 1) & 1) * BUFSZ;
            const float* wsrc = Wp2c + (size_t)(c + 1) * 32 * 128;
            for (int i = t; i < 32 * 32; i += 512) {
                int row = i >> 5, c4 = i & 31;
                *(float4*)&nxt[row * PITCH2 + c4 * 4] =
                    *(const float4*)&wsrc[(size_t)row * 128 + c4 * 4];
            }
        }
        int k0 = c * 32;
        #pragma unroll
        for (int ks = 0; ks < 32; ks += 8) {
            unsigned af[2][4];
            #pragma unroll
            for (int ms = 0; ms < 2; ms++) {
                int ar = (wr * 32 + ms * 16 + g) * PITCH1 + k0 + ks + q;
                af[ms][0] = __float_as_uint(s_ef[ar]);
                af[ms][1] = __float_as_uint(s_ef[ar + 8 * PITCH1]);
                af[ms][2] = __float_as_uint(s_ef[ar + 4]);
                af[ms][3] = __float_as_uint(s_ef[ar + 8 * PITCH1 + 4]);
            }
            #pragma unroll
            for (int ns = 0; ns < 4; ns++) {
                int n0 = wc * 32 + ns * 8;
                unsigned b0 = __float_as_uint(cur[(ks + q) * PITCH2 + n0 + g]);
                unsigned b1 = __float_as_uint(cur[(ks + q + 4) * PITCH2 + n0 + g]);
                mma_tf32(acc2[0][ns], af[0][0], af[0][1], af[0][2], af[0][3], b0, b1);
                mma_tf32(acc2[1][ns], af[1][0], af[1][1], af[1][2], af[1][3], b0, b1);
            }
        }
        __syncthreads();
    }

    // output
    #pragma unroll
    for (int ms = 0; ms < 2; ms++) {
        int er0 = e0 + wr * 32 + ms * 16 + g;
        #pragma unroll
        for (int ns = 0; ns < 4; ns++) {
            int n0 = wc * 32 + ns * 8 + 2 * q;
            float bx = bp2[n0], by = bp2[n0 + 1];
            if (er0 < E)
                *(float2*)&out[(size_t)er0 * 128 + n0] =
                    make_float2(acc2[ms][ns][0] + bx, acc2[ms][ns][1] + by);
            if (er0 + 8 < E)
                *(float2*)&out[(size_t)(er0 + 8) * 128 + n0] =
                    make_float2(acc2[ms][ns][2] + bx, acc2[ms][ns][3] + by);
        }
    }
}

// ---------------------------------------------------------------------------
extern "C" void kernel_launch(void* const* d_in, const int* in_sizes, int n_in,
                              void* d_out, int out_size)
{
    const float* x   = (const float*)d_in[0];
    const int*   ei  = (const int*)d_in[1];
    const float* W1  = (const float*)d_in[2];
    const float* b1  = (const float*)d_in[3];
    const float* W2  = (const float*)d_in[4];
    const float* b2  = (const float*)d_in[5];
    const float* Wp1 = (const float*)d_in[6];
    const float* bp1 = (const float*)d_in[7];
    const float* Wp2 = (const float*)d_in[8];
    const float* bp2 = (const float*)d_in[9];
    const float* Wc  = (const float*)d_in[10];
    const float* bc  = (const float*)d_in[11];

    int n = in_sizes[0] / 256;
    int E = in_sizes[1] / 2;

    float* out    = (float*)d_out;
    float* f      = out;
    float* ef_out = f + (long long)n * 128;
    float* logits = ef_out + (long long)E * 128;
    float* ei_out = logits + (long long)n * 40;

    float *xw, *h, *hw, *dinv, *W1c, *W2c, *Wp1c, *Wp2c;
    int *cnt, *startp, *cursor, *csr, *bsum;
    cudaGetSymbolAddress((void**)&xw,     g_xw);
    cudaGetSymbolAddress((void**)&h,      g_h);
    cudaGetSymbolAddress((void**)&hw,     g_hw);
    cudaGetSymbolAddress((void**)&dinv,   g_dinv);
    cudaGetSymbolAddress((void**)&cnt,    g_cnt);
    cudaGetSymbolAddress((void**)&startp, g_start);
    cudaGetSymbolAddress((void**)&cursor, g_cursor);
    cudaGetSymbolAddress((void**)&csr,    g_csr);
    cudaGetSymbolAddress((void**)&bsum,   g_bsum);
    cudaGetSymbolAddress((void**)&W1c,    g_W1c);
    cudaGetSymbolAddress((void**)&W2c,    g_W2c);
    cudaGetSymbolAddress((void**)&Wp1c,   g_Wp1c);
    cudaGetSymbolAddress((void**)&Wp2c,   g_Wp2c);

    cudaFuncSetAttribute(k_edge_mlp_tc,
                         cudaFuncAttributeMaxDynamicSharedMemorySize, EMLP_SMEM);

    // weight pre-conversion to tf32
    k_cvt<<<(256 * 256 + 255) / 256, 256>>>(W1,  W1c,  256 * 256);
    k_cvt<<<(256 * 128 + 255) / 256, 256>>>(W2,  W2c,  256 * 128);
    k_cvt<<<(256 * 256 + 255) / 256, 256>>>(Wp1, Wp1c, 256 * 256);
    k_cvt<<<(256 * 128 + 255) / 256, 256>>>(Wp2, Wp2c, 256 * 128);

    // CSR build
    cudaMemsetAsync(cnt, 0, (size_t)n * sizeof(int));
    k_hist<<<(E + 255) / 256, 256>>>(ei, cnt, E);
    k_dinv<<<(n + 255) / 256, 256>>>(cnt, dinv, n);
    int nb = (n + 1023) / 1024;
    k_scan1<<<nb, 256>>>(cnt, startp, bsum, n);
    k_scan2<<<1, 32>>>(bsum, nb);
    k_scan3<<<(n + 255) / 256, 256>>>(startp, cursor, bsum, n);
    k_scatter<<<(E + 255) / 256, 256>>>(ei, cursor, csr, E);

    // layer 1
    k_gemm_tc<<<dim3(2, (n + 63) / 64), 256>>>(n, 256, 256, x, 0, W1c, dinv, xw);
    k_agg_csr<<<(n + 3) / 4, 256>>>(csr, startp, cnt, dinv, xw, b1, h, n, 2, 1);

    // layer 2
    k_gemm_tc<<<dim3(1, (n + 63) / 64), 256>>>(n, 256, 128, h, 0, W2c, dinv, hw);
    k_agg_csr<<<(n + 7) / 8, 256>>>(csr, startp, cnt, dinv, hw, b2, f, n, 1, 0);

    // classifier (fp32)
    k_sgemm<<<dim3(1, (n + 63) / 64), 256>>>(n, 40, 128, f, Wc, bc, logits, 0);

    // edge_index passthrough
    k_copy_ei<<<(2 * E + 255) / 256, 256>>>(ei, ei_out, 2 * E);

    // edge MLP
    k_edge_mlp_tc<<<(E + TE - 1) / TE, 512, EMLP_SMEM>>>(ei, f, Wp1c, bp1, Wp2c, bp2, ef_out, E);
}

// round 8
// speedup vs baseline: 7.5667x; 1.3737x over previous
#include <cuda_runtime.h>
#include <cuda_fp16.h>
#include <cstdint>

// ---------------------------------------------------------------------------
// GraphEncoder: 2-layer GCN + edge MLP + classifier.
// Output (f32): f[N,128], edge_feats[E,128], logits[N,40], edge_index (float).
// Edge MLP on fp16 mma.sync m16n8k16 (fp32 accum).
// ---------------------------------------------------------------------------

#define MAXN 100000
#define MAXE 800000

__device__ float  g_xw[(size_t)MAXN * 256];
__device__ float  g_h [(size_t)MAXN * 256];
__device__ float  g_hw[(size_t)MAXN * 128];
__device__ float  g_dinv[MAXN];
__device__ int    g_cnt[MAXN];
__device__ int    g_start[MAXN];
__device__ int    g_cursor[MAXN];
__device__ int    g_csr[MAXE];
__device__ int    g_bsum[128];
__device__ float  g_W1c [256 * 256];
__device__ float  g_W2c [256 * 128];
__device__ __half g_Wp1h[256 * 256];   // Wp1^T fp16: [n][k]
__device__ __half g_Wp2h[128 * 256];   // Wp2^T fp16: [n][k]

// ---------------------------------------------------------------------------
__device__ __forceinline__ float to_tf32(float x) {
    float r;
    asm("cvt.rna.tf32.f32 %0, %1;" : "=f"(r) : "f"(x));
    return r;
}

__device__ __forceinline__ void mma_tf32(float c[4],
    unsigned a0, unsigned a1, unsigned a2, unsigned a3,
    unsigned b0, unsigned b1)
{
    asm volatile(
        "mma.sync.aligned.m16n8k8.row.col.f32.tf32.tf32.f32 "
        "{%0,%1,%2,%3}, {%4,%5,%6,%7}, {%8,%9}, {%0,%1,%2,%3};"
        : "+f"(c[0]), "+f"(c[1]), "+f"(c[2]), "+f"(c[3])
        : "r"(a0), "r"(a1), "r"(a2), "r"(a3), "r"(b0), "r"(b1));
}

__device__ __forceinline__ void mma_fp16(float c[4], const uint32_t a[4],
                                         uint32_t b0, uint32_t b1)
{
    asm volatile(
        "mma.sync.aligned.m16n8k16.row.col.f32.f16.f16.f32 "
        "{%0,%1,%2,%3}, {%4,%5,%6,%7}, {%8,%9}, {%0,%1,%2,%3};"
        : "+f"(c[0]), "+f"(c[1]), "+f"(c[2]), "+f"(c[3])
        : "r"(a[0]), "r"(a[1]), "r"(a[2]), "r"(a[3]), "r"(b0), "r"(b1));
}

// ---------------------------------------------------------------------------
__global__ void k_cvt(const float* __restrict__ src, float* __restrict__ dst, int n) {
    int i = blockIdx.x * blockDim.x + threadIdx.x;
    if (i < n) dst[i] = to_tf32(src[i]);
}

// transpose+convert: src [K,N] fp32 -> dst [N,K] fp16  (i = n*K + k)
__global__ void k_prep_h(const float* __restrict__ src, __half* __restrict__ dst,
                         int K, int N)
{
    int i = blockIdx.x * blockDim.x + threadIdx.x;
    if (i < K * N) {
        int n = i / K, k = i - n * K;
        dst[i] = __float2half_rn(src[(size_t)k * N + n]);
    }
}

__global__ void k_hist(const int* __restrict__ ei, int* __restrict__ cnt, int E) {
    int e = blockIdx.x * blockDim.x + threadIdx.x;
    if (e < E) atomicAdd(&cnt[ei[E + e]], 1);
}

__global__ void k_dinv(const int* __restrict__ cnt, float* __restrict__ dinv, int n) {
    int i = blockIdx.x * blockDim.x + threadIdx.x;
    if (i < n) dinv[i] = rsqrtf((float)(cnt[i] + 1));
}

__global__ void k_scan1(const int* __restrict__ in, int* __restrict__ out,
                        int* __restrict__ bsum, int n)
{
    __shared__ int wsum[8];
    int t = threadIdx.x;
    int base = blockIdx.x * 1024 + t * 4;
    int v0 = base + 0 < n ? in[base + 0] : 0;
    int v1 = base + 1 < n ? in[base + 1] : 0;
    int v2 = base + 2 < n ? in[base + 2] : 0;
    int v3 = base + 3 < n ? in[base + 3] : 0;
    int ts = v0 + v1 + v2 + v3;
    int lane = t & 31, w = t >> 5;
    int x = ts;
    #pragma unroll
    for (int o = 1; o < 32; o <<= 1) {
        int y = __shfl_up_sync(0xffffffffu, x, o);
        if (lane >= o) x += y;
    }
    if (lane == 31) wsum[w] = x;
    __syncthreads();
    if (t == 0) {
        int run = 0;
        #pragma unroll
        for (int i = 0; i < 8; i++) { int tmp = wsum[i]; wsum[i] = run; run += tmp; }
        bsum[blockIdx.x] = run;
    }
    __syncthreads();
    int excl = x - ts + wsum[w];
    if (base + 0 < n) out[base + 0] = excl;
    if (base + 1 < n) out[base + 1] = excl + v0;
    if (base + 2 < n) out[base + 2] = excl + v0 + v1;
    if (base + 3 < n) out[base + 3] = excl + v0 + v1 + v2;
}

__global__ void k_scan2(int* bsum, int nb) {
    if (threadIdx.x == 0) {
        int run = 0;
        for (int i = 0; i < nb; i++) { int t = bsum[i]; bsum[i] = run; run += t; }
    }
}

__global__ void k_scan3(int* __restrict__ out, int* __restrict__ cursor,
                        const int* __restrict__ bsum, int n)
{
    int i = blockIdx.x * blockDim.x + threadIdx.x;
    if (i < n) {
        int v = out[i] + bsum[i >> 10];
        out[i] = v;
        cursor[i] = v;
    }
}

__global__ void k_scatter(const int* __restrict__ ei, int* __restrict__ cursor,
                          int* __restrict__ csr, int E)
{
    int e = blockIdx.x * blockDim.x + threadIdx.x;
    if (e < E) {
        int c = ei[E + e];
        int pos = atomicAdd(&cursor[c], 1);
        csr[pos] = ei[e];
    }
}

// ---------------------------------------------------------------------------
__global__ __launch_bounds__(256)
void k_agg_csr(const int* __restrict__ csr,
               const int* __restrict__ start, const int* __restrict__ cnt,
               const float* __restrict__ dinv,
               const float* __restrict__ srcS,
               const float* __restrict__ bias,
               float* __restrict__ out, int n, int WPN, int relu)
{
    int w = threadIdx.x >> 5, lane = threadIdx.x & 31;
    int npb = 8 / WPN;
    int node = blockIdx.x * npb + w / WPN;
    if (node >= n) return;
    int half = w % WPN;
    int F4 = WPN * 32;
    int col4 = half * 32 + lane;
    const float4* s4 = (const float4*)srcS;
    int s0 = start[node];
    int c0 = cnt[node];
    float ax = 0.f, ay = 0.f, az = 0.f, aw = 0.f;
    for (int b = 0; b < c0; b += 32) {
        int m = min(32, c0 - b);
        int idx = (b + lane < c0) ? csr[s0 + b + lane] : 0;
        int j = 0;
        for (; j + 4 <= m; j += 4) {
            int n0 = __shfl_sync(0xffffffffu, idx, j);
            int n1 = __shfl_sync(0xffffffffu, idx, j + 1);
            int n2 = __shfl_sync(0xffffffffu, idx, j + 2);
            int n3 = __shfl_sync(0xffffffffu, idx, j + 3);
            float4 v0 = s4[(size_t)n0 * F4 + col4];
            float4 v1 = s4[(size_t)n1 * F4 + col4];
            float4 v2 = s4[(size_t)n2 * F4 + col4];
            float4 v3 = s4[(size_t)n3 * F4 + col4];
            ax += (v0.x + v1.x) + (v2.x + v3.x);
            ay += (v0.y + v1.y) + (v2.y + v3.y);
            az += (v0.z + v1.z) + (v2.z + v3.z);
            aw += (v0.w + v1.w) + (v2.w + v3.w);
        }
        for (; j < m; j++) {
            int srcn = __shfl_sync(0xffffffffu, idx, j);
            float4 v = s4[(size_t)srcn * F4 + col4];
            ax += v.x; ay += v.y; az += v.z; aw += v.w;
        }
    }
    float4 self = s4[(size_t)node * F4 + col4];
    float d = dinv[node];
    float4 b4 = ((const float4*)bias)[col4];
    float rx = fmaf(d, ax + self.x, b4.x);
    float ry = fmaf(d, ay + self.y, b4.y);
    float rz = fmaf(d, az + self.z, b4.z);
    float rw = fmaf(d, aw + self.w, b4.w);
    if (relu) {
        rx = fmaxf(rx, 0.f); ry = fmaxf(ry, 0.f);
        rz = fmaxf(rz, 0.f); rw = fmaxf(rw, 0.f);
    }
    ((float4*)out)[(size_t)node * F4 + col4] = make_float4(rx, ry, rz, rw);
}

// ---------------------------------------------------------------------------
// tf32 node GEMM (known-good)
#define GP_A 36
#define GP_B 136
__global__ __launch_bounds__(256)
void k_gemm_tc(int M, int K, int N,
               const float* __restrict__ A, int reluA,
               const float* __restrict__ Bc,
               const float* __restrict__ dinv,
               float* __restrict__ Cs)
{
    __shared__ float s_a[64 * GP_A];
    __shared__ float s_b[32 * GP_B];
    int t = threadIdx.x;
    int lane = t & 31, w = t >> 5;
    int g = lane >> 2, q = lane & 3;
    int wr = w >> 2, wc = w & 3;
    int row0 = blockIdx.y * 64;
    int col0 = blockIdx.x * 128;

    float acc[2][4][4] = {};

    for (int k0 = 0; k0 < K; k0 += 32) {
        __syncthreads();
        for (int i = t; i < 512; i += 256) {
            int r = i >> 3, c4 = i & 7;
            int gr = row0 + r;
            float4 v = make_float4(0.f, 0.f, 0.f, 0.f);
            if (gr < M) v = *(const float4*)&A[(size_t)gr * K + k0 + c4 * 4];
            if (reluA) {
                v.x = fmaxf(v.x, 0.f); v.y = fmaxf(v.y, 0.f);
                v.z = fmaxf(v.z, 0.f); v.w = fmaxf(v.w, 0.f);
            }
            v.x = to_tf32(v.x); v.y = to_tf32(v.y);
            v.z = to_tf32(v.z); v.w = to_tf32(v.w);
            *(float4*)&s_a[r * GP_A + c4 * 4] = v;
        }
        for (int i = t; i < 1024; i += 256) {
            int r = i >> 5, c4 = i & 31;
            float4 v = *(const float4*)&Bc[(size_t)(k0 + r) * N + col0 + c4 * 4];
            *(float4*)&s_b[r * GP_B + c4 * 4] = v;
        }
        __syncthreads();
        #pragma unroll
        for (int ks = 0; ks < 32; ks += 8) {
            unsigned af[2][4];
            #pragma unroll
            for (int ms = 0; ms < 2; ms++) {
                int ar = (wr * 32 + ms * 16 + g) * GP_A + ks + q;
                af[ms][0] = __float_as_uint(s_a[ar]);
                af[ms][1] = __float_as_uint(s_a[ar + 8 * GP_A]);
                af[ms][2] = __float_as_uint(s_a[ar + 4]);
                af[ms][3] = __float_as_uint(s_a[ar + 8 * GP_A + 4]);
            }
            #pragma unroll
            for (int ns = 0; ns < 4; ns++) {
                int n0 = wc * 32 + ns * 8;
                unsigned b0 = __float_as_uint(s_b[(ks + q) * GP_B + n0 + g]);
                unsigned b1 = __float_as_uint(s_b[(ks + q + 4) * GP_B + n0 + g]);
                mma_tf32(acc[0][ns], af[0][0], af[0][1], af[0][2], af[0][3], b0, b1);
                mma_tf32(acc[1][ns], af[1][0], af[1][1], af[1][2], af[1][3], b0, b1);
            }
        }
    }
    #pragma unroll
    for (int ms = 0; ms < 2; ms++) {
        #pragma unroll
        for (int ns = 0; ns < 4; ns++) {
            int c = col0 + wc * 32 + ns * 8 + 2 * q;
            int r1 = row0 + wr * 32 + ms * 16 + g;
            if (r1 < M) {
                float d = dinv[r1];
                *(float2*)&Cs[(size_t)r1 * N + c] =
                    make_float2(d * acc[ms][ns][0], d * acc[ms][ns][1]);
            }
            int r2 = r1 + 8;
            if (r2 < M) {
                float d = dinv[r2];
                *(float2*)&Cs[(size_t)r2 * N + c] =
                    make_float2(d * acc[ms][ns][2], d * acc[ms][ns][3]);
            }
        }
    }
}

// ---------------------------------------------------------------------------
__global__ __launch_bounds__(256)
void k_sgemm(int M, int N, int K,
             const float* __restrict__ A, const float* __restrict__ B,
             const float* __restrict__ bias, float* __restrict__ C, int relu)
{
    __shared__ float As[64 * 16];
    __shared__ float Bs[16 * 64];
    int t = threadIdx.x;
    int tx = t & 15, ty = t >> 4;
    int row0 = blockIdx.y * 64, col0 = blockIdx.x * 64;
    float acc[4][4] = {};

    for (int k0 = 0; k0 < K; k0 += 16) {
        for (int i = t; i < 64 * 16; i += 256) {
            int r = i >> 4, c = i & 15;
            int gr = row0 + r, gc = k0 + c;
            As[i] = (gr < M && gc < K) ? A[(long long)gr * K + gc] : 0.f;
        }
        for (int i = t; i < 16 * 64; i += 256) {
            int r = i >> 6, c = i & 63;
            int gr = k0 + r, gc = col0 + c;
            Bs[i] = (gr < K && gc < N) ? B[(long long)gr * N + gc] : 0.f;
        }
        __syncthreads();
        #pragma unroll
        for (int kk = 0; kk < 16; kk++) {
            float a[4], b[4];
            #pragma unroll
            for (int m = 0; m < 4; m++) a[m] = As[(ty * 4 + m) * 16 + kk];
            #pragma unroll
            for (int nn = 0; nn < 4; nn++) b[nn] = Bs[kk * 64 + tx * 4 + nn];
            #pragma unroll
            for (int m = 0; m < 4; m++)
                #pragma unroll
                for (int nn = 0; nn < 4; nn++)
                    acc[m][nn] += a[m] * b[nn];
        }
        __syncthreads();
    }
    #pragma unroll
    for (int m = 0; m < 4; m++) {
        int r = row0 + ty * 4 + m;
        if (r >= M) continue;
        #pragma unroll
        for (int nn = 0; nn < 4; nn++) {
            int c = col0 + tx * 4 + nn;
            if (c >= N) continue;
            float v = acc[m][nn] + (bias ? bias[c] : 0.f);
            if (relu) v = fmaxf(v, 0.f);
            C[(long long)r * N + c] = v;
        }
    }
}

__global__ void k_copy_ei(const int* __restrict__ ei, float* __restrict__ out, int n2) {
    int i = blockIdx.x * blockDim.x + threadIdx.x;
    if (i < n2) out[i] = (float)ei[i];
}

// ---------------------------------------------------------------------------
// fp16 edge MLP: 128 edges/block, 512 threads (16 warps, 4x4), m16n8k16,
// double-buffered [n][k] weight chunks.
// A (ef/hid): 128 x 264-half pitch (132 words % 32 == 4 -> banks 4g+q).
// B chunks: rows n, 40-half pitch (20 words -> banks 20g+q, all distinct).
#define TE 128
#define PH_A 264
#define PH_B 40
#define BUFH (256 * PH_B)
#define EMLP_SMEM ((TE * PH_A + 2 * BUFH) * 2)
__global__ __launch_bounds__(512, 1)
void k_edge_mlp_fp16(const int* __restrict__ ei,
                     const float* __restrict__ f,
                     const __half* __restrict__ W1h, const float* __restrict__ bp1,
                     const __half* __restrict__ W2h, const float* __restrict__ bp2,
                     float* __restrict__ out, int E)
{
    extern __shared__ __half hsm[];
    __half* s_ef = hsm;                 // TE x PH_A
    __half* s_b  = hsm + TE * PH_A;     // 2 x BUFH

    int t = threadIdx.x;
    int lane = t & 31, w = t >> 5;
    int g = lane >> 2, q = lane & 3;
    int wr = w >> 2, wc = w & 3;        // 4 x 4
    int e0 = blockIdx.x * TE;

    // gather ef tile -> fp16
    const float4* f4 = (const float4*)f;
    for (int i = t; i < TE * 64; i += 512) {
        int row = i >> 6, c4 = i & 63;
        int e = e0 + row;
        float4 v = make_float4(0.f, 0.f, 0.f, 0.f);
        if (e < E) {
            int node = (c4 < 32) ? ei[e] : ei[E + e];
            v = f4[(size_t)node * 32 + (c4 & 31)];
        }
        *(__half2*)&s_ef[row * PH_A + c4 * 4]     = __floats2half2_rn(v.x, v.y);
        *(__half2*)&s_ef[row * PH_A + c4 * 4 + 2] = __floats2half2_rn(v.z, v.w);
    }

    // preload GEMM1 weight chunk 0 (k=0..31, n=0..255)
    for (int i = t; i < 1024; i += 512) {
        int n = i >> 2, seg = i & 3;
        *(uint4*)&s_b[n * PH_B + seg * 8] = *(const uint4*)&W1h[n * 256 + seg * 8];
    }
    __syncthreads();

    // ---- GEMM1: hid[128,256] = ef @ Wp1, 8 K-chunks double-buffered ----
    float acc[2][8][4] = {};
    for (int c = 0; c < 8; c++) {
        const __half* cur = s_b + (c & 1) * BUFH;
        if (c + 1 < 8) {
            __half* nxt = s_b + ((c + 1) & 1) * BUFH;
            const __half* wsrc = W1h + (c + 1) * 32;
            for (int i = t; i < 1024; i += 512) {
                int n = i >> 2, seg = i & 3;
                *(uint4*)&nxt[n * PH_B + seg * 8] =
                    *(const uint4*)&wsrc[n * 256 + seg * 8];
            }
        }
        int k0 = c * 32;
        #pragma unroll
        for (int ks = 0; ks < 32; ks += 16) {
            uint32_t af[2][4];
            #pragma unroll
            for (int ms = 0; ms < 2; ms++) {
                const __half* ap = s_ef + (wr * 32 + ms * 16 + g) * PH_A + k0 + ks + 2 * q;
                af[ms][0] = *(const uint32_t*)(ap);
                af[ms][1] = *(const uint32_t*)(ap + 8 * PH_A);
                af[ms][2] = *(const uint32_t*)(ap + 8);
                af[ms][3] = *(const uint32_t*)(ap + 8 * PH_A + 8);
            }
            #pragma unroll
            for (int ns = 0; ns < 8; ns++) {
                int n0 = wc * 64 + ns * 8;
                const __half* bp = cur + (n0 + g) * PH_B + ks + 2 * q;
                uint32_t b0 = *(const uint32_t*)(bp);
                uint32_t b1 = *(const uint32_t*)(bp + 8);
                mma_fp16(acc[0][ns], af[0], b0, b1);
                mma_fp16(acc[1][ns], af[1], b0, b1);
            }
        }
        __syncthreads();
    }

    // hid = relu(acc + bp1) -> s_ef (fp16)
    #pragma unroll
    for (int ms = 0; ms < 2; ms++) {
        int r0 = wr * 32 + ms * 16 + g;
        #pragma unroll
        for (int ns = 0; ns < 8; ns++) {
            int n0 = wc * 64 + ns * 8 + 2 * q;
            float bx = bp1[n0], by = bp1[n0 + 1];
            *(__half2*)&s_ef[r0 * PH_A + n0] = __floats2half2_rn(
                fmaxf(acc[ms][ns][0] + bx, 0.f), fmaxf(acc[ms][ns][1] + by, 0.f));
            *(__half2*)&s_ef[(r0 + 8) * PH_A + n0] = __floats2half2_rn(
                fmaxf(acc[ms][ns][2] + bx, 0.f), fmaxf(acc[ms][ns][3] + by, 0.f));
        }
    }

    // preload GEMM2 weight chunk 0 (n=0..127)
    for (int i = t; i < 512; i += 512) {
        int n = i >> 2, seg = i & 3;
        *(uint4*)&s_b[n * PH_B + seg * 8] = *(const uint4*)&W2h[n * 256 + seg * 8];
    }
    __syncthreads();

    // ---- GEMM2: out[128,128] = hid @ Wp2 ----
    float acc2[2][4][4] = {};
    for (int c = 0; c < 8; c++) {
        const __half* cur = s_b + (c & 1) * BUFH;
        if (c + 1 < 8) {
            __half* nxt = s_b + ((c + 1) & 1) * BUFH;
            const __half* wsrc = W2h + (c + 1) * 32;
            for (int i = t; i < 512; i += 512) {
                int n = i >> 2, seg = i & 3;
                *(uint4*)&nxt[n * PH_B + seg * 8] =
                    *(const uint4*)&wsrc[n * 256 + seg * 8];
            }
        }
        int k0 = c * 32;
        #pragma unroll
        for (int ks = 0; ks < 32; ks += 16) {
            uint32_t af[2][4];
            #pragma unroll
            for (int ms = 0; ms < 2; ms++) {
                const __half* ap = s_ef + (wr * 32 + ms * 16 + g) * PH_A + k0 + ks + 2 * q;
                af[ms][0] = *(const uint32_t*)(ap);
                af[ms][1] = *(const uint32_t*)(ap + 8 * PH_A);
                af[ms][2] = *(const uint32_t*)(ap + 8);
                af[ms][3] = *(const uint32_t*)(ap + 8 * PH_A + 8);
            }
            #pragma unroll
            for (int ns = 0; ns < 4; ns++) {
                int n0 = wc * 32 + ns * 8;
                const __half* bp = cur + (n0 + g) * PH_B + ks + 2 * q;
                uint32_t b0 = *(const uint32_t*)(bp);
                uint32_t b1 = *(const uint32_t*)(bp + 8);
                mma_fp16(acc2[0][ns], af[0], b0, b1);
                mma_fp16(acc2[1][ns], af[1], b0, b1);
            }
        }
        __syncthreads();
    }

    // output
    #pragma unroll
    for (int ms = 0; ms < 2; ms++) {
        int er0 = e0 + wr * 32 + ms * 16 + g;
        #pragma unroll
        for (int ns = 0; ns < 4; ns++) {
            int n0 = wc * 32 + ns * 8 + 2 * q;
            float bx = bp2[n0], by = bp2[n0 + 1];
            if (er0 < E)
                *(float2*)&out[(size_t)er0 * 128 + n0] =
                    make_float2(acc2[ms][ns][0] + bx, acc2[ms][ns][1] + by);
            if (er0 + 8 < E)
                *(float2*)&out[(size_t)(er0 + 8) * 128 + n0] =
                    make_float2(acc2[ms][ns][2] + bx, acc2[ms][ns][3] + by);
        }
    }
}

// ---------------------------------------------------------------------------
extern "C" void kernel_launch(void* const* d_in, const int* in_sizes, int n_in,
                              void* d_out, int out_size)
{
    const float* x   = (const float*)d_in[0];
    const int*   ei  = (const int*)d_in[1];
    const float* W1  = (const float*)d_in[2];
    const float* b1  = (const float*)d_in[3];
    const float* W2  = (const float*)d_in[4];
    const float* b2  = (const float*)d_in[5];
    const float* Wp1 = (const float*)d_in[6];
    const float* bp1 = (const float*)d_in[7];
    const float* Wp2 = (const float*)d_in[8];
    const float* bp2 = (const float*)d_in[9];
    const float* Wc  = (const float*)d_in[10];
    const float* bc  = (const float*)d_in[11];

    int n = in_sizes[0] / 256;
    int E = in_sizes[1] / 2;

    float* out    = (float*)d_out;
    float* f      = out;
    float* ef_out = f + (long long)n * 128;
    float* logits = ef_out + (long long)E * 128;
    float* ei_out = logits + (long long)n * 40;

    float *xw, *h, *hw, *dinv, *W1c, *W2c;
    __half *W1h, *W2h;
    int *cnt, *startp, *cursor, *csr, *bsum;
    cudaGetSymbolAddress((void**)&xw,     g_xw);
    cudaGetSymbolAddress((void**)&h,      g_h);
    cudaGetSymbolAddress((void**)&hw,     g_hw);
    cudaGetSymbolAddress((void**)&dinv,   g_dinv);
    cudaGetSymbolAddress((void**)&cnt,    g_cnt);
    cudaGetSymbolAddress((void**)&startp, g_start);
    cudaGetSymbolAddress((void**)&cursor, g_cursor);
    cudaGetSymbolAddress((void**)&csr,    g_csr);
    cudaGetSymbolAddress((void**)&bsum,   g_bsum);
    cudaGetSymbolAddress((void**)&W1c,    g_W1c);
    cudaGetSymbolAddress((void**)&W2c,    g_W2c);
    cudaGetSymbolAddress((void**)&W1h,    g_Wp1h);
    cudaGetSymbolAddress((void**)&W2h,    g_Wp2h);

    cudaFuncSetAttribute(k_edge_mlp_fp16,
                         cudaFuncAttributeMaxDynamicSharedMemorySize, EMLP_SMEM);

    // CSR + degree + weight prep
    cudaMemsetAsync(cnt, 0, (size_t)n * sizeof(int));
    k_hist<<<(E + 255) / 256, 256>>>(ei, cnt, E);
    k_cvt<<<(256 * 256 + 255) / 256, 256>>>(W1, W1c, 256 * 256);
    k_dinv<<<(n + 255) / 256, 256>>>(cnt, dinv, n);

    // layer 1 GEMM
    k_gemm_tc<<<dim3(2, (n + 63) / 64), 256>>>(n, 256, 256, x, 0, W1c, dinv, xw);

    int nb = (n + 1023) / 1024;
    k_scan1<<<nb, 256>>>(cnt, startp, bsum, n);
    k_scan2<<<1, 32>>>(bsum, nb);
    k_scan3<<<(n + 255) / 256, 256>>>(startp, cursor, bsum, n);
    k_scatter<<<(E + 255) / 256, 256>>>(ei, cursor, csr, E);

    k_agg_csr<<<(n + 3) / 4, 256>>>(csr, startp, cnt, dinv, xw, b1, h, n, 2, 1);

    // layer 2
    k_cvt<<<(256 * 128 + 255) / 256, 256>>>(W2, W2c, 256 * 128);
    k_gemm_tc<<<dim3(1, (n + 63) / 64), 256>>>(n, 256, 128, h, 0, W2c, dinv, hw);
    k_agg_csr<<<(n + 7) / 8, 256>>>(csr, startp, cnt, dinv, hw, b2, f, n, 1, 0);

    // classifier (fp32)
    k_sgemm<<<dim3(1, (n + 63) / 64), 256>>>(n, 40, 128, f, Wc, bc, logits, 0);

    // edge_index passthrough
    k_copy_ei<<<(2 * E + 255) / 256, 256>>>(ei, ei_out, 2 * E);

    // edge MLP (fp16 tensor cores)
    k_prep_h<<<(256 * 256 + 255) / 256, 256>>>(Wp1, W1h, 256, 256);
    k_prep_h<<<(256 * 128 + 255) / 256, 256>>>(Wp2, W2h, 256, 128);
    k_edge_mlp_fp16<<<(E + TE - 1) / TE, 512, EMLP_SMEM>>>(ei, f, W1h, bp1, W2h, bp2, ef_out, E);
}

// round 9
// speedup vs baseline: 7.9316x; 1.0482x over previous
#include <cuda_runtime.h>
#include <cuda_fp16.h>
#include <cstdint>

// ---------------------------------------------------------------------------
// GraphEncoder: 2-layer GCN + edge MLP + classifier.
// Output (f32): f[N,128], edge_feats[E,128], logits[N,40], edge_index (float).
// All big GEMMs on fp16 mma.sync m16n8k16 (fp32 accum) with ldmatrix loads.
// ---------------------------------------------------------------------------

#define MAXN 100000
#define MAXE 800000

__device__ float  g_xw[(size_t)MAXN * 256];
__device__ float  g_h [(size_t)MAXN * 256];
__device__ float  g_hw[(size_t)MAXN * 128];
__device__ float  g_dinv[MAXN];
__device__ int    g_cnt[MAXN];
__device__ int    g_start[MAXN];
__device__ int    g_cursor[MAXN];
__device__ int    g_csr[MAXE];
__device__ int    g_bsum[128];
__device__ __half g_W1h [256 * 256];   // W1^T  fp16: [n][k]
__device__ __half g_W2h [128 * 256];   // W2^T  fp16: [n][k]
__device__ __half g_Wp1h[256 * 256];   // Wp1^T fp16: [n][k]
__device__ __half g_Wp2h[128 * 256];   // Wp2^T fp16: [n][k]

// ---------------------------------------------------------------------------
__device__ __forceinline__ void mma_fp16(float c[4], const uint32_t a[4],
                                         uint32_t b0, uint32_t b1)
{
    asm volatile(
        "mma.sync.aligned.m16n8k16.row.col.f32.f16.f16.f32 "
        "{%0,%1,%2,%3}, {%4,%5,%6,%7}, {%8,%9}, {%0,%1,%2,%3};"
        : "+f"(c[0]), "+f"(c[1]), "+f"(c[2]), "+f"(c[3])
        : "r"(a[0]), "r"(a[1]), "r"(a[2]), "r"(a[3]), "r"(b0), "r"(b1));
}

__device__ __forceinline__ void ldsm_x4(uint32_t r[4], uint32_t saddr) {
    asm volatile("ldmatrix.sync.aligned.m8n8.x4.shared.b16 {%0,%1,%2,%3}, [%4];"
                 : "=r"(r[0]), "=r"(r[1]), "=r"(r[2]), "=r"(r[3]) : "r"(saddr));
}

__device__ __forceinline__ uint32_t smem_to_u32(const void* p) {
    uint32_t a;
    asm("{ .reg .u64 t; cvta.to.shared.u64 t, %1; cvt.u32.u64 %0, t; }"
        : "=r"(a) : "l"(p));
    return a;
}

// ---------------------------------------------------------------------------
// transpose+convert: src [K,N] fp32 -> dst [N,K] fp16  (i = n*K + k)
__global__ void k_prep_h(const float* __restrict__ src, __half* __restrict__ dst,
                         int K, int N)
{
    int i = blockIdx.x * blockDim.x + threadIdx.x;
    if (i < K * N) {
        int n = i / K, k = i - n * K;
        dst[i] = __float2half_rn(src[(size_t)k * N + n]);
    }
}

__global__ void k_hist(const int* __restrict__ ei, int* __restrict__ cnt, int E) {
    int e = blockIdx.x * blockDim.x + threadIdx.x;
    if (e < E) atomicAdd(&cnt[ei[E + e]], 1);
}

__global__ void k_dinv(const int* __restrict__ cnt, float* __restrict__ dinv, int n) {
    int i = blockIdx.x * blockDim.x + threadIdx.x;
    if (i < n) dinv[i] = rsqrtf((float)(cnt[i] + 1));
}

__global__ void k_scan1(const int* __restrict__ in, int* __restrict__ out,
                        int* __restrict__ bsum, int n)
{
    __shared__ int wsum[8];
    int t = threadIdx.x;
    int base = blockIdx.x * 1024 + t * 4;
    int v0 = base + 0 < n ? in[base + 0] : 0;
    int v1 = base + 1 < n ? in[base + 1] : 0;
    int v2 = base + 2 < n ? in[base + 2] : 0;
    int v3 = base + 3 < n ? in[base + 3] : 0;
    int ts = v0 + v1 + v2 + v3;
    int lane = t & 31, w = t >> 5;
    int x = ts;
    #pragma unroll
    for (int o = 1; o < 32; o <<= 1) {
        int y = __shfl_up_sync(0xffffffffu, x, o);
        if (lane >= o) x += y;
    }
    if (lane == 31) wsum[w] = x;
    __syncthreads();
    if (t == 0) {
        int run = 0;
        #pragma unroll
        for (int i = 0; i < 8; i++) { int tmp = wsum[i]; wsum[i] = run; run += tmp; }
        bsum[blockIdx.x] = run;
    }
    __syncthreads();
    int excl = x - ts + wsum[w];
    if (base + 0 < n) out[base + 0] = excl;
    if (base + 1 < n) out[base + 1] = excl + v0;
    if (base + 2 < n) out[base + 2] = excl + v0 + v1;
    if (base + 3 < n) out[base + 3] = excl + v0 + v1 + v2;
}

__global__ void k_scan2(int* bsum, int nb) {
    if (threadIdx.x == 0) {
        int run = 0;
        for (int i = 0; i < nb; i++) { int t = bsum[i]; bsum[i] = run; run += t; }
    }
}

__global__ void k_scan3(int* __restrict__ out, int* __restrict__ cursor,
                        const int* __restrict__ bsum, int n)
{
    int i = blockIdx.x * blockDim.x + threadIdx.x;
    if (i < n) {
        int v = out[i] + bsum[i >> 10];
        out[i] = v;
        cursor[i] = v;
    }
}

__global__ void k_scatter(const int* __restrict__ ei, int* __restrict__ cursor,
                          int* __restrict__ csr, int E)
{
    int e = blockIdx.x * blockDim.x + threadIdx.x;
    if (e < E) {
        int c = ei[E + e];
        int pos = atomicAdd(&cursor[c], 1);
        csr[pos] = ei[e];
    }
}

// ---------------------------------------------------------------------------
__global__ __launch_bounds__(256)
void k_agg_csr(const int* __restrict__ csr,
               const int* __restrict__ start, const int* __restrict__ cnt,
               const float* __restrict__ dinv,
               const float* __restrict__ srcS,
               const float* __restrict__ bias,
               float* __restrict__ out, int n, int WPN, int relu)
{
    int w = threadIdx.x >> 5, lane = threadIdx.x & 31;
    int npb = 8 / WPN;
    int node = blockIdx.x * npb + w / WPN;
    if (node >= n) return;
    int half = w % WPN;
    int F4 = WPN * 32;
    int col4 = half * 32 + lane;
    const float4* s4 = (const float4*)srcS;
    int s0 = start[node];
    int c0 = cnt[node];
    float ax = 0.f, ay = 0.f, az = 0.f, aw = 0.f;
    for (int b = 0; b < c0; b += 32) {
        int m = min(32, c0 - b);
        int idx = (b + lane < c0) ? csr[s0 + b + lane] : 0;
        int j = 0;
        for (; j + 4 <= m; j += 4) {
            int n0 = __shfl_sync(0xffffffffu, idx, j);
            int n1 = __shfl_sync(0xffffffffu, idx, j + 1);
            int n2 = __shfl_sync(0xffffffffu, idx, j + 2);
            int n3 = __shfl_sync(0xffffffffu, idx, j + 3);
            float4 v0 = s4[(size_t)n0 * F4 + col4];
            float4 v1 = s4[(size_t)n1 * F4 + col4];
            float4 v2 = s4[(size_t)n2 * F4 + col4];
            float4 v3 = s4[(size_t)n3 * F4 + col4];
            ax += (v0.x + v1.x) + (v2.x + v3.x);
            ay += (v0.y + v1.y) + (v2.y + v3.y);
            az += (v0.z + v1.z) + (v2.z + v3.z);
            aw += (v0.w + v1.w) + (v2.w + v3.w);
        }
        for (; j < m; j++) {
            int srcn = __shfl_sync(0xffffffffu, idx, j);
            float4 v = s4[(size_t)srcn * F4 + col4];
            ax += v.x; ay += v.y; az += v.z; aw += v.w;
        }
    }
    float4 self = s4[(size_t)node * F4 + col4];
    float d = dinv[node];
    float4 b4 = ((const float4*)bias)[col4];
    float rx = fmaf(d, ax + self.x, b4.x);
    float ry = fmaf(d, ay + self.y, b4.y);
    float rz = fmaf(d, az + self.z, b4.z);
    float rw = fmaf(d, aw + self.w, b4.w);
    if (relu) {
        rx = fmaxf(rx, 0.f); ry = fmaxf(ry, 0.f);
        rz = fmaxf(rz, 0.f); rw = fmaxf(rw, 0.f);
    }
    ((float4*)out)[(size_t)node * F4 + col4] = make_float4(rx, ry, rz, rw);
}

// ---------------------------------------------------------------------------
// fp16 node GEMM: BM=64, BN=128, BK=32; 256 threads (8 warps, 2x4).
// A fp32 (optional relu on load) -> half; B pre-transposed [n][k] half.
// Epilogue: Cs[r] = dinv[r] * acc.
#define PA2 40   // halves; 20 words -> conflict-free ldmatrix rows
#define PB2 40
__global__ __launch_bounds__(256)
void k_gemm_fp16(int M, int K, int N,
                 const float* __restrict__ A, int reluA,
                 const __half* __restrict__ Bh,
                 const float* __restrict__ dinv,
                 float* __restrict__ Cs)
{
    __shared__ __half s_a[64 * PA2];
    __shared__ __half s_b[128 * PB2];
    int t = threadIdx.x;
    int lane = t & 31, w = t >> 5;
    int g = lane >> 2, q = lane & 3;
    int wr = w >> 2, wc = w & 3;       // 2 x 4
    int row0 = blockIdx.y * 64;
    int col0 = blockIdx.x * 128;
    uint32_t a_base = smem_to_u32(s_a);
    uint32_t b_base = smem_to_u32(s_b);

    float acc[2][4][4] = {};

    for (int k0 = 0; k0 < K; k0 += 32) {
        __syncthreads();
        // A tile 64x32 fp32 -> half
        for (int i = t; i < 512; i += 256) {
            int r = i >> 3, c4 = i & 7;
            int gr = row0 + r;
            float4 v = make_float4(0.f, 0.f, 0.f, 0.f);
            if (gr < M) v = *(const float4*)&A[(size_t)gr * K + k0 + c4 * 4];
            if (reluA) {
                v.x = fmaxf(v.x, 0.f); v.y = fmaxf(v.y, 0.f);
                v.z = fmaxf(v.z, 0.f); v.w = fmaxf(v.w, 0.f);
            }
            __half2 h0 = __floats2half2_rn(v.x, v.y);
            __half2 h1 = __floats2half2_rn(v.z, v.w);
            *(uint2*)&s_a[r * PA2 + c4 * 4] =
                make_uint2(*(uint32_t*)&h0, *(uint32_t*)&h1);
        }
        // B tile 128 rows x 32 halves (raw copy)
        for (int i = t; i < 512; i += 256) {
            int n = i >> 2, seg = i & 3;
            *(uint4*)&s_b[n * PB2 + seg * 8] =
                *(const uint4*)&Bh[(size_t)(col0 + n) * K + k0 + seg * 8];
        }
        __syncthreads();
        #pragma unroll
        for (int ks = 0; ks < 32; ks += 16) {
            uint32_t af[2][4];
            #pragma unroll
            for (int ms = 0; ms < 2; ms++) {
                int row = wr * 32 + ms * 16 + (lane & 15);
                int col = ks + ((lane >> 4) << 3);
                ldsm_x4(af[ms], a_base + (row * PA2 + col) * 2);
            }
            #pragma unroll
            for (int np = 0; np < 2; np++) {
                int n0 = wc * 32 + np * 16;
                int brow = n0 + ((lane >> 4) << 3) + (lane & 7);
                int bcol = ks + (((lane >> 3) & 1) << 3);
                uint32_t bf[4];
                ldsm_x4(bf, b_base + (brow * PB2 + bcol) * 2);
                mma_fp16(acc[0][np * 2],     af[0], bf[0], bf[1]);
                mma_fp16(acc[0][np * 2 + 1], af[0], bf[2], bf[3]);
                mma_fp16(acc[1][np * 2],     af[1], bf[0], bf[1]);
                mma_fp16(acc[1][np * 2 + 1], af[1], bf[2], bf[3]);
            }
        }
    }
    #pragma unroll
    for (int ms = 0; ms < 2; ms++) {
        #pragma unroll
        for (int ns = 0; ns < 4; ns++) {
            int c = col0 + wc * 32 + ns * 8 + 2 * q;
            int r1 = row0 + wr * 32 + ms * 16 + g;
            if (r1 < M) {
                float d = dinv[r1];
                *(float2*)&Cs[(size_t)r1 * N + c] =
                    make_float2(d * acc[ms][ns][0], d * acc[ms][ns][1]);
            }
            int r2 = r1 + 8;
            if (r2 < M) {
                float d = dinv[r2];
                *(float2*)&Cs[(size_t)r2 * N + c] =
                    make_float2(d * acc[ms][ns][2], d * acc[ms][ns][3]);
            }
        }
    }
}

// ---------------------------------------------------------------------------
// fp32 SGEMM (classifier only: N=40)
__global__ __launch_bounds__(256)
void k_sgemm(int M, int N, int K,
             const float* __restrict__ A, const float* __restrict__ B,
             const float* __restrict__ bias, float* __restrict__ C, int relu)
{
    __shared__ float As[64 * 16];
    __shared__ float Bs[16 * 64];
    int t = threadIdx.x;
    int tx = t & 15, ty = t >> 4;
    int row0 = blockIdx.y * 64, col0 = blockIdx.x * 64;
    float acc[4][4] = {};

    for (int k0 = 0; k0 < K; k0 += 16) {
        for (int i = t; i < 64 * 16; i += 256) {
            int r = i >> 4, c = i & 15;
            int gr = row0 + r, gc = k0 + c;
            As[i] = (gr < M && gc < K) ? A[(long long)gr * K + gc] : 0.f;
        }
        for (int i = t; i < 16 * 64; i += 256) {
            int r = i >> 6, c = i & 63;
            int gr = k0 + r, gc = col0 + c;
            Bs[i] = (gr < K && gc < N) ? B[(long long)gr * N + gc] : 0.f;
        }
        __syncthreads();
        #pragma unroll
        for (int kk = 0; kk < 16; kk++) {
            float a[4], b[4];
            #pragma unroll
            for (int m = 0; m < 4; m++) a[m] = As[(ty * 4 + m) * 16 + kk];
            #pragma unroll
            for (int nn = 0; nn < 4; nn++) b[nn] = Bs[kk * 64 + tx * 4 + nn];
            #pragma unroll
            for (int m = 0; m < 4; m++)
                #pragma unroll
                for (int nn = 0; nn < 4; nn++)
                    acc[m][nn] += a[m] * b[nn];
        }
        __syncthreads();
    }
    #pragma unroll
    for (int m = 0; m < 4; m++) {
        int r = row0 + ty * 4 + m;
        if (r >= M) continue;
        #pragma unroll
        for (int nn = 0; nn < 4; nn++) {
            int c = col0 + tx * 4 + nn;
            if (c >= N) continue;
            float v = acc[m][nn] + (bias ? bias[c] : 0.f);
            if (relu) v = fmaxf(v, 0.f);
            C[(long long)r * N + c] = v;
        }
    }
}

__global__ void k_copy_ei(const int* __restrict__ ei, float* __restrict__ out, int n2) {
    int i = blockIdx.x * blockDim.x + threadIdx.x;
    if (i < n2) out[i] = (float)ei[i];
}

// ---------------------------------------------------------------------------
// fp16 edge MLP: 128 edges/block, 512 threads (16 warps, 4x4), m16n8k16,
// ldmatrix fragment loads, double-buffered [n][k] weight chunks.
#define TE 128
#define PH_A 264   // halves; 132 words % 32 == 4 -> conflict-free ldmatrix
#define PH_B 40
#define BUFH (256 * PH_B)
#define EMLP_SMEM ((TE * PH_A + 2 * BUFH) * 2)
__global__ __launch_bounds__(512, 1)
void k_edge_mlp_fp16(const int* __restrict__ ei,
                     const float* __restrict__ f,
                     const __half* __restrict__ W1h, const float* __restrict__ bp1,
                     const __half* __restrict__ W2h, const float* __restrict__ bp2,
                     float* __restrict__ out, int E)
{
    extern __shared__ __half hsm[];
    __half* s_ef = hsm;                 // TE x PH_A
    __half* s_b  = hsm + TE * PH_A;     // 2 x BUFH
    uint32_t ef_base = smem_to_u32(s_ef);
    uint32_t sb_base = smem_to_u32(s_b);

    int t = threadIdx.x;
    int lane = t & 31, w = t >> 5;
    int g = lane >> 2, q = lane & 3;
    int wr = w >> 2, wc = w & 3;        // 4 x 4
    int e0 = blockIdx.x * TE;

    // gather ef tile -> fp16
    const float4* f4 = (const float4*)f;
    for (int i = t; i < TE * 64; i += 512) {
        int row = i >> 6, c4 = i & 63;
        int e = e0 + row;
        float4 v = make_float4(0.f, 0.f, 0.f, 0.f);
        if (e < E) {
            int node = (c4 < 32) ? ei[e] : ei[E + e];
            v = f4[(size_t)node * 32 + (c4 & 31)];
        }
        __half2 h0 = __floats2half2_rn(v.x, v.y);
        __half2 h1 = __floats2half2_rn(v.z, v.w);
        *(uint2*)&s_ef[row * PH_A + c4 * 4] =
            make_uint2(*(uint32_t*)&h0, *(uint32_t*)&h1);
    }

    // preload GEMM1 weight chunk 0
    for (int i = t; i < 1024; i += 512) {
        int n = i >> 2, seg = i & 3;
        *(uint4*)&s_b[n * PH_B + seg * 8] = *(const uint4*)&W1h[n * 256 + seg * 8];
    }
    __syncthreads();

    // ---- GEMM1: hid[128,256] = ef @ Wp1 ----
    float acc[2][8][4] = {};
    for (int c = 0; c < 8; c++) {
        uint32_t cur = sb_base + (c & 1) * (BUFH * 2);
        if (c + 1 < 8) {
            __half* nxt = s_b + ((c + 1) & 1) * BUFH;
            const __half* wsrc = W1h + (c + 1) * 32;
            for (int i = t; i < 1024; i += 512) {
                int n = i >> 2, seg = i & 3;
                *(uint4*)&nxt[n * PH_B + seg * 8] =
                    *(const uint4*)&wsrc[n * 256 + seg * 8];
            }
        }
        int k0 = c * 32;
        #pragma unroll
        for (int ks = 0; ks < 32; ks += 16) {
            uint32_t af[2][4];
            #pragma unroll
            for (int ms = 0; ms < 2; ms++) {
                int row = wr * 32 + ms * 16 + (lane & 15);
                int col = k0 + ks + ((lane >> 4) << 3);
                ldsm_x4(af[ms], ef_base + (row * PH_A + col) * 2);
            }
            #pragma unroll
            for (int np = 0; np < 4; np++) {
                int n0 = wc * 64 + np * 16;
                int brow = n0 + ((lane >> 4) << 3) + (lane & 7);
                int bcol = ks + (((lane >> 3) & 1) << 3);
                uint32_t bf[4];
                ldsm_x4(bf, cur + (brow * PH_B + bcol) * 2);
                mma_fp16(acc[0][np * 2],     af[0], bf[0], bf[1]);
                mma_fp16(acc[0][np * 2 + 1], af[0], bf[2], bf[3]);
                mma_fp16(acc[1][np * 2],     af[1], bf[0], bf[1]);
                mma_fp16(acc[1][np * 2 + 1], af[1], bf[2], bf[3]);
            }
        }
        __syncthreads();
    }

    // hid = relu(acc + bp1) -> s_ef (fp16)
    #pragma unroll
    for (int ms = 0; ms < 2; ms++) {
        int r0 = wr * 32 + ms * 16 + g;
        #pragma unroll
        for (int ns = 0; ns < 8; ns++) {
            int n0 = wc * 64 + ns * 8 + 2 * q;
            float bx = bp1[n0], by = bp1[n0 + 1];
            *(__half2*)&s_ef[r0 * PH_A + n0] = __floats2half2_rn(
                fmaxf(acc[ms][ns][0] + bx, 0.f), fmaxf(acc[ms][ns][1] + by, 0.f));
            *(__half2*)&s_ef[(r0 + 8) * PH_A + n0] = __floats2half2_rn(
                fmaxf(acc[ms][ns][2] + bx, 0.f), fmaxf(acc[ms][ns][3] + by, 0.f));
        }
    }

    // preload GEMM2 weight chunk 0
    for (int i = t; i < 512; i += 512) {
        int n = i >> 2, seg = i & 3;
        *(uint4*)&s_b[n * PH_B + seg * 8] = *(const uint4*)&W2h[n * 256 + seg * 8];
    }
    __syncthreads();

    // ---- GEMM2: out[128,128] = hid @ Wp2 ----
    float acc2[2][4][4] = {};
    for (int c = 0; c < 8; c++) {
        uint32_t cur = sb_base + (c & 1) * (BUFH * 2);
        if (c + 1 < 8) {
            __half* nxt = s_b + ((c + 1) & 1) * BUFH;
            const __half* wsrc = W2h + (c + 1) * 32;
            for (int i = t; i < 512; i += 512) {
                int n = i >> 2, seg = i & 3;
                *(uint4*)&nxt[n * PH_B + seg * 8] =
                    *(const uint4*)&wsrc[n * 256 + seg * 8];
            }
        }
        int k0 = c * 32;
        #pragma unroll
        for (int ks = 0; ks < 32; ks += 16) {
            uint32_t af[2][4];
            #pragma unroll
            for (int ms = 0; ms < 2; ms++) {
                int row = wr * 32 + ms * 16 + (lane & 15);
                int col = k0 + ks + ((lane >> 4) << 3);
                ldsm_x4(af[ms], ef_base + (row * PH_A + col) * 2);
            }
            #pragma unroll
            for (int np = 0; np < 2; np++) {
                int n0 = wc * 32 + np * 16;
                int brow = n0 + ((lane >> 4) << 3) + (lane & 7);
                int bcol = ks + (((lane >> 3) & 1) << 3);
                uint32_t bf[4];
                ldsm_x4(bf, cur + (brow * PH_B + bcol) * 2);
                mma_fp16(acc2[0][np * 2],     af[0], bf[0], bf[1]);
                mma_fp16(acc2[0][np * 2 + 1], af[0], bf[2], bf[3]);
                mma_fp16(acc2[1][np * 2],     af[1], bf[0], bf[1]);
                mma_fp16(acc2[1][np * 2 + 1], af[1], bf[2], bf[3]);
            }
        }
        __syncthreads();
    }

    // output
    #pragma unroll
    for (int ms = 0; ms < 2; ms++) {
        int er0 = e0 + wr * 32 + ms * 16 + g;
        #pragma unroll
        for (int ns = 0; ns < 4; ns++) {
            int n0 = wc * 32 + ns * 8 + 2 * q;
            float bx = bp2[n0], by = bp2[n0 + 1];
            if (er0 < E)
                *(float2*)&out[(size_t)er0 * 128 + n0] =
                    make_float2(acc2[ms][ns][0] + bx, acc2[ms][ns][1] + by);
            if (er0 + 8 < E)
                *(float2*)&out[(size_t)(er0 + 8) * 128 + n0] =
                    make_float2(acc2[ms][ns][2] + bx, acc2[ms][ns][3] + by);
        }
    }
}

// ---------------------------------------------------------------------------
extern "C" void kernel_launch(void* const* d_in, const int* in_sizes, int n_in,
                              void* d_out, int out_size)
{
    const float* x   = (const float*)d_in[0];
    const int*   ei  = (const int*)d_in[1];
    const float* W1  = (const float*)d_in[2];
    const float* b1  = (const float*)d_in[3];
    const float* W2  = (const float*)d_in[4];
    const float* b2  = (const float*)d_in[5];
    const float* Wp1 = (const float*)d_in[6];
    const float* bp1 = (const float*)d_in[7];
    const float* Wp2 = (const float*)d_in[8];
    const float* bp2 = (const float*)d_in[9];
    const float* Wc  = (const float*)d_in[10];
    const float* bc  = (const float*)d_in[11];

    int n = in_sizes[0] / 256;
    int E = in_sizes[1] / 2;

    float* out    = (float*)d_out;
    float* f      = out;
    float* ef_out = f + (long long)n * 128;
    float* logits = ef_out + (long long)E * 128;
    float* ei_out = logits + (long long)n * 40;

    float *xw, *h, *hw, *dinv;
    __half *W1h, *W2h, *Wp1h, *Wp2h;
    int *cnt, *startp, *cursor, *csr, *bsum;
    cudaGetSymbolAddress((void**)&xw,     g_xw);
    cudaGetSymbolAddress((void**)&h,      g_h);
    cudaGetSymbolAddress((void**)&hw,     g_hw);
    cudaGetSymbolAddress((void**)&dinv,   g_dinv);
    cudaGetSymbolAddress((void**)&cnt,    g_cnt);
    cudaGetSymbolAddress((void**)&startp, g_start);
    cudaGetSymbolAddress((void**)&cursor, g_cursor);
    cudaGetSymbolAddress((void**)&csr,    g_csr);
    cudaGetSymbolAddress((void**)&bsum,   g_bsum);
    cudaGetSymbolAddress((void**)&W1h,    g_W1h);
    cudaGetSymbolAddress((void**)&W2h,    g_W2h);
    cudaGetSymbolAddress((void**)&Wp1h,   g_Wp1h);
    cudaGetSymbolAddress((void**)&Wp2h,   g_Wp2h);

    cudaFuncSetAttribute(k_edge_mlp_fp16,
                         cudaFuncAttributeMaxDynamicSharedMemorySize, EMLP_SMEM);

    // CSR + degree + weight prep
    cudaMemsetAsync(cnt, 0, (size_t)n * sizeof(int));
    k_hist<<<(E + 255) / 256, 256>>>(ei, cnt, E);
    k_prep_h<<<(256 * 256 + 255) / 256, 256>>>(W1, W1h, 256, 256);
    k_dinv<<<(n + 255) / 256, 256>>>(cnt, dinv, n);

    // layer 1 GEMM (in the ncu capture slot)
    k_gemm_fp16<<<dim3(2, (n + 63) / 64), 256>>>(n, 256, 256, x, 0, W1h, dinv, xw);

    int nb = (n + 1023) / 1024;
    k_scan1<<<nb, 256>>>(cnt, startp, bsum, n);
    k_scan2<<<1, 32>>>(bsum, nb);
    k_scan3<<<(n + 255) / 256, 256>>>(startp, cursor, bsum, n);
    k_scatter<<<(E + 255) / 256, 256>>>(ei, cursor, csr, E);

    k_agg_csr<<<(n + 3) / 4, 256>>>(csr, startp, cnt, dinv, xw, b1, h, n, 2, 1);

    // layer 2
    k_prep_h<<<(256 * 128 + 255) / 256, 256>>>(W2, W2h, 256, 128);
    k_gemm_fp16<<<dim3(1, (n + 63) / 64), 256>>>(n, 256, 128, h, 1, W2h, dinv, hw);
    k_agg_csr<<<(n + 7) / 8, 256>>>(csr, startp, cnt, dinv, hw, b2, f, n, 1, 0);

    // classifier (fp32)
    k_sgemm<<<dim3(1, (n + 63) / 64), 256>>>(n, 40, 128, f, Wc, bc, logits, 0);

    // edge_index passthrough
    k_copy_ei<<<(2 * E + 255) / 256, 256>>>(ei, ei_out, 2 * E);

    // edge MLP
    k_prep_h<<<(256 * 256 + 255) / 256, 256>>>(Wp1, Wp1h, 256, 256);
    k_prep_h<<<(256 * 128 + 255) / 256, 256>>>(Wp2, Wp2h, 256, 128);
    k_edge_mlp_fp16<<<(E + TE - 1) / TE, 512, EMLP_SMEM>>>(ei, f, Wp1h, bp1, Wp2h, bp2, ef_out, E);
}

// round 11
// speedup vs baseline: 9.2581x; 1.1672x over previous
#include <cuda_runtime.h>
#include <cuda_fp16.h>
#include <cstdint>

// ---------------------------------------------------------------------------
// GraphEncoder: 2-layer GCN + edge MLP + classifier.
// Output (f32): f[N,128], edge_feats[E,128], logits[N,40], edge_index (float).
// fp16 GEMMs (m16n8k16, fp32 accum) + fp16 intermediate storage for all
// scatter/gather paths.
// ---------------------------------------------------------------------------

#define MAXN 100000
#define MAXE 800000

__device__ __half g_xwh[(size_t)MAXN * 256];  // dinv-scaled x@W1 (half)
__device__ __half g_hh [(size_t)MAXN * 256];  // hidden, relu'd (half)
__device__ __half g_hwh[(size_t)MAXN * 128];  // dinv-scaled h@W2 (half)
__device__ __half g_fh [(size_t)MAXN * 128];  // half copy of f for edge gather
__device__ float  g_dinv[MAXN];
__device__ int    g_cnt[MAXN];
__device__ int    g_start[MAXN];
__device__ int    g_cursor[MAXN];
__device__ int    g_csr[MAXE];
__device__ int    g_bsum[128];
__device__ __half g_W1h [256 * 256];   // W1^T  fp16: [n][k]
__device__ __half g_W2h [128 * 256];   // W2^T  fp16: [n][k]
__device__ __half g_Wp1h[256 * 256];   // Wp1^T fp16: [n][k]
__device__ __half g_Wp2h[128 * 256];   // Wp2^T fp16: [n][k]

// ---------------------------------------------------------------------------
__device__ __forceinline__ void mma_fp16(float c[4], const uint32_t a[4],
                                         uint32_t b0, uint32_t b1)
{
    asm volatile(
        "mma.sync.aligned.m16n8k16.row.col.f32.f16.f16.f32 "
        "{%0,%1,%2,%3}, {%4,%5,%6,%7}, {%8,%9}, {%0,%1,%2,%3};"
        : "+f"(c[0]), "+f"(c[1]), "+f"(c[2]), "+f"(c[3])
        : "r"(a[0]), "r"(a[1]), "r"(a[2]), "r"(a[3]), "r"(b0), "r"(b1));
}

__device__ __forceinline__ void ldsm_x4(uint32_t r[4], uint32_t saddr) {
    asm volatile("ldmatrix.sync.aligned.m8n8.x4.shared.b16 {%0,%1,%2,%3}, [%4];"
                 : "=r"(r[0]), "=r"(r[1]), "=r"(r[2]), "=r"(r[3]) : "r"(saddr));
}

__device__ __forceinline__ uint32_t smem_to_u32(const void* p) {
    uint32_t a;
    asm("{ .reg .u64 t; cvta.to.shared.u64 t, %1; cvt.u32.u64 %0, t; }"
        : "=r"(a) : "l"(p));
    return a;
}

// accumulate 8 halves (uint4) into 8 floats
__device__ __forceinline__ void acc8(float* a, uint4 v) {
    const __half2* h = (const __half2*)&v;
    #pragma unroll
    for (int i = 0; i < 4; i++) {
        float2 f = __half22float2(h[i]);
        a[2 * i] += f.x; a[2 * i + 1] += f.y;
    }
}
__device__ __forceinline__ void acc4(float* a, uint2 v) {
    const __half2* h = (const __half2*)&v;
    #pragma unroll
    for (int i = 0; i < 2; i++) {
        float2 f = __half22float2(h[i]);
        a[2 * i] += f.x; a[2 * i + 1] += f.y;
    }
}

// ---------------------------------------------------------------------------
// transpose+convert: src [K,N] fp32 -> dst [N,K] fp16
__global__ void k_prep_h(const float* __restrict__ src, __half* __restrict__ dst,
                         int K, int N)
{
    int i = blockIdx.x * blockDim.x + threadIdx.x;
    if (i < K * N) {
        int n = i / K, k = i - n * K;
        dst[i] = __float2half_rn(src[(size_t)k * N + n]);
    }
}

__global__ void k_hist(const int* __restrict__ ei, int* __restrict__ cnt, int E) {
    int e = blockIdx.x * blockDim.x + threadIdx.x;
    if (e < E) atomicAdd(&cnt[ei[E + e]], 1);
}

__global__ void k_dinv(const int* __restrict__ cnt, float* __restrict__ dinv, int n) {
    int i = blockIdx.x * blockDim.x + threadIdx.x;
    if (i < n) dinv[i] = rsqrtf((float)(cnt[i] + 1));
}

__global__ void k_scan1(const int* __restrict__ in, int* __restrict__ out,
                        int* __restrict__ bsum, int n)
{
    __shared__ int wsum[8];
    int t = threadIdx.x;
    int base = blockIdx.x * 1024 + t * 4;
    int v0 = base + 0 < n ? in[base + 0] : 0;
    int v1 = base + 1 < n ? in[base + 1] : 0;
    int v2 = base + 2 < n ? in[base + 2] : 0;
    int v3 = base + 3 < n ? in[base + 3] : 0;
    int ts = v0 + v1 + v2 + v3;
    int lane = t & 31, w = t >> 5;
    int x = ts;
    #pragma unroll
    for (int o = 1; o < 32; o <<= 1) {
        int y = __shfl_up_sync(0xffffffffu, x, o);
        if (lane >= o) x += y;
    }
    if (lane == 31) wsum[w] = x;
    __syncthreads();
    if (t == 0) {
        int run = 0;
        #pragma unroll
        for (int i = 0; i < 8; i++) { int tmp = wsum[i]; wsum[i] = run; run += tmp; }
        bsum[blockIdx.x] = run;
    }
    __syncthreads();
    int excl = x - ts + wsum[w];
    if (base + 0 < n) out[base + 0] = excl;
    if (base + 1 < n) out[base + 1] = excl + v0;
    if (base + 2 < n) out[base + 2] = excl + v0 + v1;
    if (base + 3 < n) out[base + 3] = excl + v0 + v1 + v2;
}

__global__ void k_scan2(int* bsum, int nb) {
    if (threadIdx.x == 0) {
        int run = 0;
        for (int i = 0; i < nb; i++) { int t = bsum[i]; bsum[i] = run; run += t; }
    }
}

__global__ void k_scan3(int* __restrict__ out, int* __restrict__ cursor,
                        const int* __restrict__ bsum, int n)
{
    int i = blockIdx.x * blockDim.x + threadIdx.x;
    if (i < n) {
        int v = out[i] + bsum[i >> 10];
        out[i] = v;
        cursor[i] = v;
    }
}

__global__ void k_scatter(const int* __restrict__ ei, int* __restrict__ cursor,
                          int* __restrict__ csr, int E)
{
    int e = blockIdx.x * blockDim.x + threadIdx.x;
    if (e < E) {
        int c = ei[E + e];
        int pos = atomicAdd(&cursor[c], 1);
        csr[pos] = ei[e];
    }
}

// ---------------------------------------------------------------------------
// Layer-1 aggregation: 256 half cols, 1 warp/node, 8 warps/block.
// outh = relu(dinv*(sum + self) + bias) as half.
__global__ __launch_bounds__(256)
void k_agg1(const int* __restrict__ csr,
            const int* __restrict__ start, const int* __restrict__ cnt,
            const float* __restrict__ dinv,
            const __half* __restrict__ src,
            const float* __restrict__ bias,
            __half* __restrict__ outh, int n)
{
    int w = threadIdx.x >> 5, lane = threadIdx.x & 31;
    int node = blockIdx.x * 8 + w;
    if (node >= n) return;
    const uint4* s4 = (const uint4*)src;   // 32 uint4 (256 halves) per row
    int s0 = start[node], c0 = cnt[node];
    float a[8] = {};
    for (int b = 0; b < c0; b += 32) {
        int m = min(32, c0 - b);
        int idx = (b + lane < c0) ? csr[s0 + b + lane] : 0;
        int j = 0;
        for (; j + 4 <= m; j += 4) {
            int n0 = __shfl_sync(0xffffffffu, idx, j);
            int n1 = __shfl_sync(0xffffffffu, idx, j + 1);
            int n2 = __shfl_sync(0xffffffffu, idx, j + 2);
            int n3 = __shfl_sync(0xffffffffu, idx, j + 3);
            uint4 v0 = s4[(size_t)n0 * 32 + lane];
            uint4 v1 = s4[(size_t)n1 * 32 + lane];
            uint4 v2 = s4[(size_t)n2 * 32 + lane];
            uint4 v3 = s4[(size_t)n3 * 32 + lane];
            acc8(a, v0); acc8(a, v1); acc8(a, v2); acc8(a, v3);
        }
        for (; j < m; j++) {
            int srcn = __shfl_sync(0xffffffffu, idx, j);
            acc8(a, s4[(size_t)srcn * 32 + lane]);
        }
    }
    float self[8] = {};
    acc8(self, s4[(size_t)node * 32 + lane]);
    float d = dinv[node];
    uint4 o;
    __half2* oh = (__half2*)&o;
    #pragma unroll
    for (int i = 0; i < 4; i++) {
        int c = lane * 8 + 2 * i;
        float r0 = fmaxf(fmaf(d, a[2 * i]     + self[2 * i],     bias[c]),     0.f);
        float r1 = fmaxf(fmaf(d, a[2 * i + 1] + self[2 * i + 1], bias[c + 1]), 0.f);
        oh[i] = __floats2half2_rn(r0, r1);
    }
    ((uint4*)outh)[(size_t)node * 32 + lane] = o;
}

// Layer-2 aggregation: 128 half cols, 1 warp/node.
// f = dinv*(sum + self) + bias (float out) ; fh = half copy.
__global__ __launch_bounds__(256)
void k_agg2(const int* __restrict__ csr,
            const int* __restrict__ start, const int* __restrict__ cnt,
            const float* __restrict__ dinv,
            const __half* __restrict__ src,
            const float* __restrict__ bias,
            float* __restrict__ f, __half* __restrict__ fh, int n)
{
    int w = threadIdx.x >> 5, lane = threadIdx.x & 31;
    int node = blockIdx.x * 8 + w;
    if (node >= n) return;
    const uint2* s2 = (const uint2*)src;   // 32 uint2 (128 halves) per row
    int s0 = start[node], c0 = cnt[node];
    float a[4] = {};
    for (int b = 0; b < c0; b += 32) {
        int m = min(32, c0 - b);
        int idx = (b + lane < c0) ? csr[s0 + b + lane] : 0;
        int j = 0;
        for (; j + 4 <= m; j += 4) {
            int n0 = __shfl_sync(0xffffffffu, idx, j);
            int n1 = __shfl_sync(0xffffffffu, idx, j + 1);
            int n2 = __shfl_sync(0xffffffffu, idx, j + 2);
            int n3 = __shfl_sync(0xffffffffu, idx, j + 3);
            uint2 v0 = s2[(size_t)n0 * 32 + lane];
            uint2 v1 = s2[(size_t)n1 * 32 + lane];
            uint2 v2 = s2[(size_t)n2 * 32 + lane];
            uint2 v3 = s2[(size_t)n3 * 32 + lane];
            acc4(a, v0); acc4(a, v1); acc4(a, v2); acc4(a, v3);
        }
        for (; j < m; j++) {
            int srcn = __shfl_sync(0xffffffffu, idx, j);
            acc4(a, s2[(size_t)srcn * 32 + lane]);
        }
    }
    float self[4] = {};
    acc4(self, s2[(size_t)node * 32 + lane]);
    float d = dinv[node];
    float4 b4 = ((const float4*)bias)[lane];
    float4 r;
    r.x = fmaf(d, a[0] + self[0], b4.x);
    r.y = fmaf(d, a[1] + self[1], b4.y);
    r.z = fmaf(d, a[2] + self[2], b4.z);
    r.w = fmaf(d, a[3] + self[3], b4.w);
    ((float4*)f)[(size_t)node * 32 + lane] = r;
    uint2 o;
    __half2* oh = (__half2*)&o;
    oh[0] = __floats2half2_rn(r.x, r.y);
    oh[1] = __floats2half2_rn(r.z, r.w);
    ((uint2*)fh)[(size_t)node * 32 + lane] = o;
}

// ---------------------------------------------------------------------------
// fp16 node GEMM: BM=64, BN=128, BK=32; 256 threads (8 warps, 2x4).
// A: fp32 (Ah==null) or half [M][K]. B pre-transposed [n][k] half.
// Epilogue: Csh[r] = (half) dinv[r] * acc.
#define PA2 40
#define PB2 40
__global__ __launch_bounds__(256)
void k_gemm_fp16(int M, int K, int N,
                 const float* __restrict__ A, const __half* __restrict__ Ah,
                 const __half* __restrict__ Bh,
                 const float* __restrict__ dinv,
                 __half* __restrict__ Csh)
{
    __shared__ __half s_a[64 * PA2];
    __shared__ __half s_b[128 * PB2];
    int t = threadIdx.x;
    int lane = t & 31, w = t >> 5;
    int g = lane >> 2, q = lane & 3;
    int wr = w >> 2, wc = w & 3;
    int row0 = blockIdx.y * 64;
    int col0 = blockIdx.x * 128;
    uint32_t a_base = smem_to_u32(s_a);
    uint32_t b_base = smem_to_u32(s_b);

    float acc[2][4][4] = {};

    for (int k0 = 0; k0 < K; k0 += 32) {
        __syncthreads();
        if (Ah) {
            for (int i = t; i < 256; i += 256) {
                int r = i >> 2, seg = i & 3;
                int gr = row0 + r;
                uint4 v = make_uint4(0, 0, 0, 0);
                if (gr < M) v = *(const uint4*)&Ah[(size_t)gr * K + k0 + seg * 8];
                *(uint4*)&s_a[r * PA2 + seg * 8] = v;
            }
        } else {
            for (int i = t; i < 512; i += 256) {
                int r = i >> 3, c4 = i & 7;
                int gr = row0 + r;
                float4 v = make_float4(0.f, 0.f, 0.f, 0.f);
                if (gr < M) v = *(const float4*)&A[(size_t)gr * K + k0 + c4 * 4];
                __half2 h0 = __floats2half2_rn(v.x, v.y);
                __half2 h1 = __floats2half2_rn(v.z, v.w);
                *(uint2*)&s_a[r * PA2 + c4 * 4] =
                    make_uint2(*(uint32_t*)&h0, *(uint32_t*)&h1);
            }
        }
        for (int i = t; i < 512; i += 256) {
            int n = i >> 2, seg = i & 3;
            *(uint4*)&s_b[n * PB2 + seg * 8] =
                *(const uint4*)&Bh[(size_t)(col0 + n) * K + k0 + seg * 8];
        }
        __syncthreads();
        #pragma unroll
        for (int ks = 0; ks < 32; ks += 16) {
            uint32_t af[2][4];
            #pragma unroll
            for (int ms = 0; ms < 2; ms++) {
                int row = wr * 32 + ms * 16 + (lane & 15);
                int col = ks + ((lane >> 4) << 3);
                ldsm_x4(af[ms], a_base + (row * PA2 + col) * 2);
            }
            #pragma unroll
            for (int np = 0; np < 2; np++) {
                int n0 = wc * 32 + np * 16;
                int brow = n0 + ((lane >> 4) << 3) + (lane & 7);
                int bcol = ks + (((lane >> 3) & 1) << 3);
                uint32_t bf[4];
                ldsm_x4(bf, b_base + (brow * PB2 + bcol) * 2);
                mma_fp16(acc[0][np * 2],     af[0], bf[0], bf[1]);
                mma_fp16(acc[0][np * 2 + 1], af[0], bf[2], bf[3]);
                mma_fp16(acc[1][np * 2],     af[1], bf[0], bf[1]);
                mma_fp16(acc[1][np * 2 + 1], af[1], bf[2], bf[3]);
            }
        }
    }
    #pragma unroll
    for (int ms = 0; ms < 2; ms++) {
        #pragma unroll
        for (int ns = 0; ns < 4; ns++) {
            int c = col0 + wc * 32 + ns * 8 + 2 * q;
            int r1 = row0 + wr * 32 + ms * 16 + g;
            if (r1 < M) {
                float d = dinv[r1];
                *(__half2*)&Csh[(size_t)r1 * N + c] =
                    __floats2half2_rn(d * acc[ms][ns][0], d * acc[ms][ns][1]);
            }
            int r2 = r1 + 8;
            if (r2 < M) {
                float d = dinv[r2];
                *(__half2*)&Csh[(size_t)r2 * N + c] =
                    __floats2half2_rn(d * acc[ms][ns][2], d * acc[ms][ns][3]);
            }
        }
    }
}

// ---------------------------------------------------------------------------
// fp32 SGEMM (classifier only: N=40)
__global__ __launch_bounds__(256)
void k_sgemm(int M, int N, int K,
             const float* __restrict__ A, const float* __restrict__ B,
             const float* __restrict__ bias, float* __restrict__ C, int relu)
{
    __shared__ float As[64 * 16];
    __shared__ float Bs[16 * 64];
    int t = threadIdx.x;
    int tx = t & 15, ty = t >> 4;
    int row0 = blockIdx.y * 64, col0 = blockIdx.x * 64;
    float acc[4][4] = {};

    for (int k0 = 0; k0 < K; k0 += 16) {
        for (int i = t; i < 64 * 16; i += 256) {
            int r = i >> 4, c = i & 15;
            int gr = row0 + r, gc = k0 + c;
            As[i] = (gr < M && gc < K) ? A[(long long)gr * K + gc] : 0.f;
        }
        for (int i = t; i < 16 * 64; i += 256) {
            int r = i >> 6, c = i & 63;
            int gr = k0 + r, gc = col0 + c;
            Bs[i] = (gr < K && gc < N) ? B[(long long)gr * N + gc] : 0.f;
        }
        __syncthreads();
        #pragma unroll
        for (int kk = 0; kk < 16; kk++) {
            float a[4], b[4];
            #pragma unroll
            for (int m = 0; m < 4; m++) a[m] = As[(ty * 4 + m) * 16 + kk];
            #pragma unroll
            for (int nn = 0; nn < 4; nn++) b[nn] = Bs[kk * 64 + tx * 4 + nn];
            #pragma unroll
            for (int m = 0; m < 4; m++)
                #pragma unroll
                for (int nn = 0; nn < 4; nn++)
                    acc[m][nn] += a[m] * b[nn];
        }
        __syncthreads();
    }
    #pragma unroll
    for (int m = 0; m < 4; m++) {
        int r = row0 + ty * 4 + m;
        if (r >= M) continue;
        #pragma unroll
        for (int nn = 0; nn < 4; nn++) {
            int c = col0 + tx * 4 + nn;
            if (c >= N) continue;
            float v = acc[m][nn] + (bias ? bias[c] : 0.f);
            if (relu) v = fmaxf(v, 0.f);
            C[(long long)r * N + c] = v;
        }
    }
}

__global__ void k_copy_ei(const int* __restrict__ ei, float* __restrict__ out, int n2) {
    int i = blockIdx.x * blockDim.x + threadIdx.x;
    if (i < n2) out[i] = (float)ei[i];
}

// ---------------------------------------------------------------------------
// fp16 edge MLP: 128 edges/block, 512 threads (16 warps, 4x4), m16n8k16,
// ldmatrix fragment loads, double-buffered weights. Gathers from half f-copy.
#define TE 128
#define PH_A 264
#define PH_B 40
#define BUFH (256 * PH_B)
#define EMLP_SMEM ((TE * PH_A + 2 * BUFH) * 2)
__global__ __launch_bounds__(512, 1)
void k_edge_mlp_fp16(const int* __restrict__ ei,
                     const __half* __restrict__ fh,
                     const __half* __restrict__ W1h, const float* __restrict__ bp1,
                     const __half* __restrict__ W2h, const float* __restrict__ bp2,
                     float* __restrict__ out, int E)
{
    extern __shared__ __half hsm[];
    __half* s_ef = hsm;
    __half* s_b  = hsm + TE * PH_A;
    uint32_t ef_base = smem_to_u32(s_ef);
    uint32_t sb_base = smem_to_u32(s_b);

    int t = threadIdx.x;
    int lane = t & 31, w = t >> 5;
    int g = lane >> 2, q = lane & 3;
    int wr = w >> 2, wc = w & 3;
    int e0 = blockIdx.x * TE;

    // gather ef tile: 256 halves per row = 32 uint4 segments.
    // seg c32: c32<16 -> f[src] halves [c32*8 ..), else f[dst] halves [(c32-16)*8..)
    // stored contiguously at half-offset c32*8 (src 0..127 | dst 128..255).
    const uint4* f16 = (const uint4*)fh;   // 16 uint4 per 128-half row
    for (int i = t; i < TE * 32; i += 512) {
        int row = i >> 5, c32 = i & 31;
        int e = e0 + row;
        uint4 v = make_uint4(0, 0, 0, 0);
        if (e < E) {
            int node = (c32 < 16) ? ei[e] : ei[E + e];
            v = f16[(size_t)node * 16 + (c32 & 15)];
        }
        *(uint4*)&s_ef[row * PH_A + c32 * 8] = v;
    }

    // preload GEMM1 weight chunk 0
    for (int i = t; i < 1024; i += 512) {
        int n = i >> 2, seg = i & 3;
        *(uint4*)&s_b[n * PH_B + seg * 8] = *(const uint4*)&W1h[n * 256 + seg * 8];
    }
    __syncthreads();

    // ---- GEMM1: hid[128,256] = ef @ Wp1 ----
    float acc[2][8][4] = {};
    for (int c = 0; c < 8; c++) {
        uint32_t cur = sb_base + (c & 1) * (BUFH * 2);
        if (c + 1 < 8) {
            __half* nxt = s_b + ((c + 1) & 1) * BUFH;
            const __half* wsrc = W1h + (c + 1) * 32;
            for (int i = t; i < 1024; i += 512) {
                int n = i >> 2, seg = i & 3;
                *(uint4*)&nxt[n * PH_B + seg * 8] =
                    *(const uint4*)&wsrc[n * 256 + seg * 8];
            }
        }
        int k0 = c * 32;
        #pragma unroll
        for (int ks = 0; ks < 32; ks += 16) {
            uint32_t af[2][4];
            #pragma unroll
            for (int ms = 0; ms < 2; ms++) {
                int row = wr * 32 + ms * 16 + (lane & 15);
                int col = k0 + ks + ((lane >> 4) << 3);
                ldsm_x4(af[ms], ef_base + (row * PH_A + col) * 2);
            }
            #pragma unroll
            for (int np = 0; np < 4; np++) {
                int n0 = wc * 64 + np * 16;
                int brow = n0 + ((lane >> 4) << 3) + (lane & 7);
                int bcol = ks + (((lane >> 3) & 1) << 3);
                uint32_t bf[4];
                ldsm_x4(bf, cur + (brow * PH_B + bcol) * 2);
                mma_fp16(acc[0][np * 2],     af[0], bf[0], bf[1]);
                mma_fp16(acc[0][np * 2 + 1], af[0], bf[2], bf[3]);
                mma_fp16(acc[1][np * 2],     af[1], bf[0], bf[1]);
                mma_fp16(acc[1][np * 2 + 1], af[1], bf[2], bf[3]);
            }
        }
        __syncthreads();
    }

    // hid = relu(acc + bp1) -> s_ef (fp16)
    #pragma unroll
    for (int ms = 0; ms < 2; ms++) {
        int r0 = wr * 32 + ms * 16 + g;
        #pragma unroll
        for (int ns = 0; ns < 8; ns++) {
            int n0 = wc * 64 + ns * 8 + 2 * q;
            float bx = bp1[n0], by = bp1[n0 + 1];
            *(__half2*)&s_ef[r0 * PH_A + n0] = __floats2half2_rn(
                fmaxf(acc[ms][ns][0] + bx, 0.f), fmaxf(acc[ms][ns][1] + by, 0.f));
            *(__half2*)&s_ef[(r0 + 8) * PH_A + n0] = __floats2half2_rn(
                fmaxf(acc[ms][ns][2] + bx, 0.f), fmaxf(acc[ms][ns][3] + by, 0.f));
        }
    }

    // preload GEMM2 weight chunk 0
    for (int i = t; i < 512; i += 512) {
        int n = i >> 2, seg = i & 3;
        *(uint4*)&s_b[n * PH_B + seg * 8] = *(const uint4*)&W2h[n * 256 + seg * 8];
    }
    __syncthreads();

    // ---- GEMM2: out[128,128] = hid @ Wp2 ----
    float acc2[2][4][4] = {};
    for (int c = 0; c < 8; c++) {
        uint32_t cur = sb_base + (c & 1) * (BUFH * 2);
        if (c + 1 < 8) {
            __half* nxt = s_b + ((c + 1) & 1) * BUFH;
            const __half* wsrc = W2h + (c + 1) * 32;
            for (int i = t; i < 512; i += 512) {
                int n = i >> 2, seg = i & 3;
                *(uint4*)&nxt[n * PH_B + seg * 8] =
                    *(const uint4*)&wsrc[n * 256 + seg * 8];
            }
        }
        int k0 = c * 32;
        #pragma unroll
        for (int ks = 0; ks < 32; ks += 16) {
            uint32_t af[2][4];
            #pragma unroll
            for (int ms = 0; ms < 2; ms++) {
                int row = wr * 32 + ms * 16 + (lane & 15);
                int col = k0 + ks + ((lane >> 4) << 3);
                ldsm_x4(af[ms], ef_base + (row * PH_A + col) * 2);
            }
            #pragma unroll
            for (int np = 0; np < 2; np++) {
                int n0 = wc * 32 + np * 16;
                int brow = n0 + ((lane >> 4) << 3) + (lane & 7);
                int bcol = ks + (((lane >> 3) & 1) << 3);
                uint32_t bf[4];
                ldsm_x4(bf, cur + (brow * PH_B + bcol) * 2);
                mma_fp16(acc2[0][np * 2],     af[0], bf[0], bf[1]);
                mma_fp16(acc2[0][np * 2 + 1], af[0], bf[2], bf[3]);
                mma_fp16(acc2[1][np * 2],     af[1], bf[0], bf[1]);
                mma_fp16(acc2[1][np * 2 + 1], af[1], bf[2], bf[3]);
            }
        }
        __syncthreads();
    }

    // output
    #pragma unroll
    for (int ms = 0; ms < 2; ms++) {
        int er0 = e0 + wr * 32 + ms * 16 + g;
        #pragma unroll
        for (int ns = 0; ns < 4; ns++) {
            int n0 = wc * 32 + ns * 8 + 2 * q;
            float bx = bp2[n0], by = bp2[n0 + 1];
            if (er0 < E)
                *(float2*)&out[(size_t)er0 * 128 + n0] =
                    make_float2(acc2[ms][ns][0] + bx, acc2[ms][ns][1] + by);
            if (er0 + 8 < E)
                *(float2*)&out[(size_t)(er0 + 8) * 128 + n0] =
                    make_float2(acc2[ms][ns][2] + bx, acc2[ms][ns][3] + by);
        }
    }
}

// ---------------------------------------------------------------------------
extern "C" void kernel_launch(void* const* d_in, const int* in_sizes, int n_in,
                              void* d_out, int out_size)
{
    const float* x   = (const float*)d_in[0];
    const int*   ei  = (const int*)d_in[1];
    const float* W1  = (const float*)d_in[2];
    const float* b1  = (const float*)d_in[3];
    const float* W2  = (const float*)d_in[4];
    const float* b2  = (const float*)d_in[5];
    const float* Wp1 = (const float*)d_in[6];
    const float* bp1 = (const float*)d_in[7];
    const float* Wp2 = (const float*)d_in[8];
    const float* bp2 = (const float*)d_in[9];
    const float* Wc  = (const float*)d_in[10];
    const float* bc  = (const float*)d_in[11];

    int n = in_sizes[0] / 256;
    int E = in_sizes[1] / 2;

    float* out    = (float*)d_out;
    float* f      = out;
    float* ef_out = f + (long long)n * 128;
    float* logits = ef_out + (long long)E * 128;
    float* ei_out = logits + (long long)n * 40;

    float *dinv;
    __half *xwh, *hh, *hwh, *fh, *W1h, *W2h, *Wp1h, *Wp2h;
    int *cnt, *startp, *cursor, *csr, *bsum;
    cudaGetSymbolAddress((void**)&xwh,    g_xwh);
    cudaGetSymbolAddress((void**)&hh,     g_hh);
    cudaGetSymbolAddress((void**)&hwh,    g_hwh);
    cudaGetSymbolAddress((void**)&fh,     g_fh);
    cudaGetSymbolAddress((void**)&dinv,   g_dinv);
    cudaGetSymbolAddress((void**)&cnt,    g_cnt);
    cudaGetSymbolAddress((void**)&startp, g_start);
    cudaGetSymbolAddress((void**)&cursor, g_cursor);
    cudaGetSymbolAddress((void**)&csr,    g_csr);
    cudaGetSymbolAddress((void**)&bsum,   g_bsum);
    cudaGetSymbolAddress((void**)&W1h,    g_W1h);
    cudaGetSymbolAddress((void**)&W2h,    g_W2h);
    cudaGetSymbolAddress((void**)&Wp1h,   g_Wp1h);
    cudaGetSymbolAddress((void**)&Wp2h,   g_Wp2h);

    cudaFuncSetAttribute(k_edge_mlp_fp16,
                         cudaFuncAttributeMaxDynamicSharedMemorySize, EMLP_SMEM);

    // CSR + degree + weight prep
    cudaMemsetAsync(cnt, 0, (size_t)n * sizeof(int));
    k_hist<<<(E + 255) / 256, 256>>>(ei, cnt, E);
    k_prep_h<<<(256 * 256 + 255) / 256, 256>>>(W1, W1h, 256, 256);
    k_dinv<<<(n + 255) / 256, 256>>>(cnt, dinv, n);

    // layer 1 GEMM (ncu capture slot)
    k_gemm_fp16<<<dim3(2, (n + 63) / 64), 256>>>(n, 256, 256, x, nullptr, W1h, dinv, xwh);

    int nb = (n + 1023) / 1024;
    k_scan1<<<nb, 256>>>(cnt, startp, bsum, n);
    k_scan2<<<1, 32>>>(bsum, nb);
    k_scan3<<<(n + 255) / 256, 256>>>(startp, cursor, bsum, n);
    k_scatter<<<(E + 255) / 256, 256>>>(ei, cursor, csr, E);

    k_agg1<<<(n + 7) / 8, 256>>>(csr, startp, cnt, dinv, xwh, b1, hh, n);

    // layer 2
    k_prep_h<<<(256 * 128 + 255) / 256, 256>>>(W2, W2h, 256, 128);
    k_gemm_fp16<<<dim3(1, (n + 63) / 64), 256>>>(n, 256, 128, nullptr, hh, W2h, dinv, hwh);
    k_agg2<<<(n + 7) / 8, 256>>>(csr, startp, cnt, dinv, hwh, b2, f, fh, n);

    // classifier (fp32, reads float f)
    k_sgemm<<<dim3(1, (n + 63) / 64), 256>>>(n, 40, 128, f, Wc, bc, logits, 0);

    // edge_index passthrough
    k_copy_ei<<<(2 * E + 255) / 256, 256>>>(ei, ei_out, 2 * E);

    // edge MLP
    k_prep_h<<<(256 * 256 + 255) / 256, 256>>>(Wp1, Wp1h, 256, 256);
    k_prep_h<<<(256 * 128 + 255) / 256, 256>>>(Wp2, Wp2h, 256, 128);
    k_edge_mlp_fp16<<<(E + TE - 1) / TE, 512, EMLP_SMEM>>>(ei, fh, Wp1h, bp1, Wp2h, bp2, ef_out, E);
}

// round 12
// speedup vs baseline: 10.0472x; 1.0852x over previous
#include <cuda_runtime.h>
#include <cuda_fp16.h>
#include <cstdint>

// ---------------------------------------------------------------------------
// GraphEncoder: 2-layer GCN + edge MLP + classifier.
// Output (f32): f[N,128], edge_feats[E,128], logits[N,40], edge_index (float).
// fp16 GEMMs everywhere (m16n8k16, fp32 accum), fp16 intermediates.
// ---------------------------------------------------------------------------

#define MAXN 100000
#define MAXE 800000

__device__ __half g_xwh[(size_t)MAXN * 256];  // dinv-scaled x@W1 (half)
__device__ __half g_hh [(size_t)MAXN * 256];  // hidden, relu'd (half)
__device__ __half g_hwh[(size_t)MAXN * 128];  // dinv-scaled h@W2 (half)
__device__ __half g_fh [(size_t)MAXN * 128];  // half copy of f
__device__ float  g_dinv[MAXN];
__device__ int    g_cnt[MAXN];
__device__ int    g_start[MAXN];
__device__ int    g_cursor[MAXN];
__device__ int    g_csr[MAXE];
__device__ int    g_bsum[128];
__device__ __half g_W1h [256 * 256];   // W1^T  fp16: [n][k]
__device__ __half g_W2h [128 * 256];   // W2^T  fp16: [n][k]
__device__ __half g_Wp1h[256 * 256];   // Wp1^T fp16: [n][k]
__device__ __half g_Wp2h[128 * 256];   // Wp2^T fp16: [n][k]
__device__ __half g_Wch [64 * 128];    // Wc^T  fp16: [n pad 64][k=128]

// ---------------------------------------------------------------------------
__device__ __forceinline__ void mma_fp16(float c[4], const uint32_t a[4],
                                         uint32_t b0, uint32_t b1)
{
    asm volatile(
        "mma.sync.aligned.m16n8k16.row.col.f32.f16.f16.f32 "
        "{%0,%1,%2,%3}, {%4,%5,%6,%7}, {%8,%9}, {%0,%1,%2,%3};"
        : "+f"(c[0]), "+f"(c[1]), "+f"(c[2]), "+f"(c[3])
        : "r"(a[0]), "r"(a[1]), "r"(a[2]), "r"(a[3]), "r"(b0), "r"(b1));
}

__device__ __forceinline__ void ldsm_x4(uint32_t r[4], uint32_t saddr) {
    asm volatile("ldmatrix.sync.aligned.m8n8.x4.shared.b16 {%0,%1,%2,%3}, [%4];"
                 : "=r"(r[0]), "=r"(r[1]), "=r"(r[2]), "=r"(r[3]) : "r"(saddr));
}

__device__ __forceinline__ uint32_t smem_to_u32(const void* p) {
    uint32_t a;
    asm("{ .reg .u64 t; cvta.to.shared.u64 t, %1; cvt.u32.u64 %0, t; }"
        : "=r"(a) : "l"(p));
    return a;
}

__device__ __forceinline__ void acc8(float* a, uint4 v) {
    const __half2* h = (const __half2*)&v;
    #pragma unroll
    for (int i = 0; i < 4; i++) {
        float2 f = __half22float2(h[i]);
        a[2 * i] += f.x; a[2 * i + 1] += f.y;
    }
}
__device__ __forceinline__ void acc4(float* a, uint2 v) {
    const __half2* h = (const __half2*)&v;
    #pragma unroll
    for (int i = 0; i < 2; i++) {
        float2 f = __half22float2(h[i]);
        a[2 * i] += f.x; a[2 * i + 1] += f.y;
    }
}

// ---------------------------------------------------------------------------
// transpose+convert: src [K,N] fp32 -> dst [N,K] fp16
__global__ void k_prep_h(const float* __restrict__ src, __half* __restrict__ dst,
                         int K, int N)
{
    int i = blockIdx.x * blockDim.x + threadIdx.x;
    if (i < K * N) {
        int n = i / K, k = i - n * K;
        dst[i] = __float2half_rn(src[(size_t)k * N + n]);
    }
}

// Wc [128,40] -> [64 pad][128] fp16 (zero pad rows 40..63)
__global__ void k_prep_cls(const float* __restrict__ Wc, __half* __restrict__ dst) {
    int i = blockIdx.x * blockDim.x + threadIdx.x;   // 8192
    if (i < 64 * 128) {
        int n = i >> 7, k = i & 127;
        dst[i] = (n < 40) ? __float2half_rn(Wc[k * 40 + n]) : __float2half_rn(0.f);
    }
}

__global__ void k_hist(const int* __restrict__ ei, int* __restrict__ cnt, int E) {
    int e = blockIdx.x * blockDim.x + threadIdx.x;
    if (e < E) atomicAdd(&cnt[ei[E + e]], 1);
}

__global__ void k_dinv(const int* __restrict__ cnt, float* __restrict__ dinv, int n) {
    int i = blockIdx.x * blockDim.x + threadIdx.x;
    if (i < n) dinv[i] = rsqrtf((float)(cnt[i] + 1));
}

__global__ void k_scan1(const int* __restrict__ in, int* __restrict__ out,
                        int* __restrict__ bsum, int n)
{
    __shared__ int wsum[8];
    int t = threadIdx.x;
    int base = blockIdx.x * 1024 + t * 4;
    int v0 = base + 0 < n ? in[base + 0] : 0;
    int v1 = base + 1 < n ? in[base + 1] : 0;
    int v2 = base + 2 < n ? in[base + 2] : 0;
    int v3 = base + 3 < n ? in[base + 3] : 0;
    int ts = v0 + v1 + v2 + v3;
    int lane = t & 31, w = t >> 5;
    int x = ts;
    #pragma unroll
    for (int o = 1; o < 32; o <<= 1) {
        int y = __shfl_up_sync(0xffffffffu, x, o);
        if (lane >= o) x += y;
    }
    if (lane == 31) wsum[w] = x;
    __syncthreads();
    if (t == 0) {
        int run = 0;
        #pragma unroll
        for (int i = 0; i < 8; i++) { int tmp = wsum[i]; wsum[i] = run; run += tmp; }
        bsum[blockIdx.x] = run;
    }
    __syncthreads();
    int excl = x - ts + wsum[w];
    if (base + 0 < n) out[base + 0] = excl;
    if (base + 1 < n) out[base + 1] = excl + v0;
    if (base + 2 < n) out[base + 2] = excl + v0 + v1;
    if (base + 3 < n) out[base + 3] = excl + v0 + v1 + v2;
}

__global__ void k_scan2(int* bsum, int nb) {
    if (threadIdx.x == 0) {
        int run = 0;
        for (int i = 0; i < nb; i++) { int t = bsum[i]; bsum[i] = run; run += t; }
    }
}

__global__ void k_scan3(int* __restrict__ out, int* __restrict__ cursor,
                        const int* __restrict__ bsum, int n)
{
    int i = blockIdx.x * blockDim.x + threadIdx.x;
    if (i < n) {
        int v = out[i] + bsum[i >> 10];
        out[i] = v;
        cursor[i] = v;
    }
}

__global__ void k_scatter(const int* __restrict__ ei, int* __restrict__ cursor,
                          int* __restrict__ csr, int E)
{
    int e = blockIdx.x * blockDim.x + threadIdx.x;
    if (e < E) {
        int c = ei[E + e];
        int pos = atomicAdd(&cursor[c], 1);
        csr[pos] = ei[e];
    }
}

// ---------------------------------------------------------------------------
// Layer-1 aggregation: 256 half cols, 1 warp/node.
__global__ __launch_bounds__(256)
void k_agg1(const int* __restrict__ csr,
            const int* __restrict__ start, const int* __restrict__ cnt,
            const float* __restrict__ dinv,
            const __half* __restrict__ src,
            const float* __restrict__ bias,
            __half* __restrict__ outh, int n)
{
    int w = threadIdx.x >> 5, lane = threadIdx.x & 31;
    int node = blockIdx.x * 8 + w;
    if (node >= n) return;
    const uint4* s4 = (const uint4*)src;
    int s0 = start[node], c0 = cnt[node];
    float a[8] = {};
    for (int b = 0; b < c0; b += 32) {
        int m = min(32, c0 - b);
        int idx = (b + lane < c0) ? csr[s0 + b + lane] : 0;
        int j = 0;
        for (; j + 4 <= m; j += 4) {
            int n0 = __shfl_sync(0xffffffffu, idx, j);
            int n1 = __shfl_sync(0xffffffffu, idx, j + 1);
            int n2 = __shfl_sync(0xffffffffu, idx, j + 2);
            int n3 = __shfl_sync(0xffffffffu, idx, j + 3);
            uint4 v0 = s4[(size_t)n0 * 32 + lane];
            uint4 v1 = s4[(size_t)n1 * 32 + lane];
            uint4 v2 = s4[(size_t)n2 * 32 + lane];
            uint4 v3 = s4[(size_t)n3 * 32 + lane];
            acc8(a, v0); acc8(a, v1); acc8(a, v2); acc8(a, v3);
        }
        for (; j < m; j++) {
            int srcn = __shfl_sync(0xffffffffu, idx, j);
            acc8(a, s4[(size_t)srcn * 32 + lane]);
        }
    }
    float self[8] = {};
    acc8(self, s4[(size_t)node * 32 + lane]);
    float d = dinv[node];
    uint4 o;
    __half2* oh = (__half2*)&o;
    #pragma unroll
    for (int i = 0; i < 4; i++) {
        int c = lane * 8 + 2 * i;
        float r0 = fmaxf(fmaf(d, a[2 * i]     + self[2 * i],     bias[c]),     0.f);
        float r1 = fmaxf(fmaf(d, a[2 * i + 1] + self[2 * i + 1], bias[c + 1]), 0.f);
        oh[i] = __floats2half2_rn(r0, r1);
    }
    ((uint4*)outh)[(size_t)node * 32 + lane] = o;
}

// Layer-2 aggregation: 128 half cols, 1 warp/node; float f + half copy.
__global__ __launch_bounds__(256)
void k_agg2(const int* __restrict__ csr,
            const int* __restrict__ start, const int* __restrict__ cnt,
            const float* __restrict__ dinv,
            const __half* __restrict__ src,
            const float* __restrict__ bias,
            float* __restrict__ f, __half* __restrict__ fh, int n)
{
    int w = threadIdx.x >> 5, lane = threadIdx.x & 31;
    int node = blockIdx.x * 8 + w;
    if (node >= n) return;
    const uint2* s2 = (const uint2*)src;
    int s0 = start[node], c0 = cnt[node];
    float a[4] = {};
    for (int b = 0; b < c0; b += 32) {
        int m = min(32, c0 - b);
        int idx = (b + lane < c0) ? csr[s0 + b + lane] : 0;
        int j = 0;
        for (; j + 4 <= m; j += 4) {
            int n0 = __shfl_sync(0xffffffffu, idx, j);
            int n1 = __shfl_sync(0xffffffffu, idx, j + 1);
            int n2 = __shfl_sync(0xffffffffu, idx, j + 2);
            int n3 = __shfl_sync(0xffffffffu, idx, j + 3);
            uint2 v0 = s2[(size_t)n0 * 32 + lane];
            uint2 v1 = s2[(size_t)n1 * 32 + lane];
            uint2 v2 = s2[(size_t)n2 * 32 + lane];
            uint2 v3 = s2[(size_t)n3 * 32 + lane];
            acc4(a, v0); acc4(a, v1); acc4(a, v2); acc4(a, v3);
        }
        for (; j < m; j++) {
            int srcn = __shfl_sync(0xffffffffu, idx, j);
            acc4(a, s2[(size_t)srcn * 32 + lane]);
        }
    }
    float self[4] = {};
    acc4(self, s2[(size_t)node * 32 + lane]);
    float d = dinv[node];
    float4 b4 = ((const float4*)bias)[lane];
    float4 r;
    r.x = fmaf(d, a[0] + self[0], b4.x);
    r.y = fmaf(d, a[1] + self[1], b4.y);
    r.z = fmaf(d, a[2] + self[2], b4.z);
    r.w = fmaf(d, a[3] + self[3], b4.w);
    ((float4*)f)[(size_t)node * 32 + lane] = r;
    uint2 o;
    __half2* oh = (__half2*)&o;
    oh[0] = __floats2half2_rn(r.x, r.y);
    oh[1] = __floats2half2_rn(r.z, r.w);
    ((uint2*)fh)[(size_t)node * 32 + lane] = o;
}

// ---------------------------------------------------------------------------
// fp16 node GEMM: BM=64, BN=128, BK=64; 256 threads (8 warps, 2x4).
#define PA2 72   // halves; 36 words % 32 == 4 -> conflict-free ldmatrix
#define PB2 72
__global__ __launch_bounds__(256)
void k_gemm_fp16(int M, int K, int N,
                 const float* __restrict__ A, const __half* __restrict__ Ah,
                 const __half* __restrict__ Bh,
                 const float* __restrict__ dinv,
                 __half* __restrict__ Csh)
{
    __shared__ __half s_a[64 * PA2];
    __shared__ __half s_b[128 * PB2];
    int t = threadIdx.x;
    int lane = t & 31, w = t >> 5;
    int g = lane >> 2, q = lane & 3;
    int wr = w >> 2, wc = w & 3;
    int row0 = blockIdx.y * 64;
    int col0 = blockIdx.x * 128;
    uint32_t a_base = smem_to_u32(s_a);
    uint32_t b_base = smem_to_u32(s_b);

    float acc[2][4][4] = {};

    for (int k0 = 0; k0 < K; k0 += 64) {
        __syncthreads();
        if (Ah) {
            // A tile 64x64 halves: 64 rows x 8 uint4
            for (int i = t; i < 512; i += 256) {
                int r = i >> 3, seg = i & 7;
                int gr = row0 + r;
                uint4 v = make_uint4(0, 0, 0, 0);
                if (gr < M) v = *(const uint4*)&Ah[(size_t)gr * K + k0 + seg * 8];
                *(uint4*)&s_a[r * PA2 + seg * 8] = v;
            }
        } else {
            // A tile 64x64 fp32: 64 rows x 16 float4
            for (int i = t; i < 1024; i += 256) {
                int r = i >> 4, c4 = i & 15;
                int gr = row0 + r;
                float4 v = make_float4(0.f, 0.f, 0.f, 0.f);
                if (gr < M) v = *(const float4*)&A[(size_t)gr * K + k0 + c4 * 4];
                __half2 h0 = __floats2half2_rn(v.x, v.y);
                __half2 h1 = __floats2half2_rn(v.z, v.w);
                *(uint2*)&s_a[r * PA2 + c4 * 4] =
                    make_uint2(*(uint32_t*)&h0, *(uint32_t*)&h1);
            }
        }
        // B tile 128 rows x 64 halves
        for (int i = t; i < 1024; i += 256) {
            int n = i >> 3, seg = i & 7;
            *(uint4*)&s_b[n * PB2 + seg * 8] =
                *(const uint4*)&Bh[(size_t)(col0 + n) * K + k0 + seg * 8];
        }
        __syncthreads();
        #pragma unroll
        for (int ks = 0; ks < 64; ks += 16) {
            uint32_t af[2][4];
            #pragma unroll
            for (int ms = 0; ms < 2; ms++) {
                int row = wr * 32 + ms * 16 + (lane & 15);
                int col = ks + ((lane >> 4) << 3);
                ldsm_x4(af[ms], a_base + (row * PA2 + col) * 2);
            }
            #pragma unroll
            for (int np = 0; np < 2; np++) {
                int n0 = wc * 32 + np * 16;
                int brow = n0 + ((lane >> 4) << 3) + (lane & 7);
                int bcol = ks + (((lane >> 3) & 1) << 3);
                uint32_t bf[4];
                ldsm_x4(bf, b_base + (brow * PB2 + bcol) * 2);
                mma_fp16(acc[0][np * 2],     af[0], bf[0], bf[1]);
                mma_fp16(acc[0][np * 2 + 1], af[0], bf[2], bf[3]);
                mma_fp16(acc[1][np * 2],     af[1], bf[0], bf[1]);
                mma_fp16(acc[1][np * 2 + 1], af[1], bf[2], bf[3]);
            }
        }
    }
    #pragma unroll
    for (int ms = 0; ms < 2; ms++) {
        #pragma unroll
        for (int ns = 0; ns < 4; ns++) {
            int c = col0 + wc * 32 + ns * 8 + 2 * q;
            int r1 = row0 + wr * 32 + ms * 16 + g;
            if (r1 < M) {
                float d = dinv[r1];
                *(__half2*)&Csh[(size_t)r1 * N + c] =
                    __floats2half2_rn(d * acc[ms][ns][0], d * acc[ms][ns][1]);
            }
            int r2 = r1 + 8;
            if (r2 < M) {
                float d = dinv[r2];
                *(__half2*)&Csh[(size_t)r2 * N + c] =
                    __floats2half2_rn(d * acc[ms][ns][2], d * acc[ms][ns][3]);
            }
        }
    }
}

// ---------------------------------------------------------------------------
// fp16 classifier GEMM: logits[M,40] = fh[M,128] @ Wch^T + bc.
// BM=64, BN=64 (N padded), K=128 fully resident; 256 threads (8 warps 2x4).
#define PC 136   // halves; 68 words % 32 == 4
__global__ __launch_bounds__(256)
void k_gemm_cls(int M,
                const __half* __restrict__ Ah,   // [M][128]
                const __half* __restrict__ Bh,   // [64][128] padded
                const float* __restrict__ bias,  // [40]
                float* __restrict__ C)           // [M][40]
{
    __shared__ __half s_a[64 * PC];
    __shared__ __half s_b[64 * PC];
    int t = threadIdx.x;
    int lane = t & 31, w = t >> 5;
    int g = lane >> 2, q = lane & 3;
    int wr = w >> 2, wc = w & 3;
    int row0 = blockIdx.y * 64;
    uint32_t a_base = smem_to_u32(s_a);
    uint32_t b_base = smem_to_u32(s_b);

    // load A tile 64x128 halves (16 uint4/row) + B 64x128
    for (int i = t; i < 1024; i += 256) {
        int r = i >> 4, seg = i & 15;
        int gr = row0 + r;
        uint4 v = make_uint4(0, 0, 0, 0);
        if (gr < M) v = *(const uint4*)&Ah[(size_t)gr * 128 + seg * 8];
        *(uint4*)&s_a[r * PC + seg * 8] = v;
    }
    for (int i = t; i < 1024; i += 256) {
        int n = i >> 4, seg = i & 15;
        *(uint4*)&s_b[n * PC + seg * 8] = *(const uint4*)&Bh[n * 128 + seg * 8];
    }
    __syncthreads();

    float acc[2][2][4] = {};
    #pragma unroll
    for (int ks = 0; ks < 128; ks += 16) {
        uint32_t af[2][4];
        #pragma unroll
        for (int ms = 0; ms < 2; ms++) {
            int row = wr * 32 + ms * 16 + (lane & 15);
            int col = ks + ((lane >> 4) << 3);
            ldsm_x4(af[ms], a_base + (row * PC + col) * 2);
        }
        int n0 = wc * 16;
        int brow = n0 + ((lane >> 4) << 3) + (lane & 7);
        int bcol = ks + (((lane >> 3) & 1) << 3);
        uint32_t bf[4];
        ldsm_x4(bf, b_base + (brow * PC + bcol) * 2);
        #pragma unroll
        for (int ms = 0; ms < 2; ms++) {
            mma_fp16(acc[ms][0], af[ms], bf[0], bf[1]);
            mma_fp16(acc[ms][1], af[ms], bf[2], bf[3]);
        }
    }

    #pragma unroll
    for (int ms = 0; ms < 2; ms++) {
        #pragma unroll
        for (int ns = 0; ns < 2; ns++) {
            int c = wc * 16 + ns * 8 + 2 * q;
            if (c >= 40) continue;
            float bx = bias[c], by = bias[c + 1];
            int r1 = row0 + wr * 32 + ms * 16 + g;
            if (r1 < M)
                *(float2*)&C[(size_t)r1 * 40 + c] =
                    make_float2(acc[ms][ns][0] + bx, acc[ms][ns][1] + by);
            int r2 = r1 + 8;
            if (r2 < M)
                *(float2*)&C[(size_t)r2 * 40 + c] =
                    make_float2(acc[ms][ns][2] + bx, acc[ms][ns][3] + by);
        }
    }
}

__global__ void k_copy_ei(const int* __restrict__ ei, float* __restrict__ out, int n2) {
    int i = blockIdx.x * blockDim.x + threadIdx.x;
    if (i < n2) out[i] = (float)ei[i];
}

// ---------------------------------------------------------------------------
// fp16 edge MLP (unchanged from R11)
#define TE 128
#define PH_A 264
#define PH_B 40
#define BUFH (256 * PH_B)
#define EMLP_SMEM ((TE * PH_A + 2 * BUFH) * 2)
__global__ __launch_bounds__(512, 1)
void k_edge_mlp_fp16(const int* __restrict__ ei,
                     const __half* __restrict__ fh,
                     const __half* __restrict__ W1h, const float* __restrict__ bp1,
                     const __half* __restrict__ W2h, const float* __restrict__ bp2,
                     float* __restrict__ out, int E)
{
    extern __shared__ __half hsm[];
    __half* s_ef = hsm;
    __half* s_b  = hsm + TE * PH_A;
    uint32_t ef_base = smem_to_u32(s_ef);
    uint32_t sb_base = smem_to_u32(s_b);

    int t = threadIdx.x;
    int lane = t & 31, w = t >> 5;
    int g = lane >> 2, q = lane & 3;
    int wr = w >> 2, wc = w & 3;
    int e0 = blockIdx.x * TE;

    const uint4* f16 = (const uint4*)fh;
    for (int i = t; i < TE * 32; i += 512) {
        int row = i >> 5, c32 = i & 31;
        int e = e0 + row;
        uint4 v = make_uint4(0, 0, 0, 0);
        if (e < E) {
            int node = (c32 < 16) ? ei[e] : ei[E + e];
            v = f16[(size_t)node * 16 + (c32 & 15)];
        }
        *(uint4*)&s_ef[row * PH_A + c32 * 8] = v;
    }

    for (int i = t; i < 1024; i += 512) {
        int n = i >> 2, seg = i & 3;
        *(uint4*)&s_b[n * PH_B + seg * 8] = *(const uint4*)&W1h[n * 256 + seg * 8];
    }
    __syncthreads();

    float acc[2][8][4] = {};
    for (int c = 0; c < 8; c++) {
        uint32_t cur = sb_base + (c & 1) * (BUFH * 2);
        if (c + 1 < 8) {
            __half* nxt = s_b + ((c + 1) & 1) * BUFH;
            const __half* wsrc = W1h + (c + 1) * 32;
            for (int i = t; i < 1024; i += 512) {
                int n = i >> 2, seg = i & 3;
                *(uint4*)&nxt[n * PH_B + seg * 8] =
                    *(const uint4*)&wsrc[n * 256 + seg * 8];
            }
        }
        int k0 = c * 32;
        #pragma unroll
        for (int ks = 0; ks < 32; ks += 16) {
            uint32_t af[2][4];
            #pragma unroll
            for (int ms = 0; ms < 2; ms++) {
                int row = wr * 32 + ms * 16 + (lane & 15);
                int col = k0 + ks + ((lane >> 4) << 3);
                ldsm_x4(af[ms], ef_base + (row * PH_A + col) * 2);
            }
            #pragma unroll
            for (int np = 0; np < 4; np++) {
                int n0 = wc * 64 + np * 16;
                int brow = n0 + ((lane >> 4) << 3) + (lane & 7);
                int bcol = ks + (((lane >> 3) & 1) << 3);
                uint32_t bf[4];
                ldsm_x4(bf, cur + (brow * PH_B + bcol) * 2);
                mma_fp16(acc[0][np * 2],     af[0], bf[0], bf[1]);
                mma_fp16(acc[0][np * 2 + 1], af[0], bf[2], bf[3]);
                mma_fp16(acc[1][np * 2],     af[1], bf[0], bf[1]);
                mma_fp16(acc[1][np * 2 + 1], af[1], bf[2], bf[3]);
            }
        }
        __syncthreads();
    }

    #pragma unroll
    for (int ms = 0; ms < 2; ms++) {
        int r0 = wr * 32 + ms * 16 + g;
        #pragma unroll
        for (int ns = 0; ns < 8; ns++) {
            int n0 = wc * 64 + ns * 8 + 2 * q;
            float bx = bp1[n0], by = bp1[n0 + 1];
            *(__half2*)&s_ef[r0 * PH_A + n0] = __floats2half2_rn(
                fmaxf(acc[ms][ns][0] + bx, 0.f), fmaxf(acc[ms][ns][1] + by, 0.f));
            *(__half2*)&s_ef[(r0 + 8) * PH_A + n0] = __floats2half2_rn(
                fmaxf(acc[ms][ns][2] + bx, 0.f), fmaxf(acc[ms][ns][3] + by, 0.f));
        }
    }

    for (int i = t; i < 512; i += 512) {
        int n = i >> 2, seg = i & 3;
        *(uint4*)&s_b[n * PH_B + seg * 8] = *(const uint4*)&W2h[n * 256 + seg * 8];
    }
    __syncthreads();

    float acc2[2][4][4] = {};
    for (int c = 0; c < 8; c++) {
        uint32_t cur = sb_base + (c & 1) * (BUFH * 2);
        if (c + 1 < 8) {
            __half* nxt = s_b + ((c + 1) & 1) * BUFH;
            const __half* wsrc = W2h + (c + 1) * 32;
            for (int i = t; i < 512; i += 512) {
                int n = i >> 2, seg = i & 3;
                *(uint4*)&nxt[n * PH_B + seg * 8] =
                    *(const uint4*)&wsrc[n * 256 + seg * 8];
            }
        }
        int k0 = c * 32;
        #pragma unroll
        for (int ks = 0; ks < 32; ks += 16) {
            uint32_t af[2][4];
            #pragma unroll
            for (int ms = 0; ms < 2; ms++) {
                int row = wr * 32 + ms * 16 + (lane & 15);
                int col = k0 + ks + ((lane >> 4) << 3);
                ldsm_x4(af[ms], ef_base + (row * PH_A + col) * 2);
            }
            #pragma unroll
            for (int np = 0; np < 2; np++) {
                int n0 = wc * 32 + np * 16;
                int brow = n0 + ((lane >> 4) << 3) + (lane & 7);
                int bcol = ks + (((lane >> 3) & 1) << 3);
                uint32_t bf[4];
                ldsm_x4(bf, cur + (brow * PH_B + bcol) * 2);
                mma_fp16(acc2[0][np * 2],     af[0], bf[0], bf[1]);
                mma_fp16(acc2[0][np * 2 + 1], af[0], bf[2], bf[3]);
                mma_fp16(acc2[1][np * 2],     af[1], bf[0], bf[1]);
                mma_fp16(acc2[1][np * 2 + 1], af[1], bf[2], bf[3]);
            }
        }
        __syncthreads();
    }

    #pragma unroll
    for (int ms = 0; ms < 2; ms++) {
        int er0 = e0 + wr * 32 + ms * 16 + g;
        #pragma unroll
        for (int ns = 0; ns < 4; ns++) {
            int n0 = wc * 32 + ns * 8 + 2 * q;
            float bx = bp2[n0], by = bp2[n0 + 1];
            if (er0 < E)
                *(float2*)&out[(size_t)er0 * 128 + n0] =
                    make_float2(acc2[ms][ns][0] + bx, acc2[ms][ns][1] + by);
            if (er0 + 8 < E)
                *(float2*)&out[(size_t)(er0 + 8) * 128 + n0] =
                    make_float2(acc2[ms][ns][2] + bx, acc2[ms][ns][3] + by);
        }
    }
}

// ---------------------------------------------------------------------------
extern "C" void kernel_launch(void* const* d_in, const int* in_sizes, int n_in,
                              void* d_out, int out_size)
{
    const float* x   = (const float*)d_in[0];
    const int*   ei  = (const int*)d_in[1];
    const float* W1  = (const float*)d_in[2];
    const float* b1  = (const float*)d_in[3];
    const float* W2  = (const float*)d_in[4];
    const float* b2  = (const float*)d_in[5];
    const float* Wp1 = (const float*)d_in[6];
    const float* bp1 = (const float*)d_in[7];
    const float* Wp2 = (const float*)d_in[8];
    const float* bp2 = (const float*)d_in[9];
    const float* Wc  = (const float*)d_in[10];
    const float* bc  = (const float*)d_in[11];

    int n = in_sizes[0] / 256;
    int E = in_sizes[1] / 2;

    float* out    = (float*)d_out;
    float* f      = out;
    float* ef_out = f + (long long)n * 128;
    float* logits = ef_out + (long long)E * 128;
    float* ei_out = logits + (long long)n * 40;

    float *dinv;
    __half *xwh, *hh, *hwh, *fh, *W1h, *W2h, *Wp1h, *Wp2h, *Wch;
    int *cnt, *startp, *cursor, *csr, *bsum;
    cudaGetSymbolAddress((void**)&xwh,    g_xwh);
    cudaGetSymbolAddress((void**)&hh,     g_hh);
    cudaGetSymbolAddress((void**)&hwh,    g_hwh);
    cudaGetSymbolAddress((void**)&fh,     g_fh);
    cudaGetSymbolAddress((void**)&dinv,   g_dinv);
    cudaGetSymbolAddress((void**)&cnt,    g_cnt);
    cudaGetSymbolAddress((void**)&startp, g_start);
    cudaGetSymbolAddress((void**)&cursor, g_cursor);
    cudaGetSymbolAddress((void**)&csr,    g_csr);
    cudaGetSymbolAddress((void**)&bsum,   g_bsum);
    cudaGetSymbolAddress((void**)&W1h,    g_W1h);
    cudaGetSymbolAddress((void**)&W2h,    g_W2h);
    cudaGetSymbolAddress((void**)&Wp1h,   g_Wp1h);
    cudaGetSymbolAddress((void**)&Wp2h,   g_Wp2h);
    cudaGetSymbolAddress((void**)&Wch,    g_Wch);

    cudaFuncSetAttribute(k_edge_mlp_fp16,
                         cudaFuncAttributeMaxDynamicSharedMemorySize, EMLP_SMEM);

    // CSR + degree + weight prep
    cudaMemsetAsync(cnt, 0, (size_t)n * sizeof(int));
    k_hist<<<(E + 255) / 256, 256>>>(ei, cnt, E);
    k_prep_h<<<(256 * 256 + 255) / 256, 256>>>(W1, W1h, 256, 256);
    k_dinv<<<(n + 255) / 256, 256>>>(cnt, dinv, n);

    // layer 1 GEMM (ncu capture slot)
    k_gemm_fp16<<<dim3(2, (n + 63) / 64), 256>>>(n, 256, 256, x, nullptr, W1h, dinv, xwh);

    int nb = (n + 1023) / 1024;
    k_scan1<<<nb, 256>>>(cnt, startp, bsum, n);
    k_scan2<<<1, 32>>>(bsum, nb);
    k_scan3<<<(n + 255) / 256, 256>>>(startp, cursor, bsum, n);
    k_scatter<<<(E + 255) / 256, 256>>>(ei, cursor, csr, E);

    k_agg1<<<(n + 7) / 8, 256>>>(csr, startp, cnt, dinv, xwh, b1, hh, n);

    // layer 2
    k_prep_h<<<(256 * 128 + 255) / 256, 256>>>(W2, W2h, 256, 128);
    k_gemm_fp16<<<dim3(1, (n + 63) / 64), 256>>>(n, 256, 128, nullptr, hh, W2h, dinv, hwh);
    k_agg2<<<(n + 7) / 8, 256>>>(csr, startp, cnt, dinv, hwh, b2, f, fh, n);

    // classifier (fp16 tensor, reads half f copy)
    k_prep_cls<<<(64 * 128 + 255) / 256, 256>>>(Wc, Wch);
    k_gemm_cls<<<dim3(1, (n + 63) / 64), 256>>>(n, fh, Wch, bc, logits);

    // edge_index passthrough
    k_copy_ei<<<(2 * E + 255) / 256, 256>>>(ei, ei_out, 2 * E);

    // edge MLP
    k_prep_h<<<(256 * 256 + 255) / 256, 256>>>(Wp1, Wp1h, 256, 256);
    k_prep_h<<<(256 * 128 + 255) / 256, 256>>>(Wp2, Wp2h, 256, 128);
    k_edge_mlp_fp16<<<(E + TE - 1) / TE, 512, EMLP_SMEM>>>(ei, fh, Wp1h, bp1, Wp2h, bp2, ef_out, E);
}